// round 11
// baseline (speedup 1.0000x reference)
#include <cuda_runtime.h>
#include <cuda_bf16.h>
#include <math.h>
#include <stdint.h>

typedef __nv_bfloat16 bf16;

// ---------------- problem constants ----------------
#define S_   2048
#define B_   2
#define H_   1024
#define NH_  16
#define NKV_ 4
#define HD_  64
#define T_   4096            // S_*B_
#define QKV_OUT_ 1536
#define E_   16
#define TOPK_ 2
#define FFN_ 2048
#define CAP_ 640             // ceil(T*K/E*1.25)
#define NSLOT_ (T_*TOPK_)

// ---------------- scratch (device globals; no runtime allocation) ----------------
__device__ float g_ln1[(size_t)T_*H_];
__device__ float g_qkv[(size_t)T_*QKV_OUT_];
__device__ float g_attn[(size_t)T_*H_];
__device__ float g_hattn[(size_t)T_*H_];
__device__ float g_ln2[(size_t)T_*H_];
__device__ int   g_expidx[NSLOT_];
__device__ int   g_pos[NSLOT_];
__device__ int   g_cnt[E_];
__device__ float g_gate[NSLOT_];
__device__ float g_buf[(size_t)E_*CAP_*H_];
__device__ float g_h1[(size_t)E_*CAP_*FFN_];
__device__ float g_h2[(size_t)E_*CAP_*H_];
// weight planes (B operand is always a weight in all four GEMMs)
__device__ __align__(16) bf16 g_qkvwh[(size_t)QKV_OUT_*H_], g_qkvwl[(size_t)QKV_OUT_*H_];
__device__ __align__(16) bf16 g_projwh[(size_t)H_*H_],      g_projwl[(size_t)H_*H_];
__device__ __align__(16) bf16 g_w1h[(size_t)E_*FFN_*H_],    g_w1l[(size_t)E_*FFN_*H_];
__device__ __align__(16) bf16 g_w2h[(size_t)E_*H_*FFN_],    g_w2l[(size_t)E_*H_*FFN_];

// =====================================================================
// PTX helpers (baseline sm_80+ ISA — tcgen05 unavailable on this
// build target, verified by R2 ptxas errors)
// =====================================================================
__device__ __forceinline__ uint32_t smem_to_u32(const void* smem_ptr) {
    uint32_t addr;
    asm("{ .reg .u64 tmp; cvta.to.shared.u64 tmp, %1; cvt.u32.u64 %0, tmp; }"
        : "=r"(addr) : "l"(smem_ptr));
    return addr;
}

#define CVT_BF16X2_F32(result, a, b) \
    asm("cvt.rn.satfinite.bf16x2.f32 %0, %1, %2;" : "=r"(result) : "f"(b), "f"(a))

__device__ __forceinline__ void ldsm_x4(uint32_t& r0, uint32_t& r1,
                                        uint32_t& r2, uint32_t& r3, uint32_t addr) {
    asm volatile("ldmatrix.sync.aligned.m8n8.x4.shared.b16 {%0,%1,%2,%3}, [%4];"
                 : "=r"(r0), "=r"(r1), "=r"(r2), "=r"(r3) : "r"(addr));
}
__device__ __forceinline__ void ldsm_x4_t(uint32_t& r0, uint32_t& r1,
                                          uint32_t& r2, uint32_t& r3, uint32_t addr) {
    asm volatile("ldmatrix.sync.aligned.m8n8.x4.trans.shared.b16 {%0,%1,%2,%3}, [%4];"
                 : "=r"(r0), "=r"(r1), "=r"(r2), "=r"(r3) : "r"(addr));
}

__device__ __forceinline__ void mma16816(float* c,
        uint32_t a0, uint32_t a1, uint32_t a2, uint32_t a3,
        uint32_t b0, uint32_t b1) {
    asm volatile(
        "mma.sync.aligned.m16n8k16.row.col.f32.bf16.bf16.f32 "
        "{%0,%1,%2,%3}, {%4,%5,%6,%7}, {%8,%9}, {%0,%1,%2,%3};"
        : "+f"(c[0]), "+f"(c[1]), "+f"(c[2]), "+f"(c[3])
        : "r"(a0), "r"(a1), "r"(a2), "r"(a3), "r"(b0), "r"(b1));
}

// fp32 float4 -> (hi, lo) split bf16
__device__ __forceinline__ void cvt_split(float4 v, uint2& hi, uint2& lo) {
    uint32_t h01, h23, l01, l23;
    CVT_BF16X2_F32(h01, v.x, v.y);
    CVT_BF16X2_F32(h23, v.z, v.w);
    float f0 = __uint_as_float(h01 << 16), f1 = __uint_as_float(h01 & 0xFFFF0000u);
    float f2 = __uint_as_float(h23 << 16), f3 = __uint_as_float(h23 & 0xFFFF0000u);
    CVT_BF16X2_F32(l01, v.x - f0, v.y - f1);
    CVT_BF16X2_F32(l23, v.z - f2, v.w - f3);
    hi = make_uint2(h01, h23); lo = make_uint2(l01, l23);
}

// ---------------- epilogues ----------------
struct EpiStore {
    __device__ __forceinline__ float op(float v, int, int) const { return v; }
};
struct EpiResidual {
    const float* r; int ld;
    __device__ __forceinline__ float op(float v, int m, int n) const {
        return v + r[(size_t)m * ld + n];
    }
};
struct EpiGelu {
    __device__ __forceinline__ float op(float v, int, int) const {
        // tanh-approx gelu; tanh(x) = 1 - 2/(exp(2x)+1) via fast exp
        float x = 0.7978845608028654f * (v + 0.044715f * v * v * v);
        float t = 1.0f - 2.0f / (__expf(2.0f * x) + 1.0f);
        return 0.5f * v * (1.0f + t);
    }
};

// =====================================================================
// split-bf16 HMMA NT GEMM: C[M,N] = A[M,K] * B[N,K]^T
// A: fp32, converted in-loop. B: preconverted hi/lo bf16 weight planes
// (copied to SMEM with NO conversion work). 128x128 tile, 8 warps,
// K-chunk 64. Optional per-z row-count gating (MoE early exit).
// =====================================================================
#define CH_  64
#define AST  136
#define HMMA_SMEM_BYTES (2 * 128 * AST * 2)   // 69632

template<typename Epi>
__global__ void __launch_bounds__(256, 2)
k_hmma_nt(const float* __restrict__ A, int lda, size_t aB,
          const bf16* __restrict__ Bh, const bf16* __restrict__ Bl, int ldb, size_t bB,
          float* __restrict__ C, int ldc, size_t cB,
          int K, Epi epi, const int* __restrict__ cnt)
{
    if (cnt) {
        int lim = cnt[blockIdx.z];
        if (lim > CAP_) lim = CAP_;
        if ((int)(blockIdx.y * 128) >= lim) return;
    }

    extern __shared__ __nv_bfloat16 sm[];
    __nv_bfloat16 (*As)[AST] = (__nv_bfloat16(*)[AST])sm;
    __nv_bfloat16 (*Bs)[AST] = (__nv_bfloat16(*)[AST])(sm + 128 * AST);

    const int tid = threadIdx.x, lane = tid & 31, wid = tid >> 5;
    const int m0 = blockIdx.y * 128, n0 = blockIdx.x * 128;
    A  += (size_t)blockIdx.z * aB;
    Bh += (size_t)blockIdx.z * bB;
    Bl += (size_t)blockIdx.z * bB;
    C  += (size_t)blockIdx.z * cB;
    const int warpM = (wid >> 2) * 64, warpN = (wid & 3) * 32;

    float acc[4][4][4] = {};

    const uint32_t sA = smem_to_u32(As), sB = smem_to_u32(Bs);
    const int lrow = lane & 15, lsel = lane >> 4;

    for (int k0 = 0; k0 < K; k0 += CH_) {
        #pragma unroll
        for (int i = 0; i < 8; i++) {
            int f = tid + i * 256;
            int row = f >> 4, kq = f & 15;

            float4 va = *(const float4*)&A[(size_t)(m0 + row) * lda + k0 + kq * 4];
            uint2 hi, lo;
            cvt_split(va, hi, lo);
            *(uint2*)&As[row][kq * 4]      = hi;
            *(uint2*)&As[row][64 + kq * 4] = lo;

            size_t bo = (size_t)(n0 + row) * ldb + k0 + kq * 4;
            *(uint2*)&Bs[row][kq * 4]      = *(const uint2*)&Bh[bo];
            *(uint2*)&Bs[row][64 + kq * 4] = *(const uint2*)&Bl[bo];
        }
        __syncthreads();

        const int AO[12] = {0,16,32,48, 64,80,96,112, 0,16,32,48};
        const int BO[12] = {0,16,32,48, 0,16,32,48, 64,80,96,112};
        #pragma unroll
        for (int s = 0; s < 12; s++) {
            uint32_t af[4][4];
            #pragma unroll
            for (int mt = 0; mt < 4; mt++) {
                uint32_t addr = sA +
                    ((uint32_t)(warpM + mt * 16 + lrow) * AST + AO[s] + lsel * 8) * 2;
                ldsm_x4(af[mt][0], af[mt][1], af[mt][2], af[mt][3], addr);
            }
            uint32_t bf[4][2];
            #pragma unroll
            for (int pt = 0; pt < 2; pt++) {
                uint32_t r0, r1, r2, r3;
                uint32_t addr = sB +
                    ((uint32_t)(warpN + pt * 16 + lrow) * AST + BO[s] + lsel * 8) * 2;
                ldsm_x4(r0, r1, r2, r3, addr);
                bf[pt * 2][0] = r0;     bf[pt * 2][1] = r2;
                bf[pt * 2 + 1][0] = r1; bf[pt * 2 + 1][1] = r3;
            }
            #pragma unroll
            for (int mt = 0; mt < 4; mt++)
                #pragma unroll
                for (int nt = 0; nt < 4; nt++)
                    mma16816(acc[mt][nt], af[mt][0], af[mt][1], af[mt][2], af[mt][3],
                             bf[nt][0], bf[nt][1]);
        }
        __syncthreads();
    }

    const int r = lane >> 2, cpair = (lane & 3) * 2;
    #pragma unroll
    for (int mt = 0; mt < 4; mt++) {
        int gm0 = m0 + warpM + mt * 16 + r;
        #pragma unroll
        for (int nt = 0; nt < 4; nt++) {
            int gn = n0 + warpN + nt * 8 + cpair;
            float2 v0 = make_float2(epi.op(acc[mt][nt][0], gm0, gn),
                                    epi.op(acc[mt][nt][1], gm0, gn + 1));
            *(float2*)&C[(size_t)gm0 * ldc + gn] = v0;
            float2 v1 = make_float2(epi.op(acc[mt][nt][2], gm0 + 8, gn),
                                    epi.op(acc[mt][nt][3], gm0 + 8, gn + 1));
            *(float2*)&C[(size_t)(gm0 + 8) * ldc + gn] = v1;
        }
    }
}

// ---------------- weight split: fp32 -> hi/lo planes ----------------
__global__ void k_split(const float* __restrict__ src, bf16* __restrict__ hi,
                        bf16* __restrict__ lo, int n4)
{
    int i = blockIdx.x * blockDim.x + threadIdx.x;
    if (i >= n4) return;
    float4 v = ((const float4*)src)[i];
    uint2 h, l;
    cvt_split(v, h, l);
    ((uint2*)hi)[i] = h;
    ((uint2*)lo)[i] = l;
}

// =====================================================================
// Fused flash attention, split-bf16 HMMA, causal GQA (fp32 in/out).
// =====================================================================
#define FL_QROWS 128
#define FL_KT    64
#define FL_AST   136
#define FL_RB    (FL_AST * 2)
#define FLASH_SMEM ((FL_QROWS + 2 * FL_KT) * FL_RB)   // 69632

__global__ void __launch_bounds__(256, 2)
k_flash(const float* __restrict__ qkv, float* __restrict__ attn)
{
    extern __shared__ char sm8[];
    const uint32_t sQ = smem_to_u32(sm8);
    const uint32_t sK = sQ + FL_QROWS * FL_RB;
    const uint32_t sV = sK + FL_KT * FL_RB;
    char* pQ = sm8;
    char* pK = sm8 + FL_QROWS * FL_RB;
    char* pV = pK + FL_KT * FL_RB;

    const int tid = threadIdx.x, lane = tid & 31, wid = tid >> 5;
    const int lrow = lane & 15, lsel = lane >> 4;
    const int bh = blockIdx.x;
    const int b = bh >> 4, hq = bh & 15, hk = hq >> 2;
    const int q0 = (int)(gridDim.y - 1 - blockIdx.y) * FL_QROWS;

    const int seqstride = B_ * QKV_OUT_;
    const float* Qg = qkv + (size_t)b * QKV_OUT_ + hq * HD_;
    const float* Kg = qkv + (size_t)b * QKV_OUT_ + NH_ * HD_ + hk * HD_;
    const float* Vg = qkv + (size_t)b * QKV_OUT_ + (NH_ + NKV_) * HD_ + hk * HD_;

    #pragma unroll
    for (int i = 0; i < 8; i++) {
        int f = tid + i * 256;
        int row = f >> 4, c4 = f & 15;
        float4 v = *(const float4*)&Qg[(size_t)(q0 + row) * seqstride + c4 * 4];
        uint2 hi, lo;
        cvt_split(v, hi, lo);
        char* pr = pQ + row * FL_RB;
        *(uint2*)(pr + c4 * 8) = hi;
        *(uint2*)(pr + 128 + c4 * 8) = lo;
    }

    float accO[8][4] = {};
    float S[8][4];
    float m0 = -1e30f, m1 = -1e30f, l0 = 0.f, l1 = 0.f;

    const int rbase = q0 + wid * 16;
    const int q_hi = rbase + 15;
    const int jmax = (q0 >> 6) + 2;

    for (int j = 0; j < jmax; j++) {
        const int jbase = j * FL_KT;
        #pragma unroll
        for (int i = 0; i < 4; i++) {
            int f = tid + i * 256;
            int row = f >> 4, c4 = f & 15;
            size_t go = (size_t)(jbase + row) * seqstride + c4 * 4;
            uint2 hi, lo;
            float4 v = *(const float4*)&Kg[go];
            cvt_split(v, hi, lo);
            char* pr = pK + row * FL_RB;
            *(uint2*)(pr + c4 * 8) = hi;
            *(uint2*)(pr + 128 + c4 * 8) = lo;
            v = *(const float4*)&Vg[go];
            cvt_split(v, hi, lo);
            pr = pV + row * FL_RB;
            *(uint2*)(pr + c4 * 8) = hi;
            *(uint2*)(pr + 128 + c4 * 8) = lo;
        }
        __syncthreads();

        if (jbase <= q_hi) {
            #pragma unroll
            for (int t = 0; t < 8; t++) {
                S[t][0] = 0.f; S[t][1] = 0.f; S[t][2] = 0.f; S[t][3] = 0.f;
            }
            #pragma unroll
            for (int s = 0; s < 4; s++) {
                uint32_t qh[4], ql[4], kb[4][2];
                uint32_t qaddr = sQ + (uint32_t)(wid * 16 + lrow) * FL_RB +
                                 (s * 16 + lsel * 8) * 2;
                ldsm_x4(qh[0], qh[1], qh[2], qh[3], qaddr);
                ldsm_x4(ql[0], ql[1], ql[2], ql[3], qaddr + 128);
                #pragma unroll
                for (int g = 0; g < 4; g++) {
                    uint32_t r0, r1, r2, r3;
                    uint32_t kaddr = sK + (uint32_t)(g * 16 + lrow) * FL_RB +
                                     (s * 16 + lsel * 8) * 2;
                    ldsm_x4(r0, r1, r2, r3, kaddr);
                    kb[g][0] = r0; kb[g][1] = r2;
                    mma16816(S[g * 2 + 1], qh[0], qh[1], qh[2], qh[3], r1, r3);
                    mma16816(S[g * 2 + 1], ql[0], ql[1], ql[2], ql[3], r1, r3);
                }
                #pragma unroll
                for (int g = 0; g < 4; g++) {
                    mma16816(S[g * 2], qh[0], qh[1], qh[2], qh[3], kb[g][0], kb[g][1]);
                    mma16816(S[g * 2], ql[0], ql[1], ql[2], ql[3], kb[g][0], kb[g][1]);
                }
                #pragma unroll
                for (int g = 0; g < 4; g++) {
                    uint32_t r0, r1, r2, r3;
                    uint32_t kaddr = sK + (uint32_t)(g * 16 + lrow) * FL_RB +
                                     (64 + s * 16 + lsel * 8) * 2;
                    ldsm_x4(r0, r1, r2, r3, kaddr);
                    mma16816(S[g * 2],     qh[0], qh[1], qh[2], qh[3], r0, r2);
                    mma16816(S[g * 2 + 1], qh[0], qh[1], qh[2], qh[3], r1, r3);
                }
            }

            const float scale = 0.125f;
            #pragma unroll
            for (int t = 0; t < 8; t++) {
                S[t][0] *= scale; S[t][1] *= scale;
                S[t][2] *= scale; S[t][3] *= scale;
            }
            if (jbase + 63 > rbase) {
                int r0g = rbase + (lane >> 2);
                int cg = jbase + (lane & 3) * 2;
                #pragma unroll
                for (int t = 0; t < 8; t++) {
                    int c0 = cg + t * 8;
                    if (c0 > r0g)     S[t][0] = -1e30f;
                    if (c0 + 1 > r0g) S[t][1] = -1e30f;
                    if (c0 > r0g + 8)     S[t][2] = -1e30f;
                    if (c0 + 1 > r0g + 8) S[t][3] = -1e30f;
                }
            }

            float tm0 = -1e30f, tm1 = -1e30f;
            #pragma unroll
            for (int t = 0; t < 8; t++) {
                tm0 = fmaxf(tm0, fmaxf(S[t][0], S[t][1]));
                tm1 = fmaxf(tm1, fmaxf(S[t][2], S[t][3]));
            }
            tm0 = fmaxf(tm0, __shfl_xor_sync(0xFFFFFFFFu, tm0, 1));
            tm0 = fmaxf(tm0, __shfl_xor_sync(0xFFFFFFFFu, tm0, 2));
            tm1 = fmaxf(tm1, __shfl_xor_sync(0xFFFFFFFFu, tm1, 1));
            tm1 = fmaxf(tm1, __shfl_xor_sync(0xFFFFFFFFu, tm1, 2));
            float mn0 = fmaxf(m0, tm0), mn1 = fmaxf(m1, tm1);
            float fac0 = __expf(m0 - mn0), fac1 = __expf(m1 - mn1);

            float ts0 = 0.f, ts1 = 0.f;
            #pragma unroll
            for (int t = 0; t < 8; t++) {
                S[t][0] = __expf(S[t][0] - mn0);
                S[t][1] = __expf(S[t][1] - mn0);
                S[t][2] = __expf(S[t][2] - mn1);
                S[t][3] = __expf(S[t][3] - mn1);
                ts0 += S[t][0] + S[t][1];
                ts1 += S[t][2] + S[t][3];
            }
            ts0 += __shfl_xor_sync(0xFFFFFFFFu, ts0, 1);
            ts0 += __shfl_xor_sync(0xFFFFFFFFu, ts0, 2);
            ts1 += __shfl_xor_sync(0xFFFFFFFFu, ts1, 1);
            ts1 += __shfl_xor_sync(0xFFFFFFFFu, ts1, 2);
            l0 = l0 * fac0 + ts0;
            l1 = l1 * fac1 + ts1;
            m0 = mn0; m1 = mn1;

            #pragma unroll
            for (int t = 0; t < 8; t++) {
                accO[t][0] *= fac0; accO[t][1] *= fac0;
                accO[t][2] *= fac1; accO[t][3] *= fac1;
            }

            #pragma unroll
            for (int s = 0; s < 4; s++) {
                uint32_t ah[4], al[4];
                CVT_BF16X2_F32(ah[0], S[2*s][0],   S[2*s][1]);
                CVT_BF16X2_F32(ah[1], S[2*s][2],   S[2*s][3]);
                CVT_BF16X2_F32(ah[2], S[2*s+1][0], S[2*s+1][1]);
                CVT_BF16X2_F32(ah[3], S[2*s+1][2], S[2*s+1][3]);
                #pragma unroll
                for (int i = 0; i < 4; i++) {
                    const float* sp = (i < 2) ? S[2*s] : S[2*s+1];
                    int o = (i & 1) * 2;
                    float flo = __uint_as_float(ah[i] << 16);
                    float fhi = __uint_as_float(ah[i] & 0xFFFF0000u);
                    CVT_BF16X2_F32(al[i], sp[o] - flo, sp[o + 1] - fhi);
                }
                #pragma unroll
                for (int dg = 0; dg < 4; dg++) {
                    uint32_t vrow = (uint32_t)(s * 16 + ((lane >> 3) & 1) * 8 + (lane & 7));
                    uint32_t vcol = (uint32_t)(dg * 16 + (lane >> 4) * 8);
                    uint32_t vaddr = sV + vrow * FL_RB + vcol * 2;
                    uint32_t h0, h1, h2, h3;
                    ldsm_x4_t(h0, h1, h2, h3, vaddr);
                    mma16816(accO[dg * 2],     ah[0], ah[1], ah[2], ah[3], h0, h1);
                    mma16816(accO[dg * 2],     al[0], al[1], al[2], al[3], h0, h1);
                    mma16816(accO[dg * 2 + 1], ah[0], ah[1], ah[2], ah[3], h2, h3);
                    mma16816(accO[dg * 2 + 1], al[0], al[1], al[2], al[3], h2, h3);
                    uint32_t g0, g1, g2, g3;
                    ldsm_x4_t(g0, g1, g2, g3, vaddr + 128);
                    mma16816(accO[dg * 2],     ah[0], ah[1], ah[2], ah[3], g0, g1);
                    mma16816(accO[dg * 2 + 1], ah[0], ah[1], ah[2], ah[3], g2, g3);
                }
            }
        }
        __syncthreads();
    }

    float inv0 = 1.f / l0, inv1 = 1.f / l1;
    int r0g = rbase + (lane >> 2);
    float* Og = attn + (size_t)b * H_ + hq * HD_;
    const int ostride = B_ * H_;
    #pragma unroll
    for (int t = 0; t < 8; t++) {
        int gd = t * 8 + (lane & 3) * 2;
        *(float2*)&Og[(size_t)r0g * ostride + gd] =
            make_float2(accO[t][0] * inv0, accO[t][1] * inv0);
        *(float2*)&Og[(size_t)(r0g + 8) * ostride + gd] =
            make_float2(accO[t][2] * inv1, accO[t][3] * inv1);
    }
}

// ---------------- layernorm ----------------
__global__ void k_layernorm(const float* __restrict__ x, const float* __restrict__ w,
                            const float* __restrict__ b, float* __restrict__ y)
{
    int t = blockIdx.x;
    const float* xr = x + (size_t)t * H_;
    float* yr = y + (size_t)t * H_;
    float v[4], s = 0.f, s2 = 0.f;
    #pragma unroll
    for (int i = 0; i < 4; i++) {
        v[i] = xr[threadIdx.x + i * 256];
        s += v[i]; s2 += v[i] * v[i];
    }
    __shared__ float r1[256], r2[256];
    r1[threadIdx.x] = s; r2[threadIdx.x] = s2;
    __syncthreads();
    for (int o = 128; o; o >>= 1) {
        if (threadIdx.x < o) {
            r1[threadIdx.x] += r1[threadIdx.x + o];
            r2[threadIdx.x] += r2[threadIdx.x + o];
        }
        __syncthreads();
    }
    float mean = r1[0] * (1.0f / H_);
    float var  = r2[0] * (1.0f / H_) - mean * mean;
    float inv  = rsqrtf(var + 1e-5f);
    #pragma unroll
    for (int i = 0; i < 4; i++) {
        int h = threadIdx.x + i * 256;
        yr[h] = (v[i] - mean) * inv * w[h] + b[h];
    }
}

// ---------------- router ----------------
__global__ void k_router(const float* __restrict__ ln2, const float* __restrict__ Wr,
                         int* __restrict__ expidx, float* __restrict__ gate)
{
    int t = blockIdx.x;
    __shared__ float logits[E_];
    int w = threadIdx.x >> 5, lane = threadIdx.x & 31;
    const float* x = ln2 + (size_t)t * H_;
    const float* wr = Wr + (size_t)w * H_;
    float s = 0.f;
    for (int i = lane; i < H_; i += 32) s += x[i] * wr[i];
    #pragma unroll
    for (int o = 16; o; o >>= 1) s += __shfl_xor_sync(0xFFFFFFFFu, s, o);
    if (lane == 0) logits[w] = s;
    __syncthreads();
    if (threadIdx.x == 0) {
        float lmax = -1e30f;
        #pragma unroll
        for (int e = 0; e < E_; e++) lmax = fmaxf(lmax, logits[e]);
        float den = 0.f;
        #pragma unroll
        for (int e = 0; e < E_; e++) den += expf(logits[e] - lmax);
        int i1 = 0; float v1 = logits[0];
        #pragma unroll
        for (int e = 1; e < E_; e++) if (logits[e] > v1) { v1 = logits[e]; i1 = e; }
        int i2 = -1; float v2 = -1e30f;
        #pragma unroll
        for (int e = 0; e < E_; e++) if (e != i1 && logits[e] > v2) { v2 = logits[e]; i2 = e; }
        float inv = 1.0f / den;
        expidx[2 * t]     = i1;  gate[2 * t]     = expf(v1 - lmax) * inv;
        expidx[2 * t + 1] = i2;  gate[2 * t + 1] = expf(v2 - lmax) * inv;
    }
}

// ---------------- slot positions + per-expert counts (ballot scan) ----------
__global__ void k_pos(const int* __restrict__ expidx, int* __restrict__ pos,
                      int* __restrict__ cnt)
{
    __shared__ int sidx[NSLOT_];
    for (int i = threadIdx.x; i < NSLOT_; i += 512) sidx[i] = expidx[i];
    __syncthreads();
    int w = threadIdx.x >> 5, lane = threadIdx.x & 31;
    int c = 0;
    for (int base = 0; base < NSLOT_; base += 32) {
        bool f = (sidx[base + lane] == w);
        unsigned m = __ballot_sync(0xFFFFFFFFu, f);
        if (f) pos[base + lane] = c + __popc(m & ((1u << lane) - 1));
        c += __popc(m);
    }
    if (lane == 0) cnt[w] = (c < CAP_) ? c : CAP_;
}

// ---------------- dispatch kept slots into expert buffer ----------------
__global__ void k_dispatch(const float* __restrict__ ln2, const int* __restrict__ expidx,
                           const int* __restrict__ pos, float* __restrict__ buf)
{
    int slot = blockIdx.x;
    int p = pos[slot];
    if (p >= CAP_) return;
    int e = expidx[slot];
    int t = slot >> 1;
    const float* src = ln2 + (size_t)t * H_;
    float* dst = buf + ((size_t)e * CAP_ + p) * H_;
    for (int h = threadIdx.x; h < H_; h += 256) dst[h] = src[h];
}

// ---------------- combine: residual + gated expert outputs ----------------
__global__ void k_combine(const float* __restrict__ hattn, const float* __restrict__ h2,
                          const int* __restrict__ expidx, const int* __restrict__ pos,
                          const float* __restrict__ gate, float* __restrict__ out)
{
    int t = blockIdx.x;
    int s0 = 2 * t, s1 = 2 * t + 1;
    int p0 = pos[s0], p1 = pos[s1];
    int e0 = expidx[s0], e1 = expidx[s1];
    float g0 = (p0 < CAP_) ? gate[s0] : 0.f;
    float g1 = (p1 < CAP_) ? gate[s1] : 0.f;
    const float* r0 = (p0 < CAP_) ? h2 + ((size_t)e0 * CAP_ + p0) * H_ : nullptr;
    const float* r1 = (p1 < CAP_) ? h2 + ((size_t)e1 * CAP_ + p1) * H_ : nullptr;
    for (int h = threadIdx.x; h < H_; h += 256) {
        float v = hattn[(size_t)t * H_ + h];
        if (r0) v += r0[h] * g0;
        if (r1) v += r1[h] * g1;
        out[(size_t)t * H_ + h] = v;
    }
}

// ---------------- launch ----------------
extern "C" void kernel_launch(void* const* d_in, const int* in_sizes, int n_in,
                              void* d_out, int out_size)
{
    const float* hidden  = (const float*)d_in[0];
    const float* ln1w    = (const float*)d_in[1];
    const float* ln1b    = (const float*)d_in[2];
    const float* ln2w    = (const float*)d_in[3];
    const float* ln2b    = (const float*)d_in[4];
    const float* qkvw    = (const float*)d_in[5];
    const float* projw   = (const float*)d_in[6];
    const float* routerw = (const float*)d_in[7];
    const float* w1      = (const float*)d_in[8];
    const float* w2      = (const float*)d_in[9];
    float* out = (float*)d_out;

    float *ln1, *qkv, *attn, *hattn, *ln2, *gatep, *buf, *h1, *h2;
    int *expidx, *pos, *cnt;
    bf16 *qkvwh, *qkvwl, *projwh, *projwl, *w1h, *w1l, *w2h, *w2l;
    cudaGetSymbolAddress((void**)&ln1,    g_ln1);
    cudaGetSymbolAddress((void**)&qkv,    g_qkv);
    cudaGetSymbolAddress((void**)&attn,   g_attn);
    cudaGetSymbolAddress((void**)&hattn,  g_hattn);
    cudaGetSymbolAddress((void**)&ln2,    g_ln2);
    cudaGetSymbolAddress((void**)&expidx, g_expidx);
    cudaGetSymbolAddress((void**)&pos,    g_pos);
    cudaGetSymbolAddress((void**)&cnt,    g_cnt);
    cudaGetSymbolAddress((void**)&gatep,  g_gate);
    cudaGetSymbolAddress((void**)&buf,    g_buf);
    cudaGetSymbolAddress((void**)&h1,     g_h1);
    cudaGetSymbolAddress((void**)&h2,     g_h2);
    cudaGetSymbolAddress((void**)&qkvwh,  g_qkvwh);
    cudaGetSymbolAddress((void**)&qkvwl,  g_qkvwl);
    cudaGetSymbolAddress((void**)&projwh, g_projwh);
    cudaGetSymbolAddress((void**)&projwl, g_projwl);
    cudaGetSymbolAddress((void**)&w1h,    g_w1h);
    cudaGetSymbolAddress((void**)&w1l,    g_w1l);
    cudaGetSymbolAddress((void**)&w2h,    g_w2h);
    cudaGetSymbolAddress((void**)&w2l,    g_w2l);

    cudaFuncSetAttribute((void*)k_hmma_nt<EpiStore>,
                         cudaFuncAttributeMaxDynamicSharedMemorySize, HMMA_SMEM_BYTES);
    cudaFuncSetAttribute((void*)k_hmma_nt<EpiResidual>,
                         cudaFuncAttributeMaxDynamicSharedMemorySize, HMMA_SMEM_BYTES);
    cudaFuncSetAttribute((void*)k_hmma_nt<EpiGelu>,
                         cudaFuncAttributeMaxDynamicSharedMemorySize, HMMA_SMEM_BYTES);
    cudaFuncSetAttribute((void*)k_flash,
                         cudaFuncAttributeMaxDynamicSharedMemorySize, FLASH_SMEM);

    // weight preconversion (B operand of every GEMM)
    k_split<<<(QKV_OUT_ * H_ / 4 + 255) / 256, 256>>>(qkvw, qkvwh, qkvwl, QKV_OUT_ * H_ / 4);
    k_split<<<(H_ * H_ / 4 + 255) / 256, 256>>>(projw, projwh, projwl, H_ * H_ / 4);
    k_split<<<(E_ * FFN_ * H_ / 4 + 255) / 256, 256>>>(w1, w1h, w1l, E_ * FFN_ * H_ / 4);
    k_split<<<(E_ * H_ * FFN_ / 4 + 255) / 256, 256>>>(w2, w2h, w2l, E_ * H_ * FFN_ / 4);

    // LN1
    k_layernorm<<<T_, 256>>>(hidden, ln1w, ln1b, ln1);
    // QKV = ln1 @ W_qkv^T (HMMA split-bf16, weight planes)
    k_hmma_nt<<<dim3(QKV_OUT_ / 128, T_ / 128, 1), 256, HMMA_SMEM_BYTES>>>(
        ln1, H_, (size_t)0, qkvwh, qkvwl, H_, (size_t)0, qkv, QKV_OUT_, (size_t)0, H_,
        EpiStore{}, nullptr);
    // fused causal flash attention (HMMA split-bf16)
    k_flash<<<dim3(B_ * NH_, S_ / FL_QROWS), 256, FLASH_SMEM>>>(qkv, attn);
    // proj + residual (HMMA, weight planes)
    k_hmma_nt<<<dim3(H_ / 128, T_ / 128, 1), 256, HMMA_SMEM_BYTES>>>(
        attn, H_, (size_t)0, projwh, projwl, H_, (size_t)0, hattn, H_, (size_t)0, H_,
        EpiResidual{hidden, H_}, nullptr);
    // LN2
    k_layernorm<<<T_, 256>>>(hattn, ln2w, ln2b, ln2);
    // router top-2
    k_router<<<T_, 512>>>(ln2, routerw, expidx, gatep);
    // slot positions + counts
    k_pos<<<1, 512>>>(expidx, pos, cnt);
    // dispatch (rows >= cnt[e] never read by combine; no zeroing needed)
    k_dispatch<<<NSLOT_, 256>>>(ln2, expidx, pos, buf);
    // expert FC1 (gelu) and FC2 (HMMA, weight planes, count-gated)
    k_hmma_nt<<<dim3(FFN_ / 128, CAP_ / 128, E_), 256, HMMA_SMEM_BYTES>>>(
        buf, H_, (size_t)CAP_ * H_, w1h, w1l, H_, (size_t)FFN_ * H_,
        h1, FFN_, (size_t)CAP_ * FFN_, H_, EpiGelu{}, cnt);
    k_hmma_nt<<<dim3(H_ / 128, CAP_ / 128, E_), 256, HMMA_SMEM_BYTES>>>(
        h1, FFN_, (size_t)CAP_ * FFN_, w2h, w2l, FFN_, (size_t)H_ * FFN_,
        h2, H_, (size_t)CAP_ * H_, FFN_, EpiStore{}, cnt);
    // combine + final residual
    k_combine<<<T_, 256>>>(hattn, h2, expidx, pos, gatep, out);
}

// round 12
// speedup vs baseline: 1.7126x; 1.7126x over previous
#include <cuda_runtime.h>
#include <cuda_bf16.h>
#include <cuda_fp16.h>
#include <math.h>
#include <stdint.h>

// ---------------- problem constants ----------------
#define S_   2048
#define B_   2
#define H_   1024
#define NH_  16
#define NKV_ 4
#define HD_  64
#define T_   4096            // S_*B_
#define QKV_OUT_ 1536
#define E_   16
#define TOPK_ 2
#define FFN_ 2048
#define CAP_ 640             // ceil(T*K/E*1.25)
#define NSLOT_ (T_*TOPK_)

// ---------------- scratch (device globals; no runtime allocation) ----------------
__device__ float g_ln1[(size_t)T_*H_];
__device__ float g_qkv[(size_t)T_*QKV_OUT_];
__device__ float g_attn[(size_t)T_*H_];
__device__ float g_hattn[(size_t)T_*H_];
__device__ float g_ln2[(size_t)T_*H_];
__device__ int   g_expidx[NSLOT_];
__device__ int   g_pos[NSLOT_];
__device__ int   g_cnt[E_];
__device__ float g_gate[NSLOT_];
__device__ float g_buf[(size_t)E_*CAP_*H_];
__device__ float g_h1[(size_t)E_*CAP_*FFN_];
__device__ float g_h2[(size_t)E_*CAP_*H_];

// =====================================================================
// PTX helpers (baseline sm_80+ ISA — tcgen05 unavailable on this
// build target, verified by R2 ptxas errors)
// =====================================================================
__device__ __forceinline__ uint32_t smem_to_u32(const void* smem_ptr) {
    uint32_t addr;
    asm("{ .reg .u64 tmp; cvta.to.shared.u64 tmp, %1; cvt.u32.u64 %0, tmp; }"
        : "=r"(addr) : "l"(smem_ptr));
    return addr;
}

#define CVT_BF16X2_F32(result, a, b) \
    asm("cvt.rn.satfinite.bf16x2.f32 %0, %1, %2;" : "=r"(result) : "f"(b), "f"(a))

__device__ __forceinline__ void ldsm_x4(uint32_t& r0, uint32_t& r1,
                                        uint32_t& r2, uint32_t& r3, uint32_t addr) {
    asm volatile("ldmatrix.sync.aligned.m8n8.x4.shared.b16 {%0,%1,%2,%3}, [%4];"
                 : "=r"(r0), "=r"(r1), "=r"(r2), "=r"(r3) : "r"(addr));
}
__device__ __forceinline__ void ldsm_x4_t(uint32_t& r0, uint32_t& r1,
                                          uint32_t& r2, uint32_t& r3, uint32_t addr) {
    asm volatile("ldmatrix.sync.aligned.m8n8.x4.trans.shared.b16 {%0,%1,%2,%3}, [%4];"
                 : "=r"(r0), "=r"(r1), "=r"(r2), "=r"(r3) : "r"(addr));
}

// bf16 MMA (flash)
__device__ __forceinline__ void mma16816(float* c,
        uint32_t a0, uint32_t a1, uint32_t a2, uint32_t a3,
        uint32_t b0, uint32_t b1) {
    asm volatile(
        "mma.sync.aligned.m16n8k16.row.col.f32.bf16.bf16.f32 "
        "{%0,%1,%2,%3}, {%4,%5,%6,%7}, {%8,%9}, {%0,%1,%2,%3};"
        : "+f"(c[0]), "+f"(c[1]), "+f"(c[2]), "+f"(c[3])
        : "r"(a0), "r"(a1), "r"(a2), "r"(a3), "r"(b0), "r"(b1));
}
// fp16 MMA (GEMMs)
__device__ __forceinline__ void mma16816h(float* c,
        uint32_t a0, uint32_t a1, uint32_t a2, uint32_t a3,
        uint32_t b0, uint32_t b1) {
    asm volatile(
        "mma.sync.aligned.m16n8k16.row.col.f32.f16.f16.f32 "
        "{%0,%1,%2,%3}, {%4,%5,%6,%7}, {%8,%9}, {%0,%1,%2,%3};"
        : "+f"(c[0]), "+f"(c[1]), "+f"(c[2]), "+f"(c[3])
        : "r"(a0), "r"(a1), "r"(a2), "r"(a3), "r"(b0), "r"(b1));
}

// fp32 float4 -> (hi, lo) split bf16 (flash path)
__device__ __forceinline__ void cvt_split(float4 v, uint2& hi, uint2& lo) {
    uint32_t h01, h23, l01, l23;
    CVT_BF16X2_F32(h01, v.x, v.y);
    CVT_BF16X2_F32(h23, v.z, v.w);
    float f0 = __uint_as_float(h01 << 16), f1 = __uint_as_float(h01 & 0xFFFF0000u);
    float f2 = __uint_as_float(h23 << 16), f3 = __uint_as_float(h23 & 0xFFFF0000u);
    CVT_BF16X2_F32(l01, v.x - f0, v.y - f1);
    CVT_BF16X2_F32(l23, v.z - f2, v.w - f3);
    hi = make_uint2(h01, h23); lo = make_uint2(l01, l23);
}

// fp32 float4 -> (hi, lo) split fp16 (GEMM A operand)
__device__ __forceinline__ void cvt_split_h(float4 v, uint2& hi, uint2& lo) {
    __half2 h01 = __float22half2_rn(make_float2(v.x, v.y));
    __half2 h23 = __float22half2_rn(make_float2(v.z, v.w));
    float2 f01 = __half22float2(h01), f23 = __half22float2(h23);
    __half2 l01 = __float22half2_rn(make_float2(v.x - f01.x, v.y - f01.y));
    __half2 l23 = __float22half2_rn(make_float2(v.z - f23.x, v.w - f23.y));
    hi = make_uint2(*(uint32_t*)&h01, *(uint32_t*)&h23);
    lo = make_uint2(*(uint32_t*)&l01, *(uint32_t*)&l23);
}
// fp32 float4 -> fp16 hi only (GEMM B operand)
__device__ __forceinline__ uint2 cvt_h(float4 v) {
    __half2 h01 = __float22half2_rn(make_float2(v.x, v.y));
    __half2 h23 = __float22half2_rn(make_float2(v.z, v.w));
    return make_uint2(*(uint32_t*)&h01, *(uint32_t*)&h23);
}

// ---------------- epilogues ----------------
struct EpiStore {
    __device__ __forceinline__ float op(float v, int, int) const { return v; }
};
struct EpiResidual {
    const float* r; int ld;
    __device__ __forceinline__ float op(float v, int m, int n) const {
        return v + r[(size_t)m * ld + n];
    }
};
struct EpiGelu {
    __device__ __forceinline__ float op(float v, int, int) const {
        float x = 0.7978845608028654f * (v + 0.044715f * v * v * v);
        float t = 1.0f - 2.0f / (__expf(2.0f * x) + 1.0f);
        return 0.5f * v * (1.0f + t);
    }
};

// =====================================================================
// fp16 2-product split HMMA NT GEMM: C[M,N] = A[M,K] * B[N,K]^T
// A split (Ah+Al) fp16; B rounded to fp16. C = Ah*Bh + Al*Bh.
// Error = A*Bl ~ 2^-12 rel per element, ~1.4e-4 per GEMM dot (K>=1024).
// 128x128 tile, 8 warps (64x32), K-chunk 64. 128 MMA/chunk (was 192).
// Optional per-z row-count gating (MoE early exit).
// =====================================================================
#define CH_  64
#define AST  136                              // A row: hi64|lo64|pad8
#define BST  72                               // B row: hi64|pad8
#define HMMA_SMEM_BYTES ((128*AST + 128*BST) * 2)   // 53248

template<typename Epi>
__global__ void __launch_bounds__(256, 2)
k_hmma_nt(const float* __restrict__ A, int lda, size_t aB,
          const float* __restrict__ B, int ldb, size_t bB,
          float* __restrict__ C, int ldc, size_t cB,
          int K, Epi epi, const int* __restrict__ cnt)
{
    if (cnt) {
        int lim = cnt[blockIdx.z];
        if (lim > CAP_) lim = CAP_;
        if ((int)(blockIdx.y * 128) >= lim) return;
    }

    extern __shared__ __half sm[];
    __half (*As)[AST] = (__half(*)[AST])sm;
    __half (*Bs)[BST] = (__half(*)[BST])(sm + 128 * AST);

    const int tid = threadIdx.x, lane = tid & 31, wid = tid >> 5;
    const int m0 = blockIdx.y * 128, n0 = blockIdx.x * 128;
    A += (size_t)blockIdx.z * aB;
    B += (size_t)blockIdx.z * bB;
    C += (size_t)blockIdx.z * cB;
    const int warpM = (wid >> 2) * 64, warpN = (wid & 3) * 32;

    float acc[4][4][4] = {};

    const uint32_t sA = smem_to_u32(As), sB = smem_to_u32(Bs);
    const int lrow = lane & 15, lsel = lane >> 4;

    for (int k0 = 0; k0 < K; k0 += CH_) {
        #pragma unroll
        for (int i = 0; i < 8; i++) {
            int f = tid + i * 256;
            int row = f >> 4, kq = f & 15;

            float4 va = *(const float4*)&A[(size_t)(m0 + row) * lda + k0 + kq * 4];
            uint2 hi, lo;
            cvt_split_h(va, hi, lo);
            *(uint2*)&As[row][kq * 4]      = hi;
            *(uint2*)&As[row][64 + kq * 4] = lo;

            float4 vb = *(const float4*)&B[(size_t)(n0 + row) * ldb + k0 + kq * 4];
            *(uint2*)&Bs[row][kq * 4] = cvt_h(vb);
        }
        __syncthreads();

        // 8 k16-step products: Ah*Bh (4 steps) then Al*Bh (4 steps)
        const int AO[8] = {0, 16, 32, 48, 64, 80, 96, 112};
        const int BO[8] = {0, 16, 32, 48, 0, 16, 32, 48};
        #pragma unroll
        for (int s = 0; s < 8; s++) {
            uint32_t af[4][4];
            #pragma unroll
            for (int mt = 0; mt < 4; mt++) {
                uint32_t addr = sA +
                    ((uint32_t)(warpM + mt * 16 + lrow) * AST + AO[s] + lsel * 8) * 2;
                ldsm_x4(af[mt][0], af[mt][1], af[mt][2], af[mt][3], addr);
            }
            uint32_t bf[4][2];
            #pragma unroll
            for (int pt = 0; pt < 2; pt++) {
                uint32_t r0, r1, r2, r3;
                uint32_t addr = sB +
                    ((uint32_t)(warpN + pt * 16 + lrow) * BST + BO[s] + lsel * 8) * 2;
                ldsm_x4(r0, r1, r2, r3, addr);
                bf[pt * 2][0] = r0;     bf[pt * 2][1] = r2;
                bf[pt * 2 + 1][0] = r1; bf[pt * 2 + 1][1] = r3;
            }
            #pragma unroll
            for (int mt = 0; mt < 4; mt++)
                #pragma unroll
                for (int nt = 0; nt < 4; nt++)
                    mma16816h(acc[mt][nt], af[mt][0], af[mt][1], af[mt][2], af[mt][3],
                              bf[nt][0], bf[nt][1]);
        }
        __syncthreads();
    }

    const int r = lane >> 2, cpair = (lane & 3) * 2;
    #pragma unroll
    for (int mt = 0; mt < 4; mt++) {
        int gm0 = m0 + warpM + mt * 16 + r;
        #pragma unroll
        for (int nt = 0; nt < 4; nt++) {
            int gn = n0 + warpN + nt * 8 + cpair;
            float2 v0 = make_float2(epi.op(acc[mt][nt][0], gm0, gn),
                                    epi.op(acc[mt][nt][1], gm0, gn + 1));
            *(float2*)&C[(size_t)gm0 * ldc + gn] = v0;
            float2 v1 = make_float2(epi.op(acc[mt][nt][2], gm0 + 8, gn),
                                    epi.op(acc[mt][nt][3], gm0 + 8, gn + 1));
            *(float2*)&C[(size_t)(gm0 + 8) * ldc + gn] = v1;
        }
    }
}

// =====================================================================
// Fused flash attention, split-bf16 3-product HMMA (kept — exp amplifies
// logit error; bf16-3 gives 2^-16 logits), causal GQA (fp32 in/out).
// =====================================================================
#define FL_QROWS 128
#define FL_KT    64
#define FL_AST   136
#define FL_RB    (FL_AST * 2)
#define FLASH_SMEM ((FL_QROWS + 2 * FL_KT) * FL_RB)   // 69632

__global__ void __launch_bounds__(256, 2)
k_flash(const float* __restrict__ qkv, float* __restrict__ attn)
{
    extern __shared__ char sm8[];
    const uint32_t sQ = smem_to_u32(sm8);
    const uint32_t sK = sQ + FL_QROWS * FL_RB;
    const uint32_t sV = sK + FL_KT * FL_RB;
    char* pQ = sm8;
    char* pK = sm8 + FL_QROWS * FL_RB;
    char* pV = pK + FL_KT * FL_RB;

    const int tid = threadIdx.x, lane = tid & 31, wid = tid >> 5;
    const int lrow = lane & 15, lsel = lane >> 4;
    const int bh = blockIdx.x;
    const int b = bh >> 4, hq = bh & 15, hk = hq >> 2;
    const int q0 = (int)(gridDim.y - 1 - blockIdx.y) * FL_QROWS;

    const int seqstride = B_ * QKV_OUT_;
    const float* Qg = qkv + (size_t)b * QKV_OUT_ + hq * HD_;
    const float* Kg = qkv + (size_t)b * QKV_OUT_ + NH_ * HD_ + hk * HD_;
    const float* Vg = qkv + (size_t)b * QKV_OUT_ + (NH_ + NKV_) * HD_ + hk * HD_;

    #pragma unroll
    for (int i = 0; i < 8; i++) {
        int f = tid + i * 256;
        int row = f >> 4, c4 = f & 15;
        float4 v = *(const float4*)&Qg[(size_t)(q0 + row) * seqstride + c4 * 4];
        uint2 hi, lo;
        cvt_split(v, hi, lo);
        char* pr = pQ + row * FL_RB;
        *(uint2*)(pr + c4 * 8) = hi;
        *(uint2*)(pr + 128 + c4 * 8) = lo;
    }

    float accO[8][4] = {};
    float S[8][4];
    float m0 = -1e30f, m1 = -1e30f, l0 = 0.f, l1 = 0.f;

    const int rbase = q0 + wid * 16;
    const int q_hi = rbase + 15;
    const int jmax = (q0 >> 6) + 2;

    for (int j = 0; j < jmax; j++) {
        const int jbase = j * FL_KT;
        #pragma unroll
        for (int i = 0; i < 4; i++) {
            int f = tid + i * 256;
            int row = f >> 4, c4 = f & 15;
            size_t go = (size_t)(jbase + row) * seqstride + c4 * 4;
            uint2 hi, lo;
            float4 v = *(const float4*)&Kg[go];
            cvt_split(v, hi, lo);
            char* pr = pK + row * FL_RB;
            *(uint2*)(pr + c4 * 8) = hi;
            *(uint2*)(pr + 128 + c4 * 8) = lo;
            v = *(const float4*)&Vg[go];
            cvt_split(v, hi, lo);
            pr = pV + row * FL_RB;
            *(uint2*)(pr + c4 * 8) = hi;
            *(uint2*)(pr + 128 + c4 * 8) = lo;
        }
        __syncthreads();

        if (jbase <= q_hi) {
            #pragma unroll
            for (int t = 0; t < 8; t++) {
                S[t][0] = 0.f; S[t][1] = 0.f; S[t][2] = 0.f; S[t][3] = 0.f;
            }
            #pragma unroll
            for (int s = 0; s < 4; s++) {
                uint32_t qh[4], ql[4], kb[4][2];
                uint32_t qaddr = sQ + (uint32_t)(wid * 16 + lrow) * FL_RB +
                                 (s * 16 + lsel * 8) * 2;
                ldsm_x4(qh[0], qh[1], qh[2], qh[3], qaddr);
                ldsm_x4(ql[0], ql[1], ql[2], ql[3], qaddr + 128);
                #pragma unroll
                for (int g = 0; g < 4; g++) {
                    uint32_t r0, r1, r2, r3;
                    uint32_t kaddr = sK + (uint32_t)(g * 16 + lrow) * FL_RB +
                                     (s * 16 + lsel * 8) * 2;
                    ldsm_x4(r0, r1, r2, r3, kaddr);
                    kb[g][0] = r0; kb[g][1] = r2;
                    mma16816(S[g * 2 + 1], qh[0], qh[1], qh[2], qh[3], r1, r3);
                    mma16816(S[g * 2 + 1], ql[0], ql[1], ql[2], ql[3], r1, r3);
                }
                #pragma unroll
                for (int g = 0; g < 4; g++) {
                    mma16816(S[g * 2], qh[0], qh[1], qh[2], qh[3], kb[g][0], kb[g][1]);
                    mma16816(S[g * 2], ql[0], ql[1], ql[2], ql[3], kb[g][0], kb[g][1]);
                }
                #pragma unroll
                for (int g = 0; g < 4; g++) {
                    uint32_t r0, r1, r2, r3;
                    uint32_t kaddr = sK + (uint32_t)(g * 16 + lrow) * FL_RB +
                                     (64 + s * 16 + lsel * 8) * 2;
                    ldsm_x4(r0, r1, r2, r3, kaddr);
                    mma16816(S[g * 2],     qh[0], qh[1], qh[2], qh[3], r0, r2);
                    mma16816(S[g * 2 + 1], qh[0], qh[1], qh[2], qh[3], r1, r3);
                }
            }

            const float scale = 0.125f;
            #pragma unroll
            for (int t = 0; t < 8; t++) {
                S[t][0] *= scale; S[t][1] *= scale;
                S[t][2] *= scale; S[t][3] *= scale;
            }
            if (jbase + 63 > rbase) {
                int r0g = rbase + (lane >> 2);
                int cg = jbase + (lane & 3) * 2;
                #pragma unroll
                for (int t = 0; t < 8; t++) {
                    int c0 = cg + t * 8;
                    if (c0 > r0g)     S[t][0] = -1e30f;
                    if (c0 + 1 > r0g) S[t][1] = -1e30f;
                    if (c0 > r0g + 8)     S[t][2] = -1e30f;
                    if (c0 + 1 > r0g + 8) S[t][3] = -1e30f;
                }
            }

            float tm0 = -1e30f, tm1 = -1e30f;
            #pragma unroll
            for (int t = 0; t < 8; t++) {
                tm0 = fmaxf(tm0, fmaxf(S[t][0], S[t][1]));
                tm1 = fmaxf(tm1, fmaxf(S[t][2], S[t][3]));
            }
            tm0 = fmaxf(tm0, __shfl_xor_sync(0xFFFFFFFFu, tm0, 1));
            tm0 = fmaxf(tm0, __shfl_xor_sync(0xFFFFFFFFu, tm0, 2));
            tm1 = fmaxf(tm1, __shfl_xor_sync(0xFFFFFFFFu, tm1, 1));
            tm1 = fmaxf(tm1, __shfl_xor_sync(0xFFFFFFFFu, tm1, 2));
            float mn0 = fmaxf(m0, tm0), mn1 = fmaxf(m1, tm1);
            float fac0 = __expf(m0 - mn0), fac1 = __expf(m1 - mn1);

            float ts0 = 0.f, ts1 = 0.f;
            #pragma unroll
            for (int t = 0; t < 8; t++) {
                S[t][0] = __expf(S[t][0] - mn0);
                S[t][1] = __expf(S[t][1] - mn0);
                S[t][2] = __expf(S[t][2] - mn1);
                S[t][3] = __expf(S[t][3] - mn1);
                ts0 += S[t][0] + S[t][1];
                ts1 += S[t][2] + S[t][3];
            }
            ts0 += __shfl_xor_sync(0xFFFFFFFFu, ts0, 1);
            ts0 += __shfl_xor_sync(0xFFFFFFFFu, ts0, 2);
            ts1 += __shfl_xor_sync(0xFFFFFFFFu, ts1, 1);
            ts1 += __shfl_xor_sync(0xFFFFFFFFu, ts1, 2);
            l0 = l0 * fac0 + ts0;
            l1 = l1 * fac1 + ts1;
            m0 = mn0; m1 = mn1;

            #pragma unroll
            for (int t = 0; t < 8; t++) {
                accO[t][0] *= fac0; accO[t][1] *= fac0;
                accO[t][2] *= fac1; accO[t][3] *= fac1;
            }

            #pragma unroll
            for (int s = 0; s < 4; s++) {
                uint32_t ah[4], al[4];
                CVT_BF16X2_F32(ah[0], S[2*s][0],   S[2*s][1]);
                CVT_BF16X2_F32(ah[1], S[2*s][2],   S[2*s][3]);
                CVT_BF16X2_F32(ah[2], S[2*s+1][0], S[2*s+1][1]);
                CVT_BF16X2_F32(ah[3], S[2*s+1][2], S[2*s+1][3]);
                #pragma unroll
                for (int i = 0; i < 4; i++) {
                    const float* sp = (i < 2) ? S[2*s] : S[2*s+1];
                    int o = (i & 1) * 2;
                    float flo = __uint_as_float(ah[i] << 16);
                    float fhi = __uint_as_float(ah[i] & 0xFFFF0000u);
                    CVT_BF16X2_F32(al[i], sp[o] - flo, sp[o + 1] - fhi);
                }
                #pragma unroll
                for (int dg = 0; dg < 4; dg++) {
                    uint32_t vrow = (uint32_t)(s * 16 + ((lane >> 3) & 1) * 8 + (lane & 7));
                    uint32_t vcol = (uint32_t)(dg * 16 + (lane >> 4) * 8);
                    uint32_t vaddr = sV + vrow * FL_RB + vcol * 2;
                    uint32_t h0, h1, h2, h3;
                    ldsm_x4_t(h0, h1, h2, h3, vaddr);
                    mma16816(accO[dg * 2],     ah[0], ah[1], ah[2], ah[3], h0, h1);
                    mma16816(accO[dg * 2],     al[0], al[1], al[2], al[3], h0, h1);
                    mma16816(accO[dg * 2 + 1], ah[0], ah[1], ah[2], ah[3], h2, h3);
                    mma16816(accO[dg * 2 + 1], al[0], al[1], al[2], al[3], h2, h3);
                    uint32_t g0, g1, g2, g3;
                    ldsm_x4_t(g0, g1, g2, g3, vaddr + 128);
                    mma16816(accO[dg * 2],     ah[0], ah[1], ah[2], ah[3], g0, g1);
                    mma16816(accO[dg * 2 + 1], ah[0], ah[1], ah[2], ah[3], g2, g3);
                }
            }
        }
        __syncthreads();
    }

    float inv0 = 1.f / l0, inv1 = 1.f / l1;
    int r0g = rbase + (lane >> 2);
    float* Og = attn + (size_t)b * H_ + hq * HD_;
    const int ostride = B_ * H_;
    #pragma unroll
    for (int t = 0; t < 8; t++) {
        int gd = t * 8 + (lane & 3) * 2;
        *(float2*)&Og[(size_t)r0g * ostride + gd] =
            make_float2(accO[t][0] * inv0, accO[t][1] * inv0);
        *(float2*)&Og[(size_t)(r0g + 8) * ostride + gd] =
            make_float2(accO[t][2] * inv1, accO[t][3] * inv1);
    }
}

// ---------------- layernorm ----------------
__global__ void k_layernorm(const float* __restrict__ x, const float* __restrict__ w,
                            const float* __restrict__ b, float* __restrict__ y)
{
    int t = blockIdx.x;
    const float* xr = x + (size_t)t * H_;
    float* yr = y + (size_t)t * H_;
    float v[4], s = 0.f, s2 = 0.f;
    #pragma unroll
    for (int i = 0; i < 4; i++) {
        v[i] = xr[threadIdx.x + i * 256];
        s += v[i]; s2 += v[i] * v[i];
    }
    __shared__ float r1[256], r2[256];
    r1[threadIdx.x] = s; r2[threadIdx.x] = s2;
    __syncthreads();
    for (int o = 128; o; o >>= 1) {
        if (threadIdx.x < o) {
            r1[threadIdx.x] += r1[threadIdx.x + o];
            r2[threadIdx.x] += r2[threadIdx.x + o];
        }
        __syncthreads();
    }
    float mean = r1[0] * (1.0f / H_);
    float var  = r2[0] * (1.0f / H_) - mean * mean;
    float inv  = rsqrtf(var + 1e-5f);
    #pragma unroll
    for (int i = 0; i < 4; i++) {
        int h = threadIdx.x + i * 256;
        yr[h] = (v[i] - mean) * inv * w[h] + b[h];
    }
}

// ---------------- router ----------------
__global__ void k_router(const float* __restrict__ ln2, const float* __restrict__ Wr,
                         int* __restrict__ expidx, float* __restrict__ gate)
{
    int t = blockIdx.x;
    __shared__ float logits[E_];
    int w = threadIdx.x >> 5, lane = threadIdx.x & 31;
    const float* x = ln2 + (size_t)t * H_;
    const float* wr = Wr + (size_t)w * H_;
    float s = 0.f;
    for (int i = lane; i < H_; i += 32) s += x[i] * wr[i];
    #pragma unroll
    for (int o = 16; o; o >>= 1) s += __shfl_xor_sync(0xFFFFFFFFu, s, o);
    if (lane == 0) logits[w] = s;
    __syncthreads();
    if (threadIdx.x == 0) {
        float lmax = -1e30f;
        #pragma unroll
        for (int e = 0; e < E_; e++) lmax = fmaxf(lmax, logits[e]);
        float den = 0.f;
        #pragma unroll
        for (int e = 0; e < E_; e++) den += expf(logits[e] - lmax);
        int i1 = 0; float v1 = logits[0];
        #pragma unroll
        for (int e = 1; e < E_; e++) if (logits[e] > v1) { v1 = logits[e]; i1 = e; }
        int i2 = -1; float v2 = -1e30f;
        #pragma unroll
        for (int e = 0; e < E_; e++) if (e != i1 && logits[e] > v2) { v2 = logits[e]; i2 = e; }
        float inv = 1.0f / den;
        expidx[2 * t]     = i1;  gate[2 * t]     = expf(v1 - lmax) * inv;
        expidx[2 * t + 1] = i2;  gate[2 * t + 1] = expf(v2 - lmax) * inv;
    }
}

// ---------------- slot positions + per-expert counts (ballot scan) ----------
__global__ void k_pos(const int* __restrict__ expidx, int* __restrict__ pos,
                      int* __restrict__ cnt)
{
    __shared__ int sidx[NSLOT_];
    for (int i = threadIdx.x; i < NSLOT_; i += 512) sidx[i] = expidx[i];
    __syncthreads();
    int w = threadIdx.x >> 5, lane = threadIdx.x & 31;
    int c = 0;
    for (int base = 0; base < NSLOT_; base += 32) {
        bool f = (sidx[base + lane] == w);
        unsigned m = __ballot_sync(0xFFFFFFFFu, f);
        if (f) pos[base + lane] = c + __popc(m & ((1u << lane) - 1));
        c += __popc(m);
    }
    if (lane == 0) cnt[w] = (c < CAP_) ? c : CAP_;
}

// ---------------- dispatch kept slots into expert buffer ----------------
__global__ void k_dispatch(const float* __restrict__ ln2, const int* __restrict__ expidx,
                           const int* __restrict__ pos, float* __restrict__ buf)
{
    int slot = blockIdx.x;
    int p = pos[slot];
    if (p >= CAP_) return;
    int e = expidx[slot];
    int t = slot >> 1;
    const float* src = ln2 + (size_t)t * H_;
    float* dst = buf + ((size_t)e * CAP_ + p) * H_;
    for (int h = threadIdx.x; h < H_; h += 256) dst[h] = src[h];
}

// ---------------- combine: residual + gated expert outputs ----------------
__global__ void k_combine(const float* __restrict__ hattn, const float* __restrict__ h2,
                          const int* __restrict__ expidx, const int* __restrict__ pos,
                          const float* __restrict__ gate, float* __restrict__ out)
{
    int t = blockIdx.x;
    int s0 = 2 * t, s1 = 2 * t + 1;
    int p0 = pos[s0], p1 = pos[s1];
    int e0 = expidx[s0], e1 = expidx[s1];
    float g0 = (p0 < CAP_) ? gate[s0] : 0.f;
    float g1 = (p1 < CAP_) ? gate[s1] : 0.f;
    const float* r0 = (p0 < CAP_) ? h2 + ((size_t)e0 * CAP_ + p0) * H_ : nullptr;
    const float* r1 = (p1 < CAP_) ? h2 + ((size_t)e1 * CAP_ + p1) * H_ : nullptr;
    for (int h = threadIdx.x; h < H_; h += 256) {
        float v = hattn[(size_t)t * H_ + h];
        if (r0) v += r0[h] * g0;
        if (r1) v += r1[h] * g1;
        out[(size_t)t * H_ + h] = v;
    }
}

// ---------------- launch ----------------
extern "C" void kernel_launch(void* const* d_in, const int* in_sizes, int n_in,
                              void* d_out, int out_size)
{
    const float* hidden  = (const float*)d_in[0];
    const float* ln1w    = (const float*)d_in[1];
    const float* ln1b    = (const float*)d_in[2];
    const float* ln2w    = (const float*)d_in[3];
    const float* ln2b    = (const float*)d_in[4];
    const float* qkvw    = (const float*)d_in[5];
    const float* projw   = (const float*)d_in[6];
    const float* routerw = (const float*)d_in[7];
    const float* w1      = (const float*)d_in[8];
    const float* w2      = (const float*)d_in[9];
    float* out = (float*)d_out;

    float *ln1, *qkv, *attn, *hattn, *ln2, *gatep, *buf, *h1, *h2;
    int *expidx, *pos, *cnt;
    cudaGetSymbolAddress((void**)&ln1,    g_ln1);
    cudaGetSymbolAddress((void**)&qkv,    g_qkv);
    cudaGetSymbolAddress((void**)&attn,   g_attn);
    cudaGetSymbolAddress((void**)&hattn,  g_hattn);
    cudaGetSymbolAddress((void**)&ln2,    g_ln2);
    cudaGetSymbolAddress((void**)&expidx, g_expidx);
    cudaGetSymbolAddress((void**)&pos,    g_pos);
    cudaGetSymbolAddress((void**)&cnt,    g_cnt);
    cudaGetSymbolAddress((void**)&gatep,  g_gate);
    cudaGetSymbolAddress((void**)&buf,    g_buf);
    cudaGetSymbolAddress((void**)&h1,     g_h1);
    cudaGetSymbolAddress((void**)&h2,     g_h2);

    cudaFuncSetAttribute((void*)k_hmma_nt<EpiStore>,
                         cudaFuncAttributeMaxDynamicSharedMemorySize, HMMA_SMEM_BYTES);
    cudaFuncSetAttribute((void*)k_hmma_nt<EpiResidual>,
                         cudaFuncAttributeMaxDynamicSharedMemorySize, HMMA_SMEM_BYTES);
    cudaFuncSetAttribute((void*)k_hmma_nt<EpiGelu>,
                         cudaFuncAttributeMaxDynamicSharedMemorySize, HMMA_SMEM_BYTES);
    cudaFuncSetAttribute((void*)k_flash,
                         cudaFuncAttributeMaxDynamicSharedMemorySize, FLASH_SMEM);

    // LN1
    k_layernorm<<<T_, 256>>>(hidden, ln1w, ln1b, ln1);
    // QKV = ln1 @ W_qkv^T (HMMA fp16 2-product)
    k_hmma_nt<<<dim3(QKV_OUT_ / 128, T_ / 128, 1), 256, HMMA_SMEM_BYTES>>>(
        ln1, H_, (size_t)0, qkvw, H_, (size_t)0, qkv, QKV_OUT_, (size_t)0, H_,
        EpiStore{}, nullptr);
    // fused causal flash attention (HMMA split-bf16, 3-product)
    k_flash<<<dim3(B_ * NH_, S_ / FL_QROWS), 256, FLASH_SMEM>>>(qkv, attn);
    // proj + residual (HMMA fp16 2-product)
    k_hmma_nt<<<dim3(H_ / 128, T_ / 128, 1), 256, HMMA_SMEM_BYTES>>>(
        attn, H_, (size_t)0, projw, H_, (size_t)0, hattn, H_, (size_t)0, H_,
        EpiResidual{hidden, H_}, nullptr);
    // LN2
    k_layernorm<<<T_, 256>>>(hattn, ln2w, ln2b, ln2);
    // router top-2
    k_router<<<T_, 512>>>(ln2, routerw, expidx, gatep);
    // slot positions + counts
    k_pos<<<1, 512>>>(expidx, pos, cnt);
    // dispatch (rows >= cnt[e] never read by combine; no zeroing needed)
    k_dispatch<<<NSLOT_, 256>>>(ln2, expidx, pos, buf);
    // expert FC1 (gelu) and FC2 (HMMA fp16 2-product, count-gated)
    k_hmma_nt<<<dim3(FFN_ / 128, CAP_ / 128, E_), 256, HMMA_SMEM_BYTES>>>(
        buf, H_, (size_t)CAP_ * H_, w1, H_, (size_t)FFN_ * H_,
        h1, FFN_, (size_t)CAP_ * FFN_, H_, EpiGelu{}, cnt);
    k_hmma_nt<<<dim3(H_ / 128, CAP_ / 128, E_), 256, HMMA_SMEM_BYTES>>>(
        h1, FFN_, (size_t)CAP_ * FFN_, w2, FFN_, (size_t)H_ * FFN_,
        h2, H_, (size_t)CAP_ * H_, FFN_, EpiStore{}, cnt);
    // combine + final residual
    k_combine<<<T_, 256>>>(hattn, h2, expidx, pos, gatep, out);
}

// round 13
// speedup vs baseline: 1.7837x; 1.0415x over previous
#include <cuda_runtime.h>
#include <cuda_bf16.h>
#include <cuda_fp16.h>
#include <math.h>
#include <stdint.h>

// ---------------- problem constants ----------------
#define S_   2048
#define B_   2
#define H_   1024
#define NH_  16
#define NKV_ 4
#define HD_  64
#define T_   4096            // S_*B_
#define QKV_OUT_ 1536
#define E_   16
#define TOPK_ 2
#define FFN_ 2048
#define CAP_ 640             // ceil(T*K/E*1.25)
#define NSLOT_ (T_*TOPK_)

// ---------------- scratch (device globals; no runtime allocation) ----------------
__device__ float g_ln1[(size_t)T_*H_];
__device__ float g_qkv[(size_t)T_*QKV_OUT_];
__device__ float g_attn[(size_t)T_*H_];
__device__ float g_hattn[(size_t)T_*H_];
__device__ float g_ln2[(size_t)T_*H_];
__device__ int   g_expidx[NSLOT_];
__device__ int   g_pos[NSLOT_];
__device__ int   g_cnt[E_];
__device__ float g_gate[NSLOT_];
__device__ float g_buf[(size_t)E_*CAP_*H_];
__device__ float g_h1[(size_t)E_*CAP_*FFN_];
__device__ float g_h2[(size_t)E_*CAP_*H_];

// =====================================================================
// PTX helpers (baseline sm_80+ ISA — tcgen05 unavailable on this
// build target, verified by R2 ptxas errors)
// =====================================================================
__device__ __forceinline__ uint32_t smem_to_u32(const void* smem_ptr) {
    uint32_t addr;
    asm("{ .reg .u64 tmp; cvta.to.shared.u64 tmp, %1; cvt.u32.u64 %0, tmp; }"
        : "=r"(addr) : "l"(smem_ptr));
    return addr;
}

__device__ __forceinline__ void ldsm_x4(uint32_t& r0, uint32_t& r1,
                                        uint32_t& r2, uint32_t& r3, uint32_t addr) {
    asm volatile("ldmatrix.sync.aligned.m8n8.x4.shared.b16 {%0,%1,%2,%3}, [%4];"
                 : "=r"(r0), "=r"(r1), "=r"(r2), "=r"(r3) : "r"(addr));
}
__device__ __forceinline__ void ldsm_x4_t(uint32_t& r0, uint32_t& r1,
                                          uint32_t& r2, uint32_t& r3, uint32_t addr) {
    asm volatile("ldmatrix.sync.aligned.m8n8.x4.trans.shared.b16 {%0,%1,%2,%3}, [%4];"
                 : "=r"(r0), "=r"(r1), "=r"(r2), "=r"(r3) : "r"(addr));
}

// fp16 MMA
__device__ __forceinline__ void mma16816h(float* c,
        uint32_t a0, uint32_t a1, uint32_t a2, uint32_t a3,
        uint32_t b0, uint32_t b1) {
    asm volatile(
        "mma.sync.aligned.m16n8k16.row.col.f32.f16.f16.f32 "
        "{%0,%1,%2,%3}, {%4,%5,%6,%7}, {%8,%9}, {%0,%1,%2,%3};"
        : "+f"(c[0]), "+f"(c[1]), "+f"(c[2]), "+f"(c[3])
        : "r"(a0), "r"(a1), "r"(a2), "r"(a3), "r"(b0), "r"(b1));
}

// fp32 pair -> packed fp16x2
__device__ __forceinline__ uint32_t pack_h2(float a, float b) {
    __half2 h = __float22half2_rn(make_float2(a, b));
    return *(uint32_t*)&h;
}
// fp32 float4 -> (hi, lo) split fp16
__device__ __forceinline__ void cvt_split_h(float4 v, uint2& hi, uint2& lo) {
    __half2 h01 = __float22half2_rn(make_float2(v.x, v.y));
    __half2 h23 = __float22half2_rn(make_float2(v.z, v.w));
    float2 f01 = __half22float2(h01), f23 = __half22float2(h23);
    __half2 l01 = __float22half2_rn(make_float2(v.x - f01.x, v.y - f01.y));
    __half2 l23 = __float22half2_rn(make_float2(v.z - f23.x, v.w - f23.y));
    hi = make_uint2(*(uint32_t*)&h01, *(uint32_t*)&h23);
    lo = make_uint2(*(uint32_t*)&l01, *(uint32_t*)&l23);
}
// fp32 float4 -> fp16 hi only
__device__ __forceinline__ uint2 cvt_h(float4 v) {
    __half2 h01 = __float22half2_rn(make_float2(v.x, v.y));
    __half2 h23 = __float22half2_rn(make_float2(v.z, v.w));
    return make_uint2(*(uint32_t*)&h01, *(uint32_t*)&h23);
}

// ---------------- epilogues ----------------
struct EpiStore {
    __device__ __forceinline__ float op(float v, int, int) const { return v; }
};
struct EpiResidual {
    const float* r; int ld;
    __device__ __forceinline__ float op(float v, int m, int n) const {
        return v + r[(size_t)m * ld + n];
    }
};
struct EpiGelu {
    __device__ __forceinline__ float op(float v, int, int) const {
        float x = 0.7978845608028654f * (v + 0.044715f * v * v * v);
        float t = 1.0f - 2.0f / (__expf(2.0f * x) + 1.0f);
        return 0.5f * v * (1.0f + t);
    }
};

// =====================================================================
// fp16 2-product split HMMA NT GEMM (unchanged from R12 win)
// =====================================================================
#define CH_  64
#define AST  136                              // A row: hi64|lo64|pad8
#define BST  72                               // B row: hi64|pad8
#define HMMA_SMEM_BYTES ((128*AST + 128*BST) * 2)   // 53248

template<typename Epi>
__global__ void __launch_bounds__(256, 2)
k_hmma_nt(const float* __restrict__ A, int lda, size_t aB,
          const float* __restrict__ B, int ldb, size_t bB,
          float* __restrict__ C, int ldc, size_t cB,
          int K, Epi epi, const int* __restrict__ cnt)
{
    if (cnt) {
        int lim = cnt[blockIdx.z];
        if (lim > CAP_) lim = CAP_;
        if ((int)(blockIdx.y * 128) >= lim) return;
    }

    extern __shared__ __half sm[];
    __half (*As)[AST] = (__half(*)[AST])sm;
    __half (*Bs)[BST] = (__half(*)[BST])(sm + 128 * AST);

    const int tid = threadIdx.x, lane = tid & 31, wid = tid >> 5;
    const int m0 = blockIdx.y * 128, n0 = blockIdx.x * 128;
    A += (size_t)blockIdx.z * aB;
    B += (size_t)blockIdx.z * bB;
    C += (size_t)blockIdx.z * cB;
    const int warpM = (wid >> 2) * 64, warpN = (wid & 3) * 32;

    float acc[4][4][4] = {};

    const uint32_t sA = smem_to_u32(As), sB = smem_to_u32(Bs);
    const int lrow = lane & 15, lsel = lane >> 4;

    for (int k0 = 0; k0 < K; k0 += CH_) {
        #pragma unroll
        for (int i = 0; i < 8; i++) {
            int f = tid + i * 256;
            int row = f >> 4, kq = f & 15;

            float4 va = *(const float4*)&A[(size_t)(m0 + row) * lda + k0 + kq * 4];
            uint2 hi, lo;
            cvt_split_h(va, hi, lo);
            *(uint2*)&As[row][kq * 4]      = hi;
            *(uint2*)&As[row][64 + kq * 4] = lo;

            float4 vb = *(const float4*)&B[(size_t)(n0 + row) * ldb + k0 + kq * 4];
            *(uint2*)&Bs[row][kq * 4] = cvt_h(vb);
        }
        __syncthreads();

        const int AO[8] = {0, 16, 32, 48, 64, 80, 96, 112};
        const int BO[8] = {0, 16, 32, 48, 0, 16, 32, 48};
        #pragma unroll
        for (int s = 0; s < 8; s++) {
            uint32_t af[4][4];
            #pragma unroll
            for (int mt = 0; mt < 4; mt++) {
                uint32_t addr = sA +
                    ((uint32_t)(warpM + mt * 16 + lrow) * AST + AO[s] + lsel * 8) * 2;
                ldsm_x4(af[mt][0], af[mt][1], af[mt][2], af[mt][3], addr);
            }
            uint32_t bf[4][2];
            #pragma unroll
            for (int pt = 0; pt < 2; pt++) {
                uint32_t r0, r1, r2, r3;
                uint32_t addr = sB +
                    ((uint32_t)(warpN + pt * 16 + lrow) * BST + BO[s] + lsel * 8) * 2;
                ldsm_x4(r0, r1, r2, r3, addr);
                bf[pt * 2][0] = r0;     bf[pt * 2][1] = r2;
                bf[pt * 2 + 1][0] = r1; bf[pt * 2 + 1][1] = r3;
            }
            #pragma unroll
            for (int mt = 0; mt < 4; mt++)
                #pragma unroll
                for (int nt = 0; nt < 4; nt++)
                    mma16816h(acc[mt][nt], af[mt][0], af[mt][1], af[mt][2], af[mt][3],
                              bf[nt][0], bf[nt][1]);
        }
        __syncthreads();
    }

    const int r = lane >> 2, cpair = (lane & 3) * 2;
    #pragma unroll
    for (int mt = 0; mt < 4; mt++) {
        int gm0 = m0 + warpM + mt * 16 + r;
        #pragma unroll
        for (int nt = 0; nt < 4; nt++) {
            int gn = n0 + warpN + nt * 8 + cpair;
            float2 v0 = make_float2(epi.op(acc[mt][nt][0], gm0, gn),
                                    epi.op(acc[mt][nt][1], gm0, gn + 1));
            *(float2*)&C[(size_t)gm0 * ldc + gn] = v0;
            float2 v1 = make_float2(epi.op(acc[mt][nt][2], gm0 + 8, gn),
                                    epi.op(acc[mt][nt][3], gm0 + 8, gn + 1));
            *(float2*)&C[(size_t)(gm0 + 8) * ldc + gn] = v1;
        }
    }
}

// =====================================================================
// Fused flash attention — fp16 2-product: S=(Qh+Ql)Kh, O+=(Ph+Pl)Vh.
// Q tile split fp16 (stride 136); K/V tiles fp16 hi-only (stride 72).
// MMAs/tile 192->128, K/V convert work halved, smem 69.6->53.2 KB.
// =====================================================================
#define FL_QROWS 128
#define FL_KT    64
#define FL_QST   136
#define FL_QRB   (FL_QST * 2)     // 272
#define FL_KST   72
#define FL_KRB   (FL_KST * 2)     // 144
#define FLASH_SMEM (FL_QROWS * FL_QRB + 2 * FL_KT * FL_KRB)   // 53248

__global__ void __launch_bounds__(256, 2)
k_flash(const float* __restrict__ qkv, float* __restrict__ attn)
{
    extern __shared__ char sm8[];
    const uint32_t sQ = smem_to_u32(sm8);
    const uint32_t sK = sQ + FL_QROWS * FL_QRB;
    const uint32_t sV = sK + FL_KT * FL_KRB;
    char* pQ = sm8;
    char* pK = sm8 + FL_QROWS * FL_QRB;
    char* pV = pK + FL_KT * FL_KRB;

    const int tid = threadIdx.x, lane = tid & 31, wid = tid >> 5;
    const int lrow = lane & 15, lsel = lane >> 4;
    const int bh = blockIdx.x;
    const int b = bh >> 4, hq = bh & 15, hk = hq >> 2;
    const int q0 = (int)(gridDim.y - 1 - blockIdx.y) * FL_QROWS;

    const int seqstride = B_ * QKV_OUT_;
    const float* Qg = qkv + (size_t)b * QKV_OUT_ + hq * HD_;
    const float* Kg = qkv + (size_t)b * QKV_OUT_ + NH_ * HD_ + hk * HD_;
    const float* Vg = qkv + (size_t)b * QKV_OUT_ + (NH_ + NKV_) * HD_ + hk * HD_;

    // ---- Q tile: split fp16 ----
    #pragma unroll
    for (int i = 0; i < 8; i++) {
        int f = tid + i * 256;
        int row = f >> 4, c4 = f & 15;
        float4 v = *(const float4*)&Qg[(size_t)(q0 + row) * seqstride + c4 * 4];
        uint2 hi, lo;
        cvt_split_h(v, hi, lo);
        char* pr = pQ + row * FL_QRB;
        *(uint2*)(pr + c4 * 8) = hi;
        *(uint2*)(pr + 128 + c4 * 8) = lo;
    }

    float accO[8][4] = {};
    float S[8][4];
    float m0 = -1e30f, m1 = -1e30f, l0 = 0.f, l1 = 0.f;

    const int rbase = q0 + wid * 16;
    const int q_hi = rbase + 15;
    const int jmax = (q0 >> 6) + 2;

    for (int j = 0; j < jmax; j++) {
        const int jbase = j * FL_KT;
        // ---- K/V tiles: fp16 hi-only ----
        #pragma unroll
        for (int i = 0; i < 4; i++) {
            int f = tid + i * 256;
            int row = f >> 4, c4 = f & 15;
            size_t go = (size_t)(jbase + row) * seqstride + c4 * 4;
            *(uint2*)(pK + row * FL_KRB + c4 * 8) = cvt_h(*(const float4*)&Kg[go]);
            *(uint2*)(pV + row * FL_KRB + c4 * 8) = cvt_h(*(const float4*)&Vg[go]);
        }
        __syncthreads();

        if (jbase <= q_hi) {
            #pragma unroll
            for (int t = 0; t < 8; t++) {
                S[t][0] = 0.f; S[t][1] = 0.f; S[t][2] = 0.f; S[t][3] = 0.f;
            }
            // ---- S = (Qh+Ql) Kh ----
            #pragma unroll
            for (int s = 0; s < 4; s++) {
                uint32_t qh[4], ql[4];
                uint32_t qaddr = sQ + (uint32_t)(wid * 16 + lrow) * FL_QRB +
                                 (s * 16 + lsel * 8) * 2;
                ldsm_x4(qh[0], qh[1], qh[2], qh[3], qaddr);
                ldsm_x4(ql[0], ql[1], ql[2], ql[3], qaddr + 128);
                #pragma unroll
                for (int g = 0; g < 4; g++) {
                    uint32_t r0, r1, r2, r3;
                    uint32_t kaddr = sK + (uint32_t)(g * 16 + lrow) * FL_KRB +
                                     (s * 16 + lsel * 8) * 2;
                    ldsm_x4(r0, r1, r2, r3, kaddr);
                    mma16816h(S[g * 2],     qh[0], qh[1], qh[2], qh[3], r0, r2);
                    mma16816h(S[g * 2],     ql[0], ql[1], ql[2], ql[3], r0, r2);
                    mma16816h(S[g * 2 + 1], qh[0], qh[1], qh[2], qh[3], r1, r3);
                    mma16816h(S[g * 2 + 1], ql[0], ql[1], ql[2], ql[3], r1, r3);
                }
            }

            const float scale = 0.125f;
            #pragma unroll
            for (int t = 0; t < 8; t++) {
                S[t][0] *= scale; S[t][1] *= scale;
                S[t][2] *= scale; S[t][3] *= scale;
            }
            if (jbase + 63 > rbase) {
                int r0g = rbase + (lane >> 2);
                int cg = jbase + (lane & 3) * 2;
                #pragma unroll
                for (int t = 0; t < 8; t++) {
                    int c0 = cg + t * 8;
                    if (c0 > r0g)     S[t][0] = -1e30f;
                    if (c0 + 1 > r0g) S[t][1] = -1e30f;
                    if (c0 > r0g + 8)     S[t][2] = -1e30f;
                    if (c0 + 1 > r0g + 8) S[t][3] = -1e30f;
                }
            }

            float tm0 = -1e30f, tm1 = -1e30f;
            #pragma unroll
            for (int t = 0; t < 8; t++) {
                tm0 = fmaxf(tm0, fmaxf(S[t][0], S[t][1]));
                tm1 = fmaxf(tm1, fmaxf(S[t][2], S[t][3]));
            }
            tm0 = fmaxf(tm0, __shfl_xor_sync(0xFFFFFFFFu, tm0, 1));
            tm0 = fmaxf(tm0, __shfl_xor_sync(0xFFFFFFFFu, tm0, 2));
            tm1 = fmaxf(tm1, __shfl_xor_sync(0xFFFFFFFFu, tm1, 1));
            tm1 = fmaxf(tm1, __shfl_xor_sync(0xFFFFFFFFu, tm1, 2));
            float mn0 = fmaxf(m0, tm0), mn1 = fmaxf(m1, tm1);
            float fac0 = __expf(m0 - mn0), fac1 = __expf(m1 - mn1);

            float ts0 = 0.f, ts1 = 0.f;
            #pragma unroll
            for (int t = 0; t < 8; t++) {
                S[t][0] = __expf(S[t][0] - mn0);
                S[t][1] = __expf(S[t][1] - mn0);
                S[t][2] = __expf(S[t][2] - mn1);
                S[t][3] = __expf(S[t][3] - mn1);
                ts0 += S[t][0] + S[t][1];
                ts1 += S[t][2] + S[t][3];
            }
            ts0 += __shfl_xor_sync(0xFFFFFFFFu, ts0, 1);
            ts0 += __shfl_xor_sync(0xFFFFFFFFu, ts0, 2);
            ts1 += __shfl_xor_sync(0xFFFFFFFFu, ts1, 1);
            ts1 += __shfl_xor_sync(0xFFFFFFFFu, ts1, 2);
            l0 = l0 * fac0 + ts0;
            l1 = l1 * fac1 + ts1;
            m0 = mn0; m1 = mn1;

            #pragma unroll
            for (int t = 0; t < 8; t++) {
                accO[t][0] *= fac0; accO[t][1] *= fac0;
                accO[t][2] *= fac1; accO[t][3] *= fac1;
            }

            // ---- O += (Ph+Pl) Vh ----
            #pragma unroll
            for (int s = 0; s < 4; s++) {
                uint32_t ah[4], al[4];
                ah[0] = pack_h2(S[2*s][0],   S[2*s][1]);
                ah[1] = pack_h2(S[2*s][2],   S[2*s][3]);
                ah[2] = pack_h2(S[2*s+1][0], S[2*s+1][1]);
                ah[3] = pack_h2(S[2*s+1][2], S[2*s+1][3]);
                #pragma unroll
                for (int i = 0; i < 4; i++) {
                    const float* sp = (i < 2) ? S[2*s] : S[2*s+1];
                    int o = (i & 1) * 2;
                    float2 f = __half22float2(*(__half2*)&ah[i]);
                    al[i] = pack_h2(sp[o] - f.x, sp[o + 1] - f.y);
                }
                #pragma unroll
                for (int dg = 0; dg < 4; dg++) {
                    uint32_t vrow = (uint32_t)(s * 16 + ((lane >> 3) & 1) * 8 + (lane & 7));
                    uint32_t vcol = (uint32_t)(dg * 16 + (lane >> 4) * 8);
                    uint32_t vaddr = sV + vrow * FL_KRB + vcol * 2;
                    uint32_t h0, h1, h2, h3;
                    ldsm_x4_t(h0, h1, h2, h3, vaddr);
                    mma16816h(accO[dg * 2],     ah[0], ah[1], ah[2], ah[3], h0, h1);
                    mma16816h(accO[dg * 2],     al[0], al[1], al[2], al[3], h0, h1);
                    mma16816h(accO[dg * 2 + 1], ah[0], ah[1], ah[2], ah[3], h2, h3);
                    mma16816h(accO[dg * 2 + 1], al[0], al[1], al[2], al[3], h2, h3);
                }
            }
        }
        __syncthreads();
    }

    float inv0 = 1.f / l0, inv1 = 1.f / l1;
    int r0g = rbase + (lane >> 2);
    float* Og = attn + (size_t)b * H_ + hq * HD_;
    const int ostride = B_ * H_;
    #pragma unroll
    for (int t = 0; t < 8; t++) {
        int gd = t * 8 + (lane & 3) * 2;
        *(float2*)&Og[(size_t)r0g * ostride + gd] =
            make_float2(accO[t][0] * inv0, accO[t][1] * inv0);
        *(float2*)&Og[(size_t)(r0g + 8) * ostride + gd] =
            make_float2(accO[t][2] * inv1, accO[t][3] * inv1);
    }
}

// ---------------- layernorm ----------------
__global__ void k_layernorm(const float* __restrict__ x, const float* __restrict__ w,
                            const float* __restrict__ b, float* __restrict__ y)
{
    int t = blockIdx.x;
    const float* xr = x + (size_t)t * H_;
    float* yr = y + (size_t)t * H_;
    float v[4], s = 0.f, s2 = 0.f;
    #pragma unroll
    for (int i = 0; i < 4; i++) {
        v[i] = xr[threadIdx.x + i * 256];
        s += v[i]; s2 += v[i] * v[i];
    }
    __shared__ float r1[256], r2[256];
    r1[threadIdx.x] = s; r2[threadIdx.x] = s2;
    __syncthreads();
    for (int o = 128; o; o >>= 1) {
        if (threadIdx.x < o) {
            r1[threadIdx.x] += r1[threadIdx.x + o];
            r2[threadIdx.x] += r2[threadIdx.x + o];
        }
        __syncthreads();
    }
    float mean = r1[0] * (1.0f / H_);
    float var  = r2[0] * (1.0f / H_) - mean * mean;
    float inv  = rsqrtf(var + 1e-5f);
    #pragma unroll
    for (int i = 0; i < 4; i++) {
        int h = threadIdx.x + i * 256;
        yr[h] = (v[i] - mean) * inv * w[h] + b[h];
    }
}

// ---------------- router ----------------
__global__ void k_router(const float* __restrict__ ln2, const float* __restrict__ Wr,
                         int* __restrict__ expidx, float* __restrict__ gate)
{
    int t = blockIdx.x;
    __shared__ float logits[E_];
    int w = threadIdx.x >> 5, lane = threadIdx.x & 31;
    const float* x = ln2 + (size_t)t * H_;
    const float* wr = Wr + (size_t)w * H_;
    float s = 0.f;
    for (int i = lane; i < H_; i += 32) s += x[i] * wr[i];
    #pragma unroll
    for (int o = 16; o; o >>= 1) s += __shfl_xor_sync(0xFFFFFFFFu, s, o);
    if (lane == 0) logits[w] = s;
    __syncthreads();
    if (threadIdx.x == 0) {
        float lmax = -1e30f;
        #pragma unroll
        for (int e = 0; e < E_; e++) lmax = fmaxf(lmax, logits[e]);
        float den = 0.f;
        #pragma unroll
        for (int e = 0; e < E_; e++) den += expf(logits[e] - lmax);
        int i1 = 0; float v1 = logits[0];
        #pragma unroll
        for (int e = 1; e < E_; e++) if (logits[e] > v1) { v1 = logits[e]; i1 = e; }
        int i2 = -1; float v2 = -1e30f;
        #pragma unroll
        for (int e = 0; e < E_; e++) if (e != i1 && logits[e] > v2) { v2 = logits[e]; i2 = e; }
        float inv = 1.0f / den;
        expidx[2 * t]     = i1;  gate[2 * t]     = expf(v1 - lmax) * inv;
        expidx[2 * t + 1] = i2;  gate[2 * t + 1] = expf(v2 - lmax) * inv;
    }
}

// ---------------- slot positions + per-expert counts (ballot scan) ----------
__global__ void k_pos(const int* __restrict__ expidx, int* __restrict__ pos,
                      int* __restrict__ cnt)
{
    __shared__ int sidx[NSLOT_];
    for (int i = threadIdx.x; i < NSLOT_; i += 512) sidx[i] = expidx[i];
    __syncthreads();
    int w = threadIdx.x >> 5, lane = threadIdx.x & 31;
    int c = 0;
    for (int base = 0; base < NSLOT_; base += 32) {
        bool f = (sidx[base + lane] == w);
        unsigned m = __ballot_sync(0xFFFFFFFFu, f);
        if (f) pos[base + lane] = c + __popc(m & ((1u << lane) - 1));
        c += __popc(m);
    }
    if (lane == 0) cnt[w] = (c < CAP_) ? c : CAP_;
}

// ---------------- dispatch kept slots into expert buffer ----------------
__global__ void k_dispatch(const float* __restrict__ ln2, const int* __restrict__ expidx,
                           const int* __restrict__ pos, float* __restrict__ buf)
{
    int slot = blockIdx.x;
    int p = pos[slot];
    if (p >= CAP_) return;
    int e = expidx[slot];
    int t = slot >> 1;
    const float* src = ln2 + (size_t)t * H_;
    float* dst = buf + ((size_t)e * CAP_ + p) * H_;
    for (int h = threadIdx.x; h < H_; h += 256) dst[h] = src[h];
}

// ---------------- combine: residual + gated expert outputs ----------------
__global__ void k_combine(const float* __restrict__ hattn, const float* __restrict__ h2,
                          const int* __restrict__ expidx, const int* __restrict__ pos,
                          const float* __restrict__ gate, float* __restrict__ out)
{
    int t = blockIdx.x;
    int s0 = 2 * t, s1 = 2 * t + 1;
    int p0 = pos[s0], p1 = pos[s1];
    int e0 = expidx[s0], e1 = expidx[s1];
    float g0 = (p0 < CAP_) ? gate[s0] : 0.f;
    float g1 = (p1 < CAP_) ? gate[s1] : 0.f;
    const float* r0 = (p0 < CAP_) ? h2 + ((size_t)e0 * CAP_ + p0) * H_ : nullptr;
    const float* r1 = (p1 < CAP_) ? h2 + ((size_t)e1 * CAP_ + p1) * H_ : nullptr;
    for (int h = threadIdx.x; h < H_; h += 256) {
        float v = hattn[(size_t)t * H_ + h];
        if (r0) v += r0[h] * g0;
        if (r1) v += r1[h] * g1;
        out[(size_t)t * H_ + h] = v;
    }
}

// ---------------- launch ----------------
extern "C" void kernel_launch(void* const* d_in, const int* in_sizes, int n_in,
                              void* d_out, int out_size)
{
    const float* hidden  = (const float*)d_in[0];
    const float* ln1w    = (const float*)d_in[1];
    const float* ln1b    = (const float*)d_in[2];
    const float* ln2w    = (const float*)d_in[3];
    const float* ln2b    = (const float*)d_in[4];
    const float* qkvw    = (const float*)d_in[5];
    const float* projw   = (const float*)d_in[6];
    const float* routerw = (const float*)d_in[7];
    const float* w1      = (const float*)d_in[8];
    const float* w2      = (const float*)d_in[9];
    float* out = (float*)d_out;

    float *ln1, *qkv, *attn, *hattn, *ln2, *gatep, *buf, *h1, *h2;
    int *expidx, *pos, *cnt;
    cudaGetSymbolAddress((void**)&ln1,    g_ln1);
    cudaGetSymbolAddress((void**)&qkv,    g_qkv);
    cudaGetSymbolAddress((void**)&attn,   g_attn);
    cudaGetSymbolAddress((void**)&hattn,  g_hattn);
    cudaGetSymbolAddress((void**)&ln2,    g_ln2);
    cudaGetSymbolAddress((void**)&expidx, g_expidx);
    cudaGetSymbolAddress((void**)&pos,    g_pos);
    cudaGetSymbolAddress((void**)&cnt,    g_cnt);
    cudaGetSymbolAddress((void**)&gatep,  g_gate);
    cudaGetSymbolAddress((void**)&buf,    g_buf);
    cudaGetSymbolAddress((void**)&h1,     g_h1);
    cudaGetSymbolAddress((void**)&h2,     g_h2);

    cudaFuncSetAttribute((void*)k_hmma_nt<EpiStore>,
                         cudaFuncAttributeMaxDynamicSharedMemorySize, HMMA_SMEM_BYTES);
    cudaFuncSetAttribute((void*)k_hmma_nt<EpiResidual>,
                         cudaFuncAttributeMaxDynamicSharedMemorySize, HMMA_SMEM_BYTES);
    cudaFuncSetAttribute((void*)k_hmma_nt<EpiGelu>,
                         cudaFuncAttributeMaxDynamicSharedMemorySize, HMMA_SMEM_BYTES);
    cudaFuncSetAttribute((void*)k_flash,
                         cudaFuncAttributeMaxDynamicSharedMemorySize, FLASH_SMEM);

    // LN1
    k_layernorm<<<T_, 256>>>(hidden, ln1w, ln1b, ln1);
    // QKV = ln1 @ W_qkv^T (HMMA fp16 2-product)
    k_hmma_nt<<<dim3(QKV_OUT_ / 128, T_ / 128, 1), 256, HMMA_SMEM_BYTES>>>(
        ln1, H_, (size_t)0, qkvw, H_, (size_t)0, qkv, QKV_OUT_, (size_t)0, H_,
        EpiStore{}, nullptr);
    // fused causal flash attention (HMMA fp16 2-product)
    k_flash<<<dim3(B_ * NH_, S_ / FL_QROWS), 256, FLASH_SMEM>>>(qkv, attn);
    // proj + residual (HMMA fp16 2-product)
    k_hmma_nt<<<dim3(H_ / 128, T_ / 128, 1), 256, HMMA_SMEM_BYTES>>>(
        attn, H_, (size_t)0, projw, H_, (size_t)0, hattn, H_, (size_t)0, H_,
        EpiResidual{hidden, H_}, nullptr);
    // LN2
    k_layernorm<<<T_, 256>>>(hattn, ln2w, ln2b, ln2);
    // router top-2
    k_router<<<T_, 512>>>(ln2, routerw, expidx, gatep);
    // slot positions + counts
    k_pos<<<1, 512>>>(expidx, pos, cnt);
    // dispatch (rows >= cnt[e] never read by combine; no zeroing needed)
    k_dispatch<<<NSLOT_, 256>>>(ln2, expidx, pos, buf);
    // expert FC1 (gelu) and FC2 (HMMA fp16 2-product, count-gated)
    k_hmma_nt<<<dim3(FFN_ / 128, CAP_ / 128, E_), 256, HMMA_SMEM_BYTES>>>(
        buf, H_, (size_t)CAP_ * H_, w1, H_, (size_t)FFN_ * H_,
        h1, FFN_, (size_t)CAP_ * FFN_, H_, EpiGelu{}, cnt);
    k_hmma_nt<<<dim3(H_ / 128, CAP_ / 128, E_), 256, HMMA_SMEM_BYTES>>>(
        h1, FFN_, (size_t)CAP_ * FFN_, w2, FFN_, (size_t)H_ * FFN_,
        h2, H_, (size_t)CAP_ * H_, FFN_, EpiStore{}, cnt);
    // combine + final residual
    k_combine<<<T_, 256>>>(hattn, h2, expidx, pos, gatep, out);
}

// round 14
// speedup vs baseline: 2.0799x; 1.1661x over previous
#include <cuda_runtime.h>
#include <cuda_bf16.h>
#include <cuda_fp16.h>
#include <math.h>
#include <stdint.h>

// ---------------- problem constants ----------------
#define S_   2048
#define B_   2
#define H_   1024
#define NH_  16
#define NKV_ 4
#define HD_  64
#define T_   4096            // S_*B_
#define QKV_OUT_ 1536
#define E_   16
#define TOPK_ 2
#define FFN_ 2048
#define CAP_ 640             // ceil(T*K/E*1.25)
#define NSLOT_ (T_*TOPK_)

// ---------------- scratch (device globals; no runtime allocation) ----------------
__device__ float g_ln1[(size_t)T_*H_];
__device__ float g_qkv[(size_t)T_*QKV_OUT_];
__device__ float g_attn[(size_t)T_*H_];
__device__ float g_hattn[(size_t)T_*H_];
__device__ float g_ln2[(size_t)T_*H_];
__device__ int   g_expidx[NSLOT_];
__device__ int   g_pos[NSLOT_];
__device__ int   g_cnt[E_];
__device__ float g_gate[NSLOT_];
__device__ float g_buf[(size_t)E_*CAP_*H_];
__device__ float g_h1[(size_t)E_*CAP_*FFN_];
__device__ float g_h2[(size_t)E_*CAP_*H_];

// =====================================================================
// PTX helpers (baseline sm_80+ ISA — tcgen05 unavailable on this
// build target, verified by R2 ptxas errors)
// =====================================================================
__device__ __forceinline__ uint32_t smem_to_u32(const void* smem_ptr) {
    uint32_t addr;
    asm("{ .reg .u64 tmp; cvta.to.shared.u64 tmp, %1; cvt.u32.u64 %0, tmp; }"
        : "=r"(addr) : "l"(smem_ptr));
    return addr;
}

__device__ __forceinline__ void ldsm_x4(uint32_t& r0, uint32_t& r1,
                                        uint32_t& r2, uint32_t& r3, uint32_t addr) {
    asm volatile("ldmatrix.sync.aligned.m8n8.x4.shared.b16 {%0,%1,%2,%3}, [%4];"
                 : "=r"(r0), "=r"(r1), "=r"(r2), "=r"(r3) : "r"(addr));
}
__device__ __forceinline__ void ldsm_x4_t(uint32_t& r0, uint32_t& r1,
                                          uint32_t& r2, uint32_t& r3, uint32_t addr) {
    asm volatile("ldmatrix.sync.aligned.m8n8.x4.trans.shared.b16 {%0,%1,%2,%3}, [%4];"
                 : "=r"(r0), "=r"(r1), "=r"(r2), "=r"(r3) : "r"(addr));
}

// fp16 MMA
__device__ __forceinline__ void mma16816h(float* c,
        uint32_t a0, uint32_t a1, uint32_t a2, uint32_t a3,
        uint32_t b0, uint32_t b1) {
    asm volatile(
        "mma.sync.aligned.m16n8k16.row.col.f32.f16.f16.f32 "
        "{%0,%1,%2,%3}, {%4,%5,%6,%7}, {%8,%9}, {%0,%1,%2,%3};"
        : "+f"(c[0]), "+f"(c[1]), "+f"(c[2]), "+f"(c[3])
        : "r"(a0), "r"(a1), "r"(a2), "r"(a3), "r"(b0), "r"(b1));
}

// fp32 pair -> packed fp16x2
__device__ __forceinline__ uint32_t pack_h2(float a, float b) {
    __half2 h = __float22half2_rn(make_float2(a, b));
    return *(uint32_t*)&h;
}
// fp32 float4 -> (hi, lo) split fp16 (flash Q path)
__device__ __forceinline__ void cvt_split_h(float4 v, uint2& hi, uint2& lo) {
    __half2 h01 = __float22half2_rn(make_float2(v.x, v.y));
    __half2 h23 = __float22half2_rn(make_float2(v.z, v.w));
    float2 f01 = __half22float2(h01), f23 = __half22float2(h23);
    __half2 l01 = __float22half2_rn(make_float2(v.x - f01.x, v.y - f01.y));
    __half2 l23 = __float22half2_rn(make_float2(v.z - f23.x, v.w - f23.y));
    hi = make_uint2(*(uint32_t*)&h01, *(uint32_t*)&h23);
    lo = make_uint2(*(uint32_t*)&l01, *(uint32_t*)&l23);
}
// fp32 float4 -> fp16
__device__ __forceinline__ uint2 cvt_h(float4 v) {
    __half2 h01 = __float22half2_rn(make_float2(v.x, v.y));
    __half2 h23 = __float22half2_rn(make_float2(v.z, v.w));
    return make_uint2(*(uint32_t*)&h01, *(uint32_t*)&h23);
}

// ---------------- epilogues ----------------
struct EpiStore {
    __device__ __forceinline__ float op(float v, int, int) const { return v; }
};
struct EpiResidual {
    const float* r; int ld;
    __device__ __forceinline__ float op(float v, int m, int n) const {
        return v + r[(size_t)m * ld + n];
    }
};
struct EpiGelu {
    __device__ __forceinline__ float op(float v, int, int) const {
        float x = 0.7978845608028654f * (v + 0.044715f * v * v * v);
        float t = 1.0f - 2.0f / (__expf(2.0f * x) + 1.0f);
        return 0.5f * v * (1.0f + t);
    }
};

// =====================================================================
// pure fp16 HMMA NT GEMM: C[M,N] = Ah[M,K] * Bh[N,K]^T (fp32 in/out)
// Both operands rounded to fp16 (error ~1.4x the 2-product variant,
// measured baseline 7.4e-5 -> expect ~1.5e-4, gate is 1e-3).
// 128x128 tile, 8 warps (64x32), K-chunk 64, 64 MMA/chunk.
// Optional per-z row-count gating (MoE early exit).
// =====================================================================
#define CH_  64
#define OST  72                               // row: 64 fp16 | pad8
#define HMMA_SMEM_BYTES (2 * 128 * OST * 2)   // 36864

template<typename Epi>
__global__ void __launch_bounds__(256, 2)
k_hmma_nt(const float* __restrict__ A, int lda, size_t aB,
          const float* __restrict__ B, int ldb, size_t bB,
          float* __restrict__ C, int ldc, size_t cB,
          int K, Epi epi, const int* __restrict__ cnt)
{
    if (cnt) {
        int lim = cnt[blockIdx.z];
        if (lim > CAP_) lim = CAP_;
        if ((int)(blockIdx.y * 128) >= lim) return;
    }

    extern __shared__ __half sm[];
    __half (*As)[OST] = (__half(*)[OST])sm;
    __half (*Bs)[OST] = (__half(*)[OST])(sm + 128 * OST);

    const int tid = threadIdx.x, lane = tid & 31, wid = tid >> 5;
    const int m0 = blockIdx.y * 128, n0 = blockIdx.x * 128;
    A += (size_t)blockIdx.z * aB;
    B += (size_t)blockIdx.z * bB;
    C += (size_t)blockIdx.z * cB;
    const int warpM = (wid >> 2) * 64, warpN = (wid & 3) * 32;

    float acc[4][4][4] = {};

    const uint32_t sA = smem_to_u32(As), sB = smem_to_u32(Bs);
    const int lrow = lane & 15, lsel = lane >> 4;

    for (int k0 = 0; k0 < K; k0 += CH_) {
        #pragma unroll
        for (int i = 0; i < 8; i++) {
            int f = tid + i * 256;
            int row = f >> 4, kq = f & 15;
            float4 va = *(const float4*)&A[(size_t)(m0 + row) * lda + k0 + kq * 4];
            *(uint2*)&As[row][kq * 4] = cvt_h(va);
            float4 vb = *(const float4*)&B[(size_t)(n0 + row) * ldb + k0 + kq * 4];
            *(uint2*)&Bs[row][kq * 4] = cvt_h(vb);
        }
        __syncthreads();

        #pragma unroll
        for (int s = 0; s < 4; s++) {
            const int ko = s * 16;
            uint32_t af[4][4];
            #pragma unroll
            for (int mt = 0; mt < 4; mt++) {
                uint32_t addr = sA +
                    ((uint32_t)(warpM + mt * 16 + lrow) * OST + ko + lsel * 8) * 2;
                ldsm_x4(af[mt][0], af[mt][1], af[mt][2], af[mt][3], addr);
            }
            uint32_t bf[4][2];
            #pragma unroll
            for (int pt = 0; pt < 2; pt++) {
                uint32_t r0, r1, r2, r3;
                uint32_t addr = sB +
                    ((uint32_t)(warpN + pt * 16 + lrow) * OST + ko + lsel * 8) * 2;
                ldsm_x4(r0, r1, r2, r3, addr);
                bf[pt * 2][0] = r0;     bf[pt * 2][1] = r2;
                bf[pt * 2 + 1][0] = r1; bf[pt * 2 + 1][1] = r3;
            }
            #pragma unroll
            for (int mt = 0; mt < 4; mt++)
                #pragma unroll
                for (int nt = 0; nt < 4; nt++)
                    mma16816h(acc[mt][nt], af[mt][0], af[mt][1], af[mt][2], af[mt][3],
                              bf[nt][0], bf[nt][1]);
        }
        __syncthreads();
    }

    const int r = lane >> 2, cpair = (lane & 3) * 2;
    #pragma unroll
    for (int mt = 0; mt < 4; mt++) {
        int gm0 = m0 + warpM + mt * 16 + r;
        #pragma unroll
        for (int nt = 0; nt < 4; nt++) {
            int gn = n0 + warpN + nt * 8 + cpair;
            float2 v0 = make_float2(epi.op(acc[mt][nt][0], gm0, gn),
                                    epi.op(acc[mt][nt][1], gm0, gn + 1));
            *(float2*)&C[(size_t)gm0 * ldc + gn] = v0;
            float2 v1 = make_float2(epi.op(acc[mt][nt][2], gm0 + 8, gn),
                                    epi.op(acc[mt][nt][3], gm0 + 8, gn + 1));
            *(float2*)&C[(size_t)(gm0 + 8) * ldc + gn] = v1;
        }
    }
}

// =====================================================================
// Fused flash attention — fp16 2-product (unchanged from R13 win):
// S=(Qh+Ql)Kh, O+=(Ph+Pl)Vh.
// =====================================================================
#define FL_QROWS 128
#define FL_KT    64
#define FL_QST   136
#define FL_QRB   (FL_QST * 2)     // 272
#define FL_KST   72
#define FL_KRB   (FL_KST * 2)     // 144
#define FLASH_SMEM (FL_QROWS * FL_QRB + 2 * FL_KT * FL_KRB)   // 53248

__global__ void __launch_bounds__(256, 2)
k_flash(const float* __restrict__ qkv, float* __restrict__ attn)
{
    extern __shared__ char sm8[];
    const uint32_t sQ = smem_to_u32(sm8);
    const uint32_t sK = sQ + FL_QROWS * FL_QRB;
    const uint32_t sV = sK + FL_KT * FL_KRB;
    char* pQ = sm8;
    char* pK = sm8 + FL_QROWS * FL_QRB;
    char* pV = pK + FL_KT * FL_KRB;

    const int tid = threadIdx.x, lane = tid & 31, wid = tid >> 5;
    const int lrow = lane & 15, lsel = lane >> 4;
    const int bh = blockIdx.x;
    const int b = bh >> 4, hq = bh & 15, hk = hq >> 2;
    const int q0 = (int)(gridDim.y - 1 - blockIdx.y) * FL_QROWS;

    const int seqstride = B_ * QKV_OUT_;
    const float* Qg = qkv + (size_t)b * QKV_OUT_ + hq * HD_;
    const float* Kg = qkv + (size_t)b * QKV_OUT_ + NH_ * HD_ + hk * HD_;
    const float* Vg = qkv + (size_t)b * QKV_OUT_ + (NH_ + NKV_) * HD_ + hk * HD_;

    #pragma unroll
    for (int i = 0; i < 8; i++) {
        int f = tid + i * 256;
        int row = f >> 4, c4 = f & 15;
        float4 v = *(const float4*)&Qg[(size_t)(q0 + row) * seqstride + c4 * 4];
        uint2 hi, lo;
        cvt_split_h(v, hi, lo);
        char* pr = pQ + row * FL_QRB;
        *(uint2*)(pr + c4 * 8) = hi;
        *(uint2*)(pr + 128 + c4 * 8) = lo;
    }

    float accO[8][4] = {};
    float S[8][4];
    float m0 = -1e30f, m1 = -1e30f, l0 = 0.f, l1 = 0.f;

    const int rbase = q0 + wid * 16;
    const int q_hi = rbase + 15;
    const int jmax = (q0 >> 6) + 2;

    for (int j = 0; j < jmax; j++) {
        const int jbase = j * FL_KT;
        #pragma unroll
        for (int i = 0; i < 4; i++) {
            int f = tid + i * 256;
            int row = f >> 4, c4 = f & 15;
            size_t go = (size_t)(jbase + row) * seqstride + c4 * 4;
            *(uint2*)(pK + row * FL_KRB + c4 * 8) = cvt_h(*(const float4*)&Kg[go]);
            *(uint2*)(pV + row * FL_KRB + c4 * 8) = cvt_h(*(const float4*)&Vg[go]);
        }
        __syncthreads();

        if (jbase <= q_hi) {
            #pragma unroll
            for (int t = 0; t < 8; t++) {
                S[t][0] = 0.f; S[t][1] = 0.f; S[t][2] = 0.f; S[t][3] = 0.f;
            }
            #pragma unroll
            for (int s = 0; s < 4; s++) {
                uint32_t qh[4], ql[4];
                uint32_t qaddr = sQ + (uint32_t)(wid * 16 + lrow) * FL_QRB +
                                 (s * 16 + lsel * 8) * 2;
                ldsm_x4(qh[0], qh[1], qh[2], qh[3], qaddr);
                ldsm_x4(ql[0], ql[1], ql[2], ql[3], qaddr + 128);
                #pragma unroll
                for (int g = 0; g < 4; g++) {
                    uint32_t r0, r1, r2, r3;
                    uint32_t kaddr = sK + (uint32_t)(g * 16 + lrow) * FL_KRB +
                                     (s * 16 + lsel * 8) * 2;
                    ldsm_x4(r0, r1, r2, r3, kaddr);
                    mma16816h(S[g * 2],     qh[0], qh[1], qh[2], qh[3], r0, r2);
                    mma16816h(S[g * 2],     ql[0], ql[1], ql[2], ql[3], r0, r2);
                    mma16816h(S[g * 2 + 1], qh[0], qh[1], qh[2], qh[3], r1, r3);
                    mma16816h(S[g * 2 + 1], ql[0], ql[1], ql[2], ql[3], r1, r3);
                }
            }

            const float scale = 0.125f;
            #pragma unroll
            for (int t = 0; t < 8; t++) {
                S[t][0] *= scale; S[t][1] *= scale;
                S[t][2] *= scale; S[t][3] *= scale;
            }
            if (jbase + 63 > rbase) {
                int r0g = rbase + (lane >> 2);
                int cg = jbase + (lane & 3) * 2;
                #pragma unroll
                for (int t = 0; t < 8; t++) {
                    int c0 = cg + t * 8;
                    if (c0 > r0g)     S[t][0] = -1e30f;
                    if (c0 + 1 > r0g) S[t][1] = -1e30f;
                    if (c0 > r0g + 8)     S[t][2] = -1e30f;
                    if (c0 + 1 > r0g + 8) S[t][3] = -1e30f;
                }
            }

            float tm0 = -1e30f, tm1 = -1e30f;
            #pragma unroll
            for (int t = 0; t < 8; t++) {
                tm0 = fmaxf(tm0, fmaxf(S[t][0], S[t][1]));
                tm1 = fmaxf(tm1, fmaxf(S[t][2], S[t][3]));
            }
            tm0 = fmaxf(tm0, __shfl_xor_sync(0xFFFFFFFFu, tm0, 1));
            tm0 = fmaxf(tm0, __shfl_xor_sync(0xFFFFFFFFu, tm0, 2));
            tm1 = fmaxf(tm1, __shfl_xor_sync(0xFFFFFFFFu, tm1, 1));
            tm1 = fmaxf(tm1, __shfl_xor_sync(0xFFFFFFFFu, tm1, 2));
            float mn0 = fmaxf(m0, tm0), mn1 = fmaxf(m1, tm1);
            float fac0 = __expf(m0 - mn0), fac1 = __expf(m1 - mn1);

            float ts0 = 0.f, ts1 = 0.f;
            #pragma unroll
            for (int t = 0; t < 8; t++) {
                S[t][0] = __expf(S[t][0] - mn0);
                S[t][1] = __expf(S[t][1] - mn0);
                S[t][2] = __expf(S[t][2] - mn1);
                S[t][3] = __expf(S[t][3] - mn1);
                ts0 += S[t][0] + S[t][1];
                ts1 += S[t][2] + S[t][3];
            }
            ts0 += __shfl_xor_sync(0xFFFFFFFFu, ts0, 1);
            ts0 += __shfl_xor_sync(0xFFFFFFFFu, ts0, 2);
            ts1 += __shfl_xor_sync(0xFFFFFFFFu, ts1, 1);
            ts1 += __shfl_xor_sync(0xFFFFFFFFu, ts1, 2);
            l0 = l0 * fac0 + ts0;
            l1 = l1 * fac1 + ts1;
            m0 = mn0; m1 = mn1;

            #pragma unroll
            for (int t = 0; t < 8; t++) {
                accO[t][0] *= fac0; accO[t][1] *= fac0;
                accO[t][2] *= fac1; accO[t][3] *= fac1;
            }

            #pragma unroll
            for (int s = 0; s < 4; s++) {
                uint32_t ah[4], al[4];
                ah[0] = pack_h2(S[2*s][0],   S[2*s][1]);
                ah[1] = pack_h2(S[2*s][2],   S[2*s][3]);
                ah[2] = pack_h2(S[2*s+1][0], S[2*s+1][1]);
                ah[3] = pack_h2(S[2*s+1][2], S[2*s+1][3]);
                #pragma unroll
                for (int i = 0; i < 4; i++) {
                    const float* sp = (i < 2) ? S[2*s] : S[2*s+1];
                    int o = (i & 1) * 2;
                    float2 f = __half22float2(*(__half2*)&ah[i]);
                    al[i] = pack_h2(sp[o] - f.x, sp[o + 1] - f.y);
                }
                #pragma unroll
                for (int dg = 0; dg < 4; dg++) {
                    uint32_t vrow = (uint32_t)(s * 16 + ((lane >> 3) & 1) * 8 + (lane & 7));
                    uint32_t vcol = (uint32_t)(dg * 16 + (lane >> 4) * 8);
                    uint32_t vaddr = sV + vrow * FL_KRB + vcol * 2;
                    uint32_t h0, h1, h2, h3;
                    ldsm_x4_t(h0, h1, h2, h3, vaddr);
                    mma16816h(accO[dg * 2],     ah[0], ah[1], ah[2], ah[3], h0, h1);
                    mma16816h(accO[dg * 2],     al[0], al[1], al[2], al[3], h0, h1);
                    mma16816h(accO[dg * 2 + 1], ah[0], ah[1], ah[2], ah[3], h2, h3);
                    mma16816h(accO[dg * 2 + 1], al[0], al[1], al[2], al[3], h2, h3);
                }
            }
        }
        __syncthreads();
    }

    float inv0 = 1.f / l0, inv1 = 1.f / l1;
    int r0g = rbase + (lane >> 2);
    float* Og = attn + (size_t)b * H_ + hq * HD_;
    const int ostride = B_ * H_;
    #pragma unroll
    for (int t = 0; t < 8; t++) {
        int gd = t * 8 + (lane & 3) * 2;
        *(float2*)&Og[(size_t)r0g * ostride + gd] =
            make_float2(accO[t][0] * inv0, accO[t][1] * inv0);
        *(float2*)&Og[(size_t)(r0g + 8) * ostride + gd] =
            make_float2(accO[t][2] * inv1, accO[t][3] * inv1);
    }
}

// ---------------- layernorm ----------------
__global__ void k_layernorm(const float* __restrict__ x, const float* __restrict__ w,
                            const float* __restrict__ b, float* __restrict__ y)
{
    int t = blockIdx.x;
    const float* xr = x + (size_t)t * H_;
    float* yr = y + (size_t)t * H_;
    float v[4], s = 0.f, s2 = 0.f;
    #pragma unroll
    for (int i = 0; i < 4; i++) {
        v[i] = xr[threadIdx.x + i * 256];
        s += v[i]; s2 += v[i] * v[i];
    }
    __shared__ float r1[256], r2[256];
    r1[threadIdx.x] = s; r2[threadIdx.x] = s2;
    __syncthreads();
    for (int o = 128; o; o >>= 1) {
        if (threadIdx.x < o) {
            r1[threadIdx.x] += r1[threadIdx.x + o];
            r2[threadIdx.x] += r2[threadIdx.x + o];
        }
        __syncthreads();
    }
    float mean = r1[0] * (1.0f / H_);
    float var  = r2[0] * (1.0f / H_) - mean * mean;
    float inv  = rsqrtf(var + 1e-5f);
    #pragma unroll
    for (int i = 0; i < 4; i++) {
        int h = threadIdx.x + i * 256;
        yr[h] = (v[i] - mean) * inv * w[h] + b[h];
    }
}

// ---------------- router ----------------
__global__ void k_router(const float* __restrict__ ln2, const float* __restrict__ Wr,
                         int* __restrict__ expidx, float* __restrict__ gate)
{
    int t = blockIdx.x;
    __shared__ float logits[E_];
    int w = threadIdx.x >> 5, lane = threadIdx.x & 31;
    const float* x = ln2 + (size_t)t * H_;
    const float* wr = Wr + (size_t)w * H_;
    float s = 0.f;
    for (int i = lane; i < H_; i += 32) s += x[i] * wr[i];
    #pragma unroll
    for (int o = 16; o; o >>= 1) s += __shfl_xor_sync(0xFFFFFFFFu, s, o);
    if (lane == 0) logits[w] = s;
    __syncthreads();
    if (threadIdx.x == 0) {
        float lmax = -1e30f;
        #pragma unroll
        for (int e = 0; e < E_; e++) lmax = fmaxf(lmax, logits[e]);
        float den = 0.f;
        #pragma unroll
        for (int e = 0; e < E_; e++) den += expf(logits[e] - lmax);
        int i1 = 0; float v1 = logits[0];
        #pragma unroll
        for (int e = 1; e < E_; e++) if (logits[e] > v1) { v1 = logits[e]; i1 = e; }
        int i2 = -1; float v2 = -1e30f;
        #pragma unroll
        for (int e = 0; e < E_; e++) if (e != i1 && logits[e] > v2) { v2 = logits[e]; i2 = e; }
        float inv = 1.0f / den;
        expidx[2 * t]     = i1;  gate[2 * t]     = expf(v1 - lmax) * inv;
        expidx[2 * t + 1] = i2;  gate[2 * t + 1] = expf(v2 - lmax) * inv;
    }
}

// ---------------- slot positions + per-expert counts (ballot scan) ----------
__global__ void k_pos(const int* __restrict__ expidx, int* __restrict__ pos,
                      int* __restrict__ cnt)
{
    __shared__ int sidx[NSLOT_];
    for (int i = threadIdx.x; i < NSLOT_; i += 512) sidx[i] = expidx[i];
    __syncthreads();
    int w = threadIdx.x >> 5, lane = threadIdx.x & 31;
    int c = 0;
    for (int base = 0; base < NSLOT_; base += 32) {
        bool f = (sidx[base + lane] == w);
        unsigned m = __ballot_sync(0xFFFFFFFFu, f);
        if (f) pos[base + lane] = c + __popc(m & ((1u << lane) - 1));
        c += __popc(m);
    }
    if (lane == 0) cnt[w] = (c < CAP_) ? c : CAP_;
}

// ---------------- dispatch kept slots into expert buffer ----------------
__global__ void k_dispatch(const float* __restrict__ ln2, const int* __restrict__ expidx,
                           const int* __restrict__ pos, float* __restrict__ buf)
{
    int slot = blockIdx.x;
    int p = pos[slot];
    if (p >= CAP_) return;
    int e = expidx[slot];
    int t = slot >> 1;
    const float* src = ln2 + (size_t)t * H_;
    float* dst = buf + ((size_t)e * CAP_ + p) * H_;
    for (int h = threadIdx.x; h < H_; h += 256) dst[h] = src[h];
}

// ---------------- combine: residual + gated expert outputs ----------------
__global__ void k_combine(const float* __restrict__ hattn, const float* __restrict__ h2,
                          const int* __restrict__ expidx, const int* __restrict__ pos,
                          const float* __restrict__ gate, float* __restrict__ out)
{
    int t = blockIdx.x;
    int s0 = 2 * t, s1 = 2 * t + 1;
    int p0 = pos[s0], p1 = pos[s1];
    int e0 = expidx[s0], e1 = expidx[s1];
    float g0 = (p0 < CAP_) ? gate[s0] : 0.f;
    float g1 = (p1 < CAP_) ? gate[s1] : 0.f;
    const float* r0 = (p0 < CAP_) ? h2 + ((size_t)e0 * CAP_ + p0) * H_ : nullptr;
    const float* r1 = (p1 < CAP_) ? h2 + ((size_t)e1 * CAP_ + p1) * H_ : nullptr;
    for (int h = threadIdx.x; h < H_; h += 256) {
        float v = hattn[(size_t)t * H_ + h];
        if (r0) v += r0[h] * g0;
        if (r1) v += r1[h] * g1;
        out[(size_t)t * H_ + h] = v;
    }
}

// ---------------- launch ----------------
extern "C" void kernel_launch(void* const* d_in, const int* in_sizes, int n_in,
                              void* d_out, int out_size)
{
    const float* hidden  = (const float*)d_in[0];
    const float* ln1w    = (const float*)d_in[1];
    const float* ln1b    = (const float*)d_in[2];
    const float* ln2w    = (const float*)d_in[3];
    const float* ln2b    = (const float*)d_in[4];
    const float* qkvw    = (const float*)d_in[5];
    const float* projw   = (const float*)d_in[6];
    const float* routerw = (const float*)d_in[7];
    const float* w1      = (const float*)d_in[8];
    const float* w2      = (const float*)d_in[9];
    float* out = (float*)d_out;

    float *ln1, *qkv, *attn, *hattn, *ln2, *gatep, *buf, *h1, *h2;
    int *expidx, *pos, *cnt;
    cudaGetSymbolAddress((void**)&ln1,    g_ln1);
    cudaGetSymbolAddress((void**)&qkv,    g_qkv);
    cudaGetSymbolAddress((void**)&attn,   g_attn);
    cudaGetSymbolAddress((void**)&hattn,  g_hattn);
    cudaGetSymbolAddress((void**)&ln2,    g_ln2);
    cudaGetSymbolAddress((void**)&expidx, g_expidx);
    cudaGetSymbolAddress((void**)&pos,    g_pos);
    cudaGetSymbolAddress((void**)&cnt,    g_cnt);
    cudaGetSymbolAddress((void**)&gatep,  g_gate);
    cudaGetSymbolAddress((void**)&buf,    g_buf);
    cudaGetSymbolAddress((void**)&h1,     g_h1);
    cudaGetSymbolAddress((void**)&h2,     g_h2);

    cudaFuncSetAttribute((void*)k_hmma_nt<EpiStore>,
                         cudaFuncAttributeMaxDynamicSharedMemorySize, HMMA_SMEM_BYTES);
    cudaFuncSetAttribute((void*)k_hmma_nt<EpiResidual>,
                         cudaFuncAttributeMaxDynamicSharedMemorySize, HMMA_SMEM_BYTES);
    cudaFuncSetAttribute((void*)k_hmma_nt<EpiGelu>,
                         cudaFuncAttributeMaxDynamicSharedMemorySize, HMMA_SMEM_BYTES);
    cudaFuncSetAttribute((void*)k_flash,
                         cudaFuncAttributeMaxDynamicSharedMemorySize, FLASH_SMEM);

    // LN1
    k_layernorm<<<T_, 256>>>(hidden, ln1w, ln1b, ln1);
    // QKV = ln1 @ W_qkv^T (HMMA fp16)
    k_hmma_nt<<<dim3(QKV_OUT_ / 128, T_ / 128, 1), 256, HMMA_SMEM_BYTES>>>(
        ln1, H_, (size_t)0, qkvw, H_, (size_t)0, qkv, QKV_OUT_, (size_t)0, H_,
        EpiStore{}, nullptr);
    // fused causal flash attention (HMMA fp16 2-product)
    k_flash<<<dim3(B_ * NH_, S_ / FL_QROWS), 256, FLASH_SMEM>>>(qkv, attn);
    // proj + residual (HMMA fp16)
    k_hmma_nt<<<dim3(H_ / 128, T_ / 128, 1), 256, HMMA_SMEM_BYTES>>>(
        attn, H_, (size_t)0, projw, H_, (size_t)0, hattn, H_, (size_t)0, H_,
        EpiResidual{hidden, H_}, nullptr);
    // LN2
    k_layernorm<<<T_, 256>>>(hattn, ln2w, ln2b, ln2);
    // router top-2
    k_router<<<T_, 512>>>(ln2, routerw, expidx, gatep);
    // slot positions + counts
    k_pos<<<1, 512>>>(expidx, pos, cnt);
    // dispatch (rows >= cnt[e] never read by combine; no zeroing needed)
    k_dispatch<<<NSLOT_, 256>>>(ln2, expidx, pos, buf);
    // expert FC1 (gelu) and FC2 (HMMA fp16, count-gated)
    k_hmma_nt<<<dim3(FFN_ / 128, CAP_ / 128, E_), 256, HMMA_SMEM_BYTES>>>(
        buf, H_, (size_t)CAP_ * H_, w1, H_, (size_t)FFN_ * H_,
        h1, FFN_, (size_t)CAP_ * FFN_, H_, EpiGelu{}, cnt);
    k_hmma_nt<<<dim3(H_ / 128, CAP_ / 128, E_), 256, HMMA_SMEM_BYTES>>>(
        h1, FFN_, (size_t)CAP_ * FFN_, w2, FFN_, (size_t)H_ * FFN_,
        h2, H_, (size_t)CAP_ * H_, FFN_, EpiStore{}, cnt);
    // combine + final residual
    k_combine<<<T_, 256>>>(hattn, h2, expidx, pos, gatep, out);
}

// round 15
// speedup vs baseline: 2.2208x; 1.0678x over previous
#include <cuda_runtime.h>
#include <cuda_fp16.h>
#include <math.h>
#include <stdint.h>

// ---------------- problem constants ----------------
#define S_   2048
#define B_   2
#define H_   1024
#define NH_  16
#define NKV_ 4
#define HD_  64
#define T_   4096            // S_*B_
#define QKV_OUT_ 1536
#define E_   16
#define TOPK_ 2
#define FFN_ 2048
#define CAP_ 640             // ceil(T*K/E*1.25)
#define NSLOT_ (T_*TOPK_)

// ---------------- scratch (device globals; no runtime allocation) ----------------
__device__ __align__(16) __half g_ln1[(size_t)T_*H_];
__device__ __align__(16) float  g_qkv[(size_t)T_*QKV_OUT_];
__device__ __align__(16) __half g_attn[(size_t)T_*H_];
__device__ __align__(16) float  g_hattn[(size_t)T_*H_];
__device__ __align__(16) float  g_ln2[(size_t)T_*H_];
__device__ int   g_expidx[NSLOT_];
__device__ int   g_pos[NSLOT_];
__device__ int   g_cnt[E_];
__device__ float g_gate[NSLOT_];
__device__ __align__(16) __half g_buf[(size_t)E_*CAP_*H_];
__device__ __align__(16) __half g_h1[(size_t)E_*CAP_*FFN_];
__device__ __align__(16) float  g_h2[(size_t)E_*CAP_*H_];
// fp16 weights (converted once per call)
__device__ __align__(16) __half g_qkvw16[(size_t)QKV_OUT_*H_];
__device__ __align__(16) __half g_projw16[(size_t)H_*H_];
__device__ __align__(16) __half g_w116[(size_t)E_*FFN_*H_];
__device__ __align__(16) __half g_w216[(size_t)E_*H_*FFN_];

// =====================================================================
// PTX helpers (baseline sm_80+ ISA — tcgen05 unavailable on this target)
// =====================================================================
__device__ __forceinline__ uint32_t smem_to_u32(const void* smem_ptr) {
    uint32_t addr;
    asm("{ .reg .u64 tmp; cvta.to.shared.u64 tmp, %1; cvt.u32.u64 %0, tmp; }"
        : "=r"(addr) : "l"(smem_ptr));
    return addr;
}

#define CP_ASYNC16(dst_u32, src_ptr) \
    asm volatile("cp.async.cg.shared.global [%0], [%1], 16;" \
        :: "r"(dst_u32), "l"(src_ptr))
#define CP_COMMIT() asm volatile("cp.async.commit_group;" ::: "memory")
#define CP_WAIT(n)  asm volatile("cp.async.wait_group %0;" :: "n"(n) : "memory")

__device__ __forceinline__ void ldsm_x4(uint32_t& r0, uint32_t& r1,
                                        uint32_t& r2, uint32_t& r3, uint32_t addr) {
    asm volatile("ldmatrix.sync.aligned.m8n8.x4.shared.b16 {%0,%1,%2,%3}, [%4];"
                 : "=r"(r0), "=r"(r1), "=r"(r2), "=r"(r3) : "r"(addr));
}
__device__ __forceinline__ void ldsm_x4_t(uint32_t& r0, uint32_t& r1,
                                          uint32_t& r2, uint32_t& r3, uint32_t addr) {
    asm volatile("ldmatrix.sync.aligned.m8n8.x4.trans.shared.b16 {%0,%1,%2,%3}, [%4];"
                 : "=r"(r0), "=r"(r1), "=r"(r2), "=r"(r3) : "r"(addr));
}

__device__ __forceinline__ void mma16816h(float* c,
        uint32_t a0, uint32_t a1, uint32_t a2, uint32_t a3,
        uint32_t b0, uint32_t b1) {
    asm volatile(
        "mma.sync.aligned.m16n8k16.row.col.f32.f16.f16.f32 "
        "{%0,%1,%2,%3}, {%4,%5,%6,%7}, {%8,%9}, {%0,%1,%2,%3};"
        : "+f"(c[0]), "+f"(c[1]), "+f"(c[2]), "+f"(c[3])
        : "r"(a0), "r"(a1), "r"(a2), "r"(a3), "r"(b0), "r"(b1));
}

__device__ __forceinline__ uint32_t pack_h2(float a, float b) {
    __half2 h = __float22half2_rn(make_float2(a, b));
    return *(uint32_t*)&h;
}
__device__ __forceinline__ void cvt_split_h(float4 v, uint2& hi, uint2& lo) {
    __half2 h01 = __float22half2_rn(make_float2(v.x, v.y));
    __half2 h23 = __float22half2_rn(make_float2(v.z, v.w));
    float2 f01 = __half22float2(h01), f23 = __half22float2(h23);
    __half2 l01 = __float22half2_rn(make_float2(v.x - f01.x, v.y - f01.y));
    __half2 l23 = __float22half2_rn(make_float2(v.z - f23.x, v.w - f23.y));
    hi = make_uint2(*(uint32_t*)&h01, *(uint32_t*)&h23);
    lo = make_uint2(*(uint32_t*)&l01, *(uint32_t*)&l23);
}
__device__ __forceinline__ uint2 cvt_h(float4 v) {
    __half2 h01 = __float22half2_rn(make_float2(v.x, v.y));
    __half2 h23 = __float22half2_rn(make_float2(v.z, v.w));
    return make_uint2(*(uint32_t*)&h01, *(uint32_t*)&h23);
}
__device__ __forceinline__ float gelu_tanh(float v) {
    float x = 0.7978845608028654f * (v + 0.044715f * v * v * v);
    float t = 1.0f - 2.0f / (__expf(2.0f * x) + 1.0f);
    return 0.5f * v * (1.0f + t);
}

// ---------------- GEMM output functors ----------------
struct OutF32 {
    float* C; int ldc; size_t cB;
    __device__ __forceinline__ void setz(int z) { C += (size_t)z * cB; }
    __device__ __forceinline__ void store2(int m, int n, float a, float b) {
        *(float2*)&C[(size_t)m * ldc + n] = make_float2(a, b);
    }
};
struct OutResid {
    float* C; const float* R; int ldc;
    __device__ __forceinline__ void setz(int) {}
    __device__ __forceinline__ void store2(int m, int n, float a, float b) {
        float2 r = *(const float2*)&R[(size_t)m * ldc + n];
        *(float2*)&C[(size_t)m * ldc + n] = make_float2(a + r.x, b + r.y);
    }
};
struct OutGeluH {
    __half* C; int ldc; size_t cB;
    __device__ __forceinline__ void setz(int z) { C += (size_t)z * cB; }
    __device__ __forceinline__ void store2(int m, int n, float a, float b) {
        *(uint32_t*)&C[(size_t)m * ldc + n] = pack_h2(gelu_tanh(a), gelu_tanh(b));
    }
};

// =====================================================================
// fp16 HMMA NT GEMM, fp16 operands in GLOBAL (preconverted by producers),
// 3-stage cp.async pipeline, ONE barrier per 64-K chunk, no conversions.
// C[M,N] (128x128/CTA) = A[M,K] * B[N,K]^T. 64 MMA/chunk.
// Optional per-z row-count gating (MoE early exit).
// =====================================================================
#define OST 72                          // smem row stride (halves): 64 data | 8 pad
#define GST_B (128 * OST * 2)           // bytes per operand per stage (18432)
#define GSTAGE (2 * GST_B)              // 36864
#define GNSTG 3
#define GEMM_SMEM (GNSTG * GSTAGE)      // 110592

template<typename Out>
__global__ void __launch_bounds__(256, 2)
k_gemm_h(const __half* __restrict__ A, int lda, size_t aB,
         const __half* __restrict__ B, int ldb, size_t bB,
         int K, Out out, const int* __restrict__ cnt)
{
    if (cnt) {
        int lim = cnt[blockIdx.z];
        if (lim > CAP_) lim = CAP_;
        if ((int)(blockIdx.y * 128) >= lim) return;
    }

    extern __shared__ __half sm[];
    const int tid = threadIdx.x, lane = tid & 31, wid = tid >> 5;
    const int m0 = blockIdx.y * 128, n0 = blockIdx.x * 128;
    const int z = blockIdx.z;
    A += (size_t)z * aB;
    B += (size_t)z * bB;
    out.setz(z);
    const int warpM = (wid >> 2) * 64, warpN = (wid & 3) * 32;
    const int lrow = lane & 15, lsel = lane >> 4;

    // load mapping: 2 threads per row, each owns 32 halves (4 x 16B)
    const int ldrow = tid >> 1;
    const int ldcol = (tid & 1) * 32;
    const __half* gA = A + (size_t)(m0 + ldrow) * lda + ldcol;
    const __half* gB = B + (size_t)(n0 + ldrow) * ldb + ldcol;
    const uint32_t smbase = smem_to_u32(sm);
    const uint32_t dA = smbase + (uint32_t)(ldrow * OST + ldcol) * 2;
    const uint32_t dB = dA + GST_B;

    float acc[4][4][4] = {};
    const int nch = K >> 6;

    // prologue: chunks 0,1 -> stages 0,1
    #pragma unroll
    for (int p = 0; p < 2; p++) {
        if (p < nch) {
            const int kk = p << 6;
            const uint32_t st = (uint32_t)p * GSTAGE;
            #pragma unroll
            for (int i = 0; i < 4; i++) {
                CP_ASYNC16(dA + st + i * 16, gA + kk + i * 8);
                CP_ASYNC16(dB + st + i * 16, gB + kk + i * 8);
            }
        }
        CP_COMMIT();
    }

    for (int c = 0; c < nch; c++) {
        CP_WAIT(1);
        __syncthreads();

        // issue chunk c+2 into stage (c+2)%3 (slot's readers finished at iter c-1,
        // guaranteed by the barrier above). Empty commit keeps group count uniform.
        if (c + 2 < nch) {
            const int k1 = (c + 2) << 6;
            const uint32_t st = (uint32_t)((c + 2) % GNSTG) * GSTAGE;
            #pragma unroll
            for (int i = 0; i < 4; i++) {
                CP_ASYNC16(dA + st + i * 16, gA + k1 + i * 8);
                CP_ASYNC16(dB + st + i * 16, gB + k1 + i * 8);
            }
        }
        CP_COMMIT();

        const uint32_t sA = smbase + (uint32_t)(c % GNSTG) * GSTAGE;
        const uint32_t sB = sA + GST_B;
        #pragma unroll
        for (int s = 0; s < 4; s++) {
            const int ko = s * 16;
            uint32_t af[4][4];
            #pragma unroll
            for (int mt = 0; mt < 4; mt++) {
                uint32_t addr = sA +
                    ((uint32_t)(warpM + mt * 16 + lrow) * OST + ko + lsel * 8) * 2;
                ldsm_x4(af[mt][0], af[mt][1], af[mt][2], af[mt][3], addr);
            }
            uint32_t bf[4][2];
            #pragma unroll
            for (int pt = 0; pt < 2; pt++) {
                uint32_t r0, r1, r2, r3;
                uint32_t addr = sB +
                    ((uint32_t)(warpN + pt * 16 + lrow) * OST + ko + lsel * 8) * 2;
                ldsm_x4(r0, r1, r2, r3, addr);
                bf[pt * 2][0] = r0;     bf[pt * 2][1] = r2;
                bf[pt * 2 + 1][0] = r1; bf[pt * 2 + 1][1] = r3;
            }
            #pragma unroll
            for (int mt = 0; mt < 4; mt++)
                #pragma unroll
                for (int nt = 0; nt < 4; nt++)
                    mma16816h(acc[mt][nt], af[mt][0], af[mt][1], af[mt][2], af[mt][3],
                              bf[nt][0], bf[nt][1]);
        }
    }

    const int r = lane >> 2, cpair = (lane & 3) * 2;
    #pragma unroll
    for (int mt = 0; mt < 4; mt++) {
        int gm0 = m0 + warpM + mt * 16 + r;
        #pragma unroll
        for (int nt = 0; nt < 4; nt++) {
            int gn = n0 + warpN + nt * 8 + cpair;
            out.store2(gm0,     gn, acc[mt][nt][0], acc[mt][nt][1]);
            out.store2(gm0 + 8, gn, acc[mt][nt][2], acc[mt][nt][3]);
        }
    }
}

// ---------------- fp32 -> fp16 conversion (weights, once per call) ----
__global__ void k_split_h(const float* __restrict__ src, __half* __restrict__ dst, int n4)
{
    int i = blockIdx.x * blockDim.x + threadIdx.x;
    if (i >= n4) return;
    ((uint2*)dst)[i] = cvt_h(((const float4*)src)[i]);
}

// =====================================================================
// Fused flash attention — fp16 2-product (unchanged math from R13/R14):
// S=(Qh+Ql)Kh, O+=(Ph+Pl)Vh. Reads fp32 qkv; writes fp16 attn.
// =====================================================================
#define FL_QROWS 128
#define FL_KT    64
#define FL_QST   136
#define FL_QRB   (FL_QST * 2)     // 272
#define FL_KST   72
#define FL_KRB   (FL_KST * 2)     // 144
#define FLASH_SMEM (FL_QROWS * FL_QRB + 2 * FL_KT * FL_KRB)   // 53248

__global__ void __launch_bounds__(256, 2)
k_flash(const float* __restrict__ qkv, __half* __restrict__ attn)
{
    extern __shared__ char sm8[];
    const uint32_t sQ = smem_to_u32(sm8);
    const uint32_t sK = sQ + FL_QROWS * FL_QRB;
    const uint32_t sV = sK + FL_KT * FL_KRB;
    char* pQ = sm8;
    char* pK = sm8 + FL_QROWS * FL_QRB;
    char* pV = pK + FL_KT * FL_KRB;

    const int tid = threadIdx.x, lane = tid & 31, wid = tid >> 5;
    const int lrow = lane & 15, lsel = lane >> 4;
    const int bh = blockIdx.x;
    const int b = bh >> 4, hq = bh & 15, hk = hq >> 2;
    const int q0 = (int)(gridDim.y - 1 - blockIdx.y) * FL_QROWS;

    const int seqstride = B_ * QKV_OUT_;
    const float* Qg = qkv + (size_t)b * QKV_OUT_ + hq * HD_;
    const float* Kg = qkv + (size_t)b * QKV_OUT_ + NH_ * HD_ + hk * HD_;
    const float* Vg = qkv + (size_t)b * QKV_OUT_ + (NH_ + NKV_) * HD_ + hk * HD_;

    #pragma unroll
    for (int i = 0; i < 8; i++) {
        int f = tid + i * 256;
        int row = f >> 4, c4 = f & 15;
        float4 v = *(const float4*)&Qg[(size_t)(q0 + row) * seqstride + c4 * 4];
        uint2 hi, lo;
        cvt_split_h(v, hi, lo);
        char* pr = pQ + row * FL_QRB;
        *(uint2*)(pr + c4 * 8) = hi;
        *(uint2*)(pr + 128 + c4 * 8) = lo;
    }

    float accO[8][4] = {};
    float S[8][4];
    float m0 = -1e30f, m1 = -1e30f, l0 = 0.f, l1 = 0.f;

    const int rbase = q0 + wid * 16;
    const int q_hi = rbase + 15;
    const int jmax = (q0 >> 6) + 2;

    for (int j = 0; j < jmax; j++) {
        const int jbase = j * FL_KT;
        #pragma unroll
        for (int i = 0; i < 4; i++) {
            int f = tid + i * 256;
            int row = f >> 4, c4 = f & 15;
            size_t go = (size_t)(jbase + row) * seqstride + c4 * 4;
            *(uint2*)(pK + row * FL_KRB + c4 * 8) = cvt_h(*(const float4*)&Kg[go]);
            *(uint2*)(pV + row * FL_KRB + c4 * 8) = cvt_h(*(const float4*)&Vg[go]);
        }
        __syncthreads();

        if (jbase <= q_hi) {
            #pragma unroll
            for (int t = 0; t < 8; t++) {
                S[t][0] = 0.f; S[t][1] = 0.f; S[t][2] = 0.f; S[t][3] = 0.f;
            }
            #pragma unroll
            for (int s = 0; s < 4; s++) {
                uint32_t qh[4], ql[4];
                uint32_t qaddr = sQ + (uint32_t)(wid * 16 + lrow) * FL_QRB +
                                 (s * 16 + lsel * 8) * 2;
                ldsm_x4(qh[0], qh[1], qh[2], qh[3], qaddr);
                ldsm_x4(ql[0], ql[1], ql[2], ql[3], qaddr + 128);
                #pragma unroll
                for (int g = 0; g < 4; g++) {
                    uint32_t r0, r1, r2, r3;
                    uint32_t kaddr = sK + (uint32_t)(g * 16 + lrow) * FL_KRB +
                                     (s * 16 + lsel * 8) * 2;
                    ldsm_x4(r0, r1, r2, r3, kaddr);
                    mma16816h(S[g * 2],     qh[0], qh[1], qh[2], qh[3], r0, r2);
                    mma16816h(S[g * 2],     ql[0], ql[1], ql[2], ql[3], r0, r2);
                    mma16816h(S[g * 2 + 1], qh[0], qh[1], qh[2], qh[3], r1, r3);
                    mma16816h(S[g * 2 + 1], ql[0], ql[1], ql[2], ql[3], r1, r3);
                }
            }

            const float scale = 0.125f;
            #pragma unroll
            for (int t = 0; t < 8; t++) {
                S[t][0] *= scale; S[t][1] *= scale;
                S[t][2] *= scale; S[t][3] *= scale;
            }
            if (jbase + 63 > rbase) {
                int r0g = rbase + (lane >> 2);
                int cg = jbase + (lane & 3) * 2;
                #pragma unroll
                for (int t = 0; t < 8; t++) {
                    int c0 = cg + t * 8;
                    if (c0 > r0g)     S[t][0] = -1e30f;
                    if (c0 + 1 > r0g) S[t][1] = -1e30f;
                    if (c0 > r0g + 8)     S[t][2] = -1e30f;
                    if (c0 + 1 > r0g + 8) S[t][3] = -1e30f;
                }
            }

            float tm0 = -1e30f, tm1 = -1e30f;
            #pragma unroll
            for (int t = 0; t < 8; t++) {
                tm0 = fmaxf(tm0, fmaxf(S[t][0], S[t][1]));
                tm1 = fmaxf(tm1, fmaxf(S[t][2], S[t][3]));
            }
            tm0 = fmaxf(tm0, __shfl_xor_sync(0xFFFFFFFFu, tm0, 1));
            tm0 = fmaxf(tm0, __shfl_xor_sync(0xFFFFFFFFu, tm0, 2));
            tm1 = fmaxf(tm1, __shfl_xor_sync(0xFFFFFFFFu, tm1, 1));
            tm1 = fmaxf(tm1, __shfl_xor_sync(0xFFFFFFFFu, tm1, 2));
            float mn0 = fmaxf(m0, tm0), mn1 = fmaxf(m1, tm1);
            float fac0 = __expf(m0 - mn0), fac1 = __expf(m1 - mn1);

            float ts0 = 0.f, ts1 = 0.f;
            #pragma unroll
            for (int t = 0; t < 8; t++) {
                S[t][0] = __expf(S[t][0] - mn0);
                S[t][1] = __expf(S[t][1] - mn0);
                S[t][2] = __expf(S[t][2] - mn1);
                S[t][3] = __expf(S[t][3] - mn1);
                ts0 += S[t][0] + S[t][1];
                ts1 += S[t][2] + S[t][3];
            }
            ts0 += __shfl_xor_sync(0xFFFFFFFFu, ts0, 1);
            ts0 += __shfl_xor_sync(0xFFFFFFFFu, ts0, 2);
            ts1 += __shfl_xor_sync(0xFFFFFFFFu, ts1, 1);
            ts1 += __shfl_xor_sync(0xFFFFFFFFu, ts1, 2);
            l0 = l0 * fac0 + ts0;
            l1 = l1 * fac1 + ts1;
            m0 = mn0; m1 = mn1;

            #pragma unroll
            for (int t = 0; t < 8; t++) {
                accO[t][0] *= fac0; accO[t][1] *= fac0;
                accO[t][2] *= fac1; accO[t][3] *= fac1;
            }

            #pragma unroll
            for (int s = 0; s < 4; s++) {
                uint32_t ah[4], al[4];
                ah[0] = pack_h2(S[2*s][0],   S[2*s][1]);
                ah[1] = pack_h2(S[2*s][2],   S[2*s][3]);
                ah[2] = pack_h2(S[2*s+1][0], S[2*s+1][1]);
                ah[3] = pack_h2(S[2*s+1][2], S[2*s+1][3]);
                #pragma unroll
                for (int i = 0; i < 4; i++) {
                    const float* sp = (i < 2) ? S[2*s] : S[2*s+1];
                    int o = (i & 1) * 2;
                    float2 f = __half22float2(*(__half2*)&ah[i]);
                    al[i] = pack_h2(sp[o] - f.x, sp[o + 1] - f.y);
                }
                #pragma unroll
                for (int dg = 0; dg < 4; dg++) {
                    uint32_t vrow = (uint32_t)(s * 16 + ((lane >> 3) & 1) * 8 + (lane & 7));
                    uint32_t vcol = (uint32_t)(dg * 16 + (lane >> 4) * 8);
                    uint32_t vaddr = sV + vrow * FL_KRB + vcol * 2;
                    uint32_t h0, h1, h2, h3;
                    ldsm_x4_t(h0, h1, h2, h3, vaddr);
                    mma16816h(accO[dg * 2],     ah[0], ah[1], ah[2], ah[3], h0, h1);
                    mma16816h(accO[dg * 2],     al[0], al[1], al[2], al[3], h0, h1);
                    mma16816h(accO[dg * 2 + 1], ah[0], ah[1], ah[2], ah[3], h2, h3);
                    mma16816h(accO[dg * 2 + 1], al[0], al[1], al[2], al[3], h2, h3);
                }
            }
        }
        __syncthreads();
    }

    // finalize: write fp16 attn (proj consumes fp16 directly)
    float inv0 = 1.f / l0, inv1 = 1.f / l1;
    int r0g = rbase + (lane >> 2);
    __half* Og = attn + (size_t)b * H_ + hq * HD_;
    const int ostride = B_ * H_;
    #pragma unroll
    for (int t = 0; t < 8; t++) {
        int gd = t * 8 + (lane & 3) * 2;
        *(uint32_t*)&Og[(size_t)r0g * ostride + gd] =
            pack_h2(accO[t][0] * inv0, accO[t][1] * inv0);
        *(uint32_t*)&Og[(size_t)(r0g + 8) * ostride + gd] =
            pack_h2(accO[t][2] * inv1, accO[t][3] * inv1);
    }
}

// ---------------- layernorm (fp16 output, for GEMM A) ----------------
__global__ void k_layernorm_h(const float* __restrict__ x, const float* __restrict__ w,
                              const float* __restrict__ b, __half* __restrict__ y)
{
    int t = blockIdx.x;
    int h0 = threadIdx.x * 4;
    float4 v = *(const float4*)&x[(size_t)t * H_ + h0];
    float s = v.x + v.y + v.z + v.w;
    float s2 = v.x*v.x + v.y*v.y + v.z*v.z + v.w*v.w;
    __shared__ float r1[256], r2[256];
    r1[threadIdx.x] = s; r2[threadIdx.x] = s2;
    __syncthreads();
    for (int o = 128; o; o >>= 1) {
        if (threadIdx.x < o) {
            r1[threadIdx.x] += r1[threadIdx.x + o];
            r2[threadIdx.x] += r2[threadIdx.x + o];
        }
        __syncthreads();
    }
    float mean = r1[0] * (1.0f / H_);
    float var  = r2[0] * (1.0f / H_) - mean * mean;
    float inv  = rsqrtf(var + 1e-5f);
    float4 wv = *(const float4*)&w[h0];
    float4 bv = *(const float4*)&b[h0];
    float4 yv = make_float4((v.x - mean) * inv * wv.x + bv.x,
                            (v.y - mean) * inv * wv.y + bv.y,
                            (v.z - mean) * inv * wv.z + bv.z,
                            (v.w - mean) * inv * wv.w + bv.w);
    ((uint2*)(y + (size_t)t * H_))[threadIdx.x] = cvt_h(yv);
}

// ---------------- layernorm (fp32 output, for router/dispatch) --------
__global__ void k_layernorm(const float* __restrict__ x, const float* __restrict__ w,
                            const float* __restrict__ b, float* __restrict__ y)
{
    int t = blockIdx.x;
    int h0 = threadIdx.x * 4;
    float4 v = *(const float4*)&x[(size_t)t * H_ + h0];
    float s = v.x + v.y + v.z + v.w;
    float s2 = v.x*v.x + v.y*v.y + v.z*v.z + v.w*v.w;
    __shared__ float r1[256], r2[256];
    r1[threadIdx.x] = s; r2[threadIdx.x] = s2;
    __syncthreads();
    for (int o = 128; o; o >>= 1) {
        if (threadIdx.x < o) {
            r1[threadIdx.x] += r1[threadIdx.x + o];
            r2[threadIdx.x] += r2[threadIdx.x + o];
        }
        __syncthreads();
    }
    float mean = r1[0] * (1.0f / H_);
    float var  = r2[0] * (1.0f / H_) - mean * mean;
    float inv  = rsqrtf(var + 1e-5f);
    float4 wv = *(const float4*)&w[h0];
    float4 bv = *(const float4*)&b[h0];
    float4 yv = make_float4((v.x - mean) * inv * wv.x + bv.x,
                            (v.y - mean) * inv * wv.y + bv.y,
                            (v.z - mean) * inv * wv.z + bv.z,
                            (v.w - mean) * inv * wv.w + bv.w);
    *(float4*)&y[(size_t)t * H_ + h0] = yv;
}

// ---------------- router ----------------
__global__ void k_router(const float* __restrict__ ln2, const float* __restrict__ Wr,
                         int* __restrict__ expidx, float* __restrict__ gate)
{
    int t = blockIdx.x;
    __shared__ float logits[E_];
    int w = threadIdx.x >> 5, lane = threadIdx.x & 31;
    const float* x = ln2 + (size_t)t * H_;
    const float* wr = Wr + (size_t)w * H_;
    float s = 0.f;
    for (int i = lane; i < H_; i += 32) s += x[i] * wr[i];
    #pragma unroll
    for (int o = 16; o; o >>= 1) s += __shfl_xor_sync(0xFFFFFFFFu, s, o);
    if (lane == 0) logits[w] = s;
    __syncthreads();
    if (threadIdx.x == 0) {
        float lmax = -1e30f;
        #pragma unroll
        for (int e = 0; e < E_; e++) lmax = fmaxf(lmax, logits[e]);
        float den = 0.f;
        #pragma unroll
        for (int e = 0; e < E_; e++) den += expf(logits[e] - lmax);
        int i1 = 0; float v1 = logits[0];
        #pragma unroll
        for (int e = 1; e < E_; e++) if (logits[e] > v1) { v1 = logits[e]; i1 = e; }
        int i2 = -1; float v2 = -1e30f;
        #pragma unroll
        for (int e = 0; e < E_; e++) if (e != i1 && logits[e] > v2) { v2 = logits[e]; i2 = e; }
        float inv = 1.0f / den;
        expidx[2 * t]     = i1;  gate[2 * t]     = expf(v1 - lmax) * inv;
        expidx[2 * t + 1] = i2;  gate[2 * t + 1] = expf(v2 - lmax) * inv;
    }
}

// ---------------- slot positions + per-expert counts (ballot scan) ----------
__global__ void k_pos(const int* __restrict__ expidx, int* __restrict__ pos,
                      int* __restrict__ cnt)
{
    __shared__ int sidx[NSLOT_];
    for (int i = threadIdx.x; i < NSLOT_; i += 512) sidx[i] = expidx[i];
    __syncthreads();
    int w = threadIdx.x >> 5, lane = threadIdx.x & 31;
    int c = 0;
    for (int base = 0; base < NSLOT_; base += 32) {
        bool f = (sidx[base + lane] == w);
        unsigned m = __ballot_sync(0xFFFFFFFFu, f);
        if (f) pos[base + lane] = c + __popc(m & ((1u << lane) - 1));
        c += __popc(m);
    }
    if (lane == 0) cnt[w] = (c < CAP_) ? c : CAP_;
}

// ---------------- dispatch kept slots into fp16 expert buffer ----------------
__global__ void k_dispatch(const float* __restrict__ ln2, const int* __restrict__ expidx,
                           const int* __restrict__ pos, __half* __restrict__ buf)
{
    int slot = blockIdx.x;
    int p = pos[slot];
    if (p >= CAP_) return;
    int e = expidx[slot];
    int t = slot >> 1;
    float4 v = *(const float4*)&ln2[(size_t)t * H_ + threadIdx.x * 4];
    ((uint2*)(buf + ((size_t)e * CAP_ + p) * H_))[threadIdx.x] = cvt_h(v);
}

// ---------------- combine: residual + gated expert outputs ----------------
__global__ void k_combine(const float* __restrict__ hattn, const float* __restrict__ h2,
                          const int* __restrict__ expidx, const int* __restrict__ pos,
                          const float* __restrict__ gate, float* __restrict__ out)
{
    int t = blockIdx.x;
    int s0 = 2 * t, s1 = 2 * t + 1;
    int p0 = pos[s0], p1 = pos[s1];
    int e0 = expidx[s0], e1 = expidx[s1];
    float g0 = (p0 < CAP_) ? gate[s0] : 0.f;
    float g1 = (p1 < CAP_) ? gate[s1] : 0.f;
    const float* r0 = (p0 < CAP_) ? h2 + ((size_t)e0 * CAP_ + p0) * H_ : nullptr;
    const float* r1 = (p1 < CAP_) ? h2 + ((size_t)e1 * CAP_ + p1) * H_ : nullptr;
    for (int h = threadIdx.x; h < H_; h += 256) {
        float v = hattn[(size_t)t * H_ + h];
        if (r0) v += r0[h] * g0;
        if (r1) v += r1[h] * g1;
        out[(size_t)t * H_ + h] = v;
    }
}

// ---------------- launch ----------------
extern "C" void kernel_launch(void* const* d_in, const int* in_sizes, int n_in,
                              void* d_out, int out_size)
{
    const float* hidden  = (const float*)d_in[0];
    const float* ln1w    = (const float*)d_in[1];
    const float* ln1b    = (const float*)d_in[2];
    const float* ln2w    = (const float*)d_in[3];
    const float* ln2b    = (const float*)d_in[4];
    const float* qkvw    = (const float*)d_in[5];
    const float* projw   = (const float*)d_in[6];
    const float* routerw = (const float*)d_in[7];
    const float* w1      = (const float*)d_in[8];
    const float* w2      = (const float*)d_in[9];
    float* out = (float*)d_out;

    __half *ln1, *attn, *buf, *h1, *qkvw16, *projw16, *w116, *w216;
    float *qkv, *hattn, *ln2, *gatep, *h2;
    int *expidx, *pos, *cnt;
    cudaGetSymbolAddress((void**)&ln1,     g_ln1);
    cudaGetSymbolAddress((void**)&qkv,     g_qkv);
    cudaGetSymbolAddress((void**)&attn,    g_attn);
    cudaGetSymbolAddress((void**)&hattn,   g_hattn);
    cudaGetSymbolAddress((void**)&ln2,     g_ln2);
    cudaGetSymbolAddress((void**)&expidx,  g_expidx);
    cudaGetSymbolAddress((void**)&pos,     g_pos);
    cudaGetSymbolAddress((void**)&cnt,     g_cnt);
    cudaGetSymbolAddress((void**)&gatep,   g_gate);
    cudaGetSymbolAddress((void**)&buf,     g_buf);
    cudaGetSymbolAddress((void**)&h1,      g_h1);
    cudaGetSymbolAddress((void**)&h2,      g_h2);
    cudaGetSymbolAddress((void**)&qkvw16,  g_qkvw16);
    cudaGetSymbolAddress((void**)&projw16, g_projw16);
    cudaGetSymbolAddress((void**)&w116,    g_w116);
    cudaGetSymbolAddress((void**)&w216,    g_w216);

    cudaFuncSetAttribute((void*)k_gemm_h<OutF32>,
                         cudaFuncAttributeMaxDynamicSharedMemorySize, GEMM_SMEM);
    cudaFuncSetAttribute((void*)k_gemm_h<OutResid>,
                         cudaFuncAttributeMaxDynamicSharedMemorySize, GEMM_SMEM);
    cudaFuncSetAttribute((void*)k_gemm_h<OutGeluH>,
                         cudaFuncAttributeMaxDynamicSharedMemorySize, GEMM_SMEM);
    cudaFuncSetAttribute((void*)k_flash,
                         cudaFuncAttributeMaxDynamicSharedMemorySize, FLASH_SMEM);

    // weight fp16 conversion (one rounding; GEMM operands identical to R14)
    k_split_h<<<(QKV_OUT_ * H_ / 4) / 256, 256>>>(qkvw, qkvw16, QKV_OUT_ * H_ / 4);
    k_split_h<<<(H_ * H_ / 4) / 256, 256>>>(projw, projw16, H_ * H_ / 4);
    k_split_h<<<(E_ * FFN_ * H_ / 4) / 256, 256>>>(w1, w116, E_ * FFN_ * H_ / 4);
    k_split_h<<<(E_ * H_ * FFN_ / 4) / 256, 256>>>(w2, w216, E_ * H_ * FFN_ / 4);

    // LN1 (fp16 out)
    k_layernorm_h<<<T_, 256>>>(hidden, ln1w, ln1b, ln1);
    // QKV = ln1 @ W_qkv^T -> fp32 qkv (flash input)
    k_gemm_h<<<dim3(QKV_OUT_ / 128, T_ / 128, 1), 256, GEMM_SMEM>>>(
        ln1, H_, (size_t)0, qkvw16, H_, (size_t)0, H_,
        OutF32{qkv, QKV_OUT_, 0}, nullptr);
    // fused causal flash attention -> fp16 attn
    k_flash<<<dim3(B_ * NH_, S_ / FL_QROWS), 256, FLASH_SMEM>>>(qkv, attn);
    // proj + residual -> fp32 hattn
    k_gemm_h<<<dim3(H_ / 128, T_ / 128, 1), 256, GEMM_SMEM>>>(
        attn, H_, (size_t)0, projw16, H_, (size_t)0, H_,
        OutResid{hattn, hidden, H_}, nullptr);
    // LN2 (fp32)
    k_layernorm<<<T_, 256>>>(hattn, ln2w, ln2b, ln2);
    // router top-2
    k_router<<<T_, 512>>>(ln2, routerw, expidx, gatep);
    // slot positions + counts
    k_pos<<<1, 512>>>(expidx, pos, cnt);
    // dispatch -> fp16 buf
    k_dispatch<<<NSLOT_, 256>>>(ln2, expidx, pos, buf);
    // expert FC1 (gelu -> fp16 h1) and FC2 (fp32 h2), count-gated
    k_gemm_h<<<dim3(FFN_ / 128, CAP_ / 128, E_), 256, GEMM_SMEM>>>(
        buf, H_, (size_t)CAP_ * H_, w116, H_, (size_t)FFN_ * H_, H_,
        OutGeluH{h1, FFN_, (size_t)CAP_ * FFN_}, cnt);
    k_gemm_h<<<dim3(H_ / 128, CAP_ / 128, E_), 256, GEMM_SMEM>>>(
        h1, FFN_, (size_t)CAP_ * FFN_, w216, FFN_, (size_t)H_ * FFN_, FFN_,
        OutF32{h2, H_, (size_t)CAP_ * H_}, cnt);
    // combine + final residual
    k_combine<<<T_, 256>>>(hattn, h2, expidx, pos, gatep, out);
}

// round 16
// speedup vs baseline: 2.2796x; 1.0265x over previous
#include <cuda_runtime.h>
#include <cuda_fp16.h>
#include <math.h>
#include <stdint.h>

// ---------------- problem constants ----------------
#define S_   2048
#define B_   2
#define H_   1024
#define NH_  16
#define NKV_ 4
#define HD_  64
#define T_   4096            // S_*B_
#define QKV_OUT_ 1536
#define E_   16
#define TOPK_ 2
#define FFN_ 2048
#define CAP_ 640             // ceil(T*K/E*1.25)
#define NSLOT_ (T_*TOPK_)

// ---------------- scratch (device globals; no runtime allocation) ----------------
__device__ __align__(16) __half g_ln1[(size_t)T_*H_];
__device__ __align__(16) float  g_qkv[(size_t)T_*QKV_OUT_];
__device__ __align__(16) __half g_attn[(size_t)T_*H_];
__device__ __align__(16) float  g_hattn[(size_t)T_*H_];
__device__ __align__(16) float  g_ln2[(size_t)T_*H_];
__device__ int   g_expidx[NSLOT_];
__device__ int   g_pos[NSLOT_];
__device__ int   g_cnt[E_];
__device__ float g_gate[NSLOT_];
__device__ __align__(16) __half g_buf[(size_t)E_*CAP_*H_];
__device__ __align__(16) __half g_h1[(size_t)E_*CAP_*FFN_];
__device__ __align__(16) float  g_h2[(size_t)E_*CAP_*H_];
// fp16 weights (converted once per call)
__device__ __align__(16) __half g_qkvw16[(size_t)QKV_OUT_*H_];
__device__ __align__(16) __half g_projw16[(size_t)H_*H_];
__device__ __align__(16) __half g_w116[(size_t)E_*FFN_*H_];
__device__ __align__(16) __half g_w216[(size_t)E_*H_*FFN_];

// =====================================================================
// PTX helpers (baseline sm_80+ ISA — tcgen05 unavailable on this target)
// =====================================================================
__device__ __forceinline__ uint32_t smem_to_u32(const void* smem_ptr) {
    uint32_t addr;
    asm("{ .reg .u64 tmp; cvta.to.shared.u64 tmp, %1; cvt.u32.u64 %0, tmp; }"
        : "=r"(addr) : "l"(smem_ptr));
    return addr;
}

#define CP_ASYNC16(dst_u32, src_ptr) \
    asm volatile("cp.async.cg.shared.global [%0], [%1], 16;" \
        :: "r"(dst_u32), "l"(src_ptr))
#define CP_COMMIT() asm volatile("cp.async.commit_group;" ::: "memory")
#define CP_WAIT(n)  asm volatile("cp.async.wait_group %0;" :: "n"(n) : "memory")

__device__ __forceinline__ void ldsm_x4(uint32_t& r0, uint32_t& r1,
                                        uint32_t& r2, uint32_t& r3, uint32_t addr) {
    asm volatile("ldmatrix.sync.aligned.m8n8.x4.shared.b16 {%0,%1,%2,%3}, [%4];"
                 : "=r"(r0), "=r"(r1), "=r"(r2), "=r"(r3) : "r"(addr));
}
__device__ __forceinline__ void ldsm_x4_t(uint32_t& r0, uint32_t& r1,
                                          uint32_t& r2, uint32_t& r3, uint32_t addr) {
    asm volatile("ldmatrix.sync.aligned.m8n8.x4.trans.shared.b16 {%0,%1,%2,%3}, [%4];"
                 : "=r"(r0), "=r"(r1), "=r"(r2), "=r"(r3) : "r"(addr));
}

__device__ __forceinline__ void mma16816h(float* c,
        uint32_t a0, uint32_t a1, uint32_t a2, uint32_t a3,
        uint32_t b0, uint32_t b1) {
    asm volatile(
        "mma.sync.aligned.m16n8k16.row.col.f32.f16.f16.f32 "
        "{%0,%1,%2,%3}, {%4,%5,%6,%7}, {%8,%9}, {%0,%1,%2,%3};"
        : "+f"(c[0]), "+f"(c[1]), "+f"(c[2]), "+f"(c[3])
        : "r"(a0), "r"(a1), "r"(a2), "r"(a3), "r"(b0), "r"(b1));
}

__device__ __forceinline__ uint32_t pack_h2(float a, float b) {
    __half2 h = __float22half2_rn(make_float2(a, b));
    return *(uint32_t*)&h;
}
__device__ __forceinline__ void cvt_split_h(float4 v, uint2& hi, uint2& lo) {
    __half2 h01 = __float22half2_rn(make_float2(v.x, v.y));
    __half2 h23 = __float22half2_rn(make_float2(v.z, v.w));
    float2 f01 = __half22float2(h01), f23 = __half22float2(h23);
    __half2 l01 = __float22half2_rn(make_float2(v.x - f01.x, v.y - f01.y));
    __half2 l23 = __float22half2_rn(make_float2(v.z - f23.x, v.w - f23.y));
    hi = make_uint2(*(uint32_t*)&h01, *(uint32_t*)&h23);
    lo = make_uint2(*(uint32_t*)&l01, *(uint32_t*)&l23);
}
__device__ __forceinline__ uint2 cvt_h(float4 v) {
    __half2 h01 = __float22half2_rn(make_float2(v.x, v.y));
    __half2 h23 = __float22half2_rn(make_float2(v.z, v.w));
    return make_uint2(*(uint32_t*)&h01, *(uint32_t*)&h23);
}
__device__ __forceinline__ float gelu_tanh(float v) {
    float x = 0.7978845608028654f * (v + 0.044715f * v * v * v);
    float t = 1.0f - 2.0f / (__expf(2.0f * x) + 1.0f);
    return 0.5f * v * (1.0f + t);
}

// ---------------- GEMM output functors ----------------
struct OutF32 {
    float* C; int ldc; size_t cB;
    __device__ __forceinline__ void setz(int z) { C += (size_t)z * cB; }
    __device__ __forceinline__ void store2(int m, int n, float a, float b) {
        *(float2*)&C[(size_t)m * ldc + n] = make_float2(a, b);
    }
};
struct OutResid {
    float* C; const float* R; int ldc;
    __device__ __forceinline__ void setz(int) {}
    __device__ __forceinline__ void store2(int m, int n, float a, float b) {
        float2 r = *(const float2*)&R[(size_t)m * ldc + n];
        *(float2*)&C[(size_t)m * ldc + n] = make_float2(a + r.x, b + r.y);
    }
};
struct OutGeluH {
    __half* C; int ldc; size_t cB;
    __device__ __forceinline__ void setz(int z) { C += (size_t)z * cB; }
    __device__ __forceinline__ void store2(int m, int n, float a, float b) {
        *(uint32_t*)&C[(size_t)m * ldc + n] = pack_h2(gelu_tanh(a), gelu_tanh(b));
    }
};

// =====================================================================
// fp16 HMMA NT GEMM, fp16 operands in GLOBAL (preconverted by producers),
// 3-stage cp.async pipeline, ONE barrier per 64-K chunk, no conversions.
// (unchanged from R15 win)
// =====================================================================
#define OST 72
#define GST_B (128 * OST * 2)
#define GSTAGE (2 * GST_B)
#define GNSTG 3
#define GEMM_SMEM (GNSTG * GSTAGE)      // 110592

template<typename Out>
__global__ void __launch_bounds__(256, 2)
k_gemm_h(const __half* __restrict__ A, int lda, size_t aB,
         const __half* __restrict__ B, int ldb, size_t bB,
         int K, Out out, const int* __restrict__ cnt)
{
    if (cnt) {
        int lim = cnt[blockIdx.z];
        if (lim > CAP_) lim = CAP_;
        if ((int)(blockIdx.y * 128) >= lim) return;
    }

    extern __shared__ __half sm[];
    const int tid = threadIdx.x, lane = tid & 31, wid = tid >> 5;
    const int m0 = blockIdx.y * 128, n0 = blockIdx.x * 128;
    const int z = blockIdx.z;
    A += (size_t)z * aB;
    B += (size_t)z * bB;
    out.setz(z);
    const int warpM = (wid >> 2) * 64, warpN = (wid & 3) * 32;
    const int lrow = lane & 15, lsel = lane >> 4;

    const int ldrow = tid >> 1;
    const int ldcol = (tid & 1) * 32;
    const __half* gA = A + (size_t)(m0 + ldrow) * lda + ldcol;
    const __half* gB = B + (size_t)(n0 + ldrow) * ldb + ldcol;
    const uint32_t smbase = smem_to_u32(sm);
    const uint32_t dA = smbase + (uint32_t)(ldrow * OST + ldcol) * 2;
    const uint32_t dB = dA + GST_B;

    float acc[4][4][4] = {};
    const int nch = K >> 6;

    #pragma unroll
    for (int p = 0; p < 2; p++) {
        if (p < nch) {
            const int kk = p << 6;
            const uint32_t st = (uint32_t)p * GSTAGE;
            #pragma unroll
            for (int i = 0; i < 4; i++) {
                CP_ASYNC16(dA + st + i * 16, gA + kk + i * 8);
                CP_ASYNC16(dB + st + i * 16, gB + kk + i * 8);
            }
        }
        CP_COMMIT();
    }

    for (int c = 0; c < nch; c++) {
        CP_WAIT(1);
        __syncthreads();

        if (c + 2 < nch) {
            const int k1 = (c + 2) << 6;
            const uint32_t st = (uint32_t)((c + 2) % GNSTG) * GSTAGE;
            #pragma unroll
            for (int i = 0; i < 4; i++) {
                CP_ASYNC16(dA + st + i * 16, gA + k1 + i * 8);
                CP_ASYNC16(dB + st + i * 16, gB + k1 + i * 8);
            }
        }
        CP_COMMIT();

        const uint32_t sA = smbase + (uint32_t)(c % GNSTG) * GSTAGE;
        const uint32_t sB = sA + GST_B;
        #pragma unroll
        for (int s = 0; s < 4; s++) {
            const int ko = s * 16;
            uint32_t af[4][4];
            #pragma unroll
            for (int mt = 0; mt < 4; mt++) {
                uint32_t addr = sA +
                    ((uint32_t)(warpM + mt * 16 + lrow) * OST + ko + lsel * 8) * 2;
                ldsm_x4(af[mt][0], af[mt][1], af[mt][2], af[mt][3], addr);
            }
            uint32_t bf[4][2];
            #pragma unroll
            for (int pt = 0; pt < 2; pt++) {
                uint32_t r0, r1, r2, r3;
                uint32_t addr = sB +
                    ((uint32_t)(warpN + pt * 16 + lrow) * OST + ko + lsel * 8) * 2;
                ldsm_x4(r0, r1, r2, r3, addr);
                bf[pt * 2][0] = r0;     bf[pt * 2][1] = r2;
                bf[pt * 2 + 1][0] = r1; bf[pt * 2 + 1][1] = r3;
            }
            #pragma unroll
            for (int mt = 0; mt < 4; mt++)
                #pragma unroll
                for (int nt = 0; nt < 4; nt++)
                    mma16816h(acc[mt][nt], af[mt][0], af[mt][1], af[mt][2], af[mt][3],
                              bf[nt][0], bf[nt][1]);
        }
    }

    const int r = lane >> 2, cpair = (lane & 3) * 2;
    #pragma unroll
    for (int mt = 0; mt < 4; mt++) {
        int gm0 = m0 + warpM + mt * 16 + r;
        #pragma unroll
        for (int nt = 0; nt < 4; nt++) {
            int gn = n0 + warpN + nt * 8 + cpair;
            out.store2(gm0,     gn, acc[mt][nt][0], acc[mt][nt][1]);
            out.store2(gm0 + 8, gn, acc[mt][nt][2], acc[mt][nt][3]);
        }
    }
}

// ---------------- fp32 -> fp16 conversion (weights, once per call) ----
__global__ void k_split_h(const float* __restrict__ src, __half* __restrict__ dst, int n4)
{
    int i = blockIdx.x * blockDim.x + threadIdx.x;
    if (i >= n4) return;
    ((uint2*)dst)[i] = cvt_h(((const float4*)src)[i]);
}

// =====================================================================
// Fused flash attention — S=(Qh+Ql)Kh (2-product, exp-sensitive logits),
// O += Ph*Vh (1-product: error ~2.4e-4 rel, inside budget).
// Reads fp32 qkv; writes fp16 attn.
// =====================================================================
#define FL_QROWS 128
#define FL_KT    64
#define FL_QST   136
#define FL_QRB   (FL_QST * 2)
#define FL_KST   72
#define FL_KRB   (FL_KST * 2)
#define FLASH_SMEM (FL_QROWS * FL_QRB + 2 * FL_KT * FL_KRB)   // 53248

__global__ void __launch_bounds__(256, 2)
k_flash(const float* __restrict__ qkv, __half* __restrict__ attn)
{
    extern __shared__ char sm8[];
    const uint32_t sQ = smem_to_u32(sm8);
    const uint32_t sK = sQ + FL_QROWS * FL_QRB;
    const uint32_t sV = sK + FL_KT * FL_KRB;
    char* pQ = sm8;
    char* pK = sm8 + FL_QROWS * FL_QRB;
    char* pV = pK + FL_KT * FL_KRB;

    const int tid = threadIdx.x, lane = tid & 31, wid = tid >> 5;
    const int lrow = lane & 15, lsel = lane >> 4;
    const int bh = blockIdx.x;
    const int b = bh >> 4, hq = bh & 15, hk = hq >> 2;
    const int q0 = (int)(gridDim.y - 1 - blockIdx.y) * FL_QROWS;

    const int seqstride = B_ * QKV_OUT_;
    const float* Qg = qkv + (size_t)b * QKV_OUT_ + hq * HD_;
    const float* Kg = qkv + (size_t)b * QKV_OUT_ + NH_ * HD_ + hk * HD_;
    const float* Vg = qkv + (size_t)b * QKV_OUT_ + (NH_ + NKV_) * HD_ + hk * HD_;

    #pragma unroll
    for (int i = 0; i < 8; i++) {
        int f = tid + i * 256;
        int row = f >> 4, c4 = f & 15;
        float4 v = *(const float4*)&Qg[(size_t)(q0 + row) * seqstride + c4 * 4];
        uint2 hi, lo;
        cvt_split_h(v, hi, lo);
        char* pr = pQ + row * FL_QRB;
        *(uint2*)(pr + c4 * 8) = hi;
        *(uint2*)(pr + 128 + c4 * 8) = lo;
    }

    float accO[8][4] = {};
    float S[8][4];
    float m0 = -1e30f, m1 = -1e30f, l0 = 0.f, l1 = 0.f;

    const int rbase = q0 + wid * 16;
    const int q_hi = rbase + 15;
    const int jmax = (q0 >> 6) + 2;

    for (int j = 0; j < jmax; j++) {
        const int jbase = j * FL_KT;
        #pragma unroll
        for (int i = 0; i < 4; i++) {
            int f = tid + i * 256;
            int row = f >> 4, c4 = f & 15;
            size_t go = (size_t)(jbase + row) * seqstride + c4 * 4;
            *(uint2*)(pK + row * FL_KRB + c4 * 8) = cvt_h(*(const float4*)&Kg[go]);
            *(uint2*)(pV + row * FL_KRB + c4 * 8) = cvt_h(*(const float4*)&Vg[go]);
        }
        __syncthreads();

        if (jbase <= q_hi) {
            #pragma unroll
            for (int t = 0; t < 8; t++) {
                S[t][0] = 0.f; S[t][1] = 0.f; S[t][2] = 0.f; S[t][3] = 0.f;
            }
            #pragma unroll
            for (int s = 0; s < 4; s++) {
                uint32_t qh[4], ql[4];
                uint32_t qaddr = sQ + (uint32_t)(wid * 16 + lrow) * FL_QRB +
                                 (s * 16 + lsel * 8) * 2;
                ldsm_x4(qh[0], qh[1], qh[2], qh[3], qaddr);
                ldsm_x4(ql[0], ql[1], ql[2], ql[3], qaddr + 128);
                #pragma unroll
                for (int g = 0; g < 4; g++) {
                    uint32_t r0, r1, r2, r3;
                    uint32_t kaddr = sK + (uint32_t)(g * 16 + lrow) * FL_KRB +
                                     (s * 16 + lsel * 8) * 2;
                    ldsm_x4(r0, r1, r2, r3, kaddr);
                    mma16816h(S[g * 2],     qh[0], qh[1], qh[2], qh[3], r0, r2);
                    mma16816h(S[g * 2],     ql[0], ql[1], ql[2], ql[3], r0, r2);
                    mma16816h(S[g * 2 + 1], qh[0], qh[1], qh[2], qh[3], r1, r3);
                    mma16816h(S[g * 2 + 1], ql[0], ql[1], ql[2], ql[3], r1, r3);
                }
            }

            const float scale = 0.125f;
            #pragma unroll
            for (int t = 0; t < 8; t++) {
                S[t][0] *= scale; S[t][1] *= scale;
                S[t][2] *= scale; S[t][3] *= scale;
            }
            if (jbase + 63 > rbase) {
                int r0g = rbase + (lane >> 2);
                int cg = jbase + (lane & 3) * 2;
                #pragma unroll
                for (int t = 0; t < 8; t++) {
                    int c0 = cg + t * 8;
                    if (c0 > r0g)     S[t][0] = -1e30f;
                    if (c0 + 1 > r0g) S[t][1] = -1e30f;
                    if (c0 > r0g + 8)     S[t][2] = -1e30f;
                    if (c0 + 1 > r0g + 8) S[t][3] = -1e30f;
                }
            }

            float tm0 = -1e30f, tm1 = -1e30f;
            #pragma unroll
            for (int t = 0; t < 8; t++) {
                tm0 = fmaxf(tm0, fmaxf(S[t][0], S[t][1]));
                tm1 = fmaxf(tm1, fmaxf(S[t][2], S[t][3]));
            }
            tm0 = fmaxf(tm0, __shfl_xor_sync(0xFFFFFFFFu, tm0, 1));
            tm0 = fmaxf(tm0, __shfl_xor_sync(0xFFFFFFFFu, tm0, 2));
            tm1 = fmaxf(tm1, __shfl_xor_sync(0xFFFFFFFFu, tm1, 1));
            tm1 = fmaxf(tm1, __shfl_xor_sync(0xFFFFFFFFu, tm1, 2));
            float mn0 = fmaxf(m0, tm0), mn1 = fmaxf(m1, tm1);
            float fac0 = __expf(m0 - mn0), fac1 = __expf(m1 - mn1);

            float ts0 = 0.f, ts1 = 0.f;
            #pragma unroll
            for (int t = 0; t < 8; t++) {
                S[t][0] = __expf(S[t][0] - mn0);
                S[t][1] = __expf(S[t][1] - mn0);
                S[t][2] = __expf(S[t][2] - mn1);
                S[t][3] = __expf(S[t][3] - mn1);
                ts0 += S[t][0] + S[t][1];
                ts1 += S[t][2] + S[t][3];
            }
            ts0 += __shfl_xor_sync(0xFFFFFFFFu, ts0, 1);
            ts0 += __shfl_xor_sync(0xFFFFFFFFu, ts0, 2);
            ts1 += __shfl_xor_sync(0xFFFFFFFFu, ts1, 1);
            ts1 += __shfl_xor_sync(0xFFFFFFFFu, ts1, 2);
            l0 = l0 * fac0 + ts0;
            l1 = l1 * fac1 + ts1;
            m0 = mn0; m1 = mn1;

            #pragma unroll
            for (int t = 0; t < 8; t++) {
                accO[t][0] *= fac0; accO[t][1] *= fac0;
                accO[t][2] *= fac1; accO[t][3] *= fac1;
            }

            // ---- O += Ph Vh (1-product) ----
            #pragma unroll
            for (int s = 0; s < 4; s++) {
                uint32_t ah[4];
                ah[0] = pack_h2(S[2*s][0],   S[2*s][1]);
                ah[1] = pack_h2(S[2*s][2],   S[2*s][3]);
                ah[2] = pack_h2(S[2*s+1][0], S[2*s+1][1]);
                ah[3] = pack_h2(S[2*s+1][2], S[2*s+1][3]);
                #pragma unroll
                for (int dg = 0; dg < 4; dg++) {
                    uint32_t vrow = (uint32_t)(s * 16 + ((lane >> 3) & 1) * 8 + (lane & 7));
                    uint32_t vcol = (uint32_t)(dg * 16 + (lane >> 4) * 8);
                    uint32_t vaddr = sV + vrow * FL_KRB + vcol * 2;
                    uint32_t h0, h1, h2, h3;
                    ldsm_x4_t(h0, h1, h2, h3, vaddr);
                    mma16816h(accO[dg * 2],     ah[0], ah[1], ah[2], ah[3], h0, h1);
                    mma16816h(accO[dg * 2 + 1], ah[0], ah[1], ah[2], ah[3], h2, h3);
                }
            }
        }
        __syncthreads();
    }

    float inv0 = 1.f / l0, inv1 = 1.f / l1;
    int r0g = rbase + (lane >> 2);
    __half* Og = attn + (size_t)b * H_ + hq * HD_;
    const int ostride = B_ * H_;
    #pragma unroll
    for (int t = 0; t < 8; t++) {
        int gd = t * 8 + (lane & 3) * 2;
        *(uint32_t*)&Og[(size_t)r0g * ostride + gd] =
            pack_h2(accO[t][0] * inv0, accO[t][1] * inv0);
        *(uint32_t*)&Og[(size_t)(r0g + 8) * ostride + gd] =
            pack_h2(accO[t][2] * inv1, accO[t][3] * inv1);
    }
}

// ---------------- layernorm (fp16 output, for GEMM A) ----------------
__global__ void k_layernorm_h(const float* __restrict__ x, const float* __restrict__ w,
                              const float* __restrict__ b, __half* __restrict__ y)
{
    int t = blockIdx.x;
    int h0 = threadIdx.x * 4;
    float4 v = *(const float4*)&x[(size_t)t * H_ + h0];
    float s = v.x + v.y + v.z + v.w;
    float s2 = v.x*v.x + v.y*v.y + v.z*v.z + v.w*v.w;
    __shared__ float r1[256], r2[256];
    r1[threadIdx.x] = s; r2[threadIdx.x] = s2;
    __syncthreads();
    for (int o = 128; o; o >>= 1) {
        if (threadIdx.x < o) {
            r1[threadIdx.x] += r1[threadIdx.x + o];
            r2[threadIdx.x] += r2[threadIdx.x + o];
        }
        __syncthreads();
    }
    float mean = r1[0] * (1.0f / H_);
    float var  = r2[0] * (1.0f / H_) - mean * mean;
    float inv  = rsqrtf(var + 1e-5f);
    float4 wv = *(const float4*)&w[h0];
    float4 bv = *(const float4*)&b[h0];
    float4 yv = make_float4((v.x - mean) * inv * wv.x + bv.x,
                            (v.y - mean) * inv * wv.y + bv.y,
                            (v.z - mean) * inv * wv.z + bv.z,
                            (v.w - mean) * inv * wv.w + bv.w);
    ((uint2*)(y + (size_t)t * H_))[threadIdx.x] = cvt_h(yv);
}

// ---------------- fused LN2 + router: normalize, write fp32 row, ----
// ---------------- then 16 expert dots from smem + top-2 softmax ----
__global__ void k_ln_router(const float* __restrict__ x, const float* __restrict__ w,
                            const float* __restrict__ b, float* __restrict__ y,
                            const float* __restrict__ Wr,
                            int* __restrict__ expidx, float* __restrict__ gate)
{
    int t = blockIdx.x;
    int tid = threadIdx.x;
    int h0 = tid * 4;
    __shared__ float r1[256], r2[256];
    __shared__ float rowbuf[H_];
    __shared__ float logits[E_];

    float4 v = *(const float4*)&x[(size_t)t * H_ + h0];
    float s = v.x + v.y + v.z + v.w;
    float s2 = v.x*v.x + v.y*v.y + v.z*v.z + v.w*v.w;
    r1[tid] = s; r2[tid] = s2;
    __syncthreads();
    for (int o = 128; o; o >>= 1) {
        if (tid < o) {
            r1[tid] += r1[tid + o];
            r2[tid] += r2[tid + o];
        }
        __syncthreads();
    }
    float mean = r1[0] * (1.0f / H_);
    float var  = r2[0] * (1.0f / H_) - mean * mean;
    float inv  = rsqrtf(var + 1e-5f);
    float4 wv = *(const float4*)&w[h0];
    float4 bv = *(const float4*)&b[h0];
    float4 yv = make_float4((v.x - mean) * inv * wv.x + bv.x,
                            (v.y - mean) * inv * wv.y + bv.y,
                            (v.z - mean) * inv * wv.z + bv.z,
                            (v.w - mean) * inv * wv.w + bv.w);
    *(float4*)&y[(size_t)t * H_ + h0] = yv;
    *(float4*)&rowbuf[h0] = yv;
    __syncthreads();

    // router dots: 8 warps x 2 experts each
    int wid = tid >> 5, lane = tid & 31;
    for (int e = wid; e < E_; e += 8) {
        const float* wr = Wr + (size_t)e * H_;
        float acc = 0.f;
        for (int i = lane; i < H_; i += 32) acc += rowbuf[i] * wr[i];
        #pragma unroll
        for (int o = 16; o; o >>= 1) acc += __shfl_xor_sync(0xFFFFFFFFu, acc, o);
        if (lane == 0) logits[e] = acc;
    }
    __syncthreads();
    if (tid == 0) {
        float lmax = -1e30f;
        #pragma unroll
        for (int e = 0; e < E_; e++) lmax = fmaxf(lmax, logits[e]);
        float den = 0.f;
        #pragma unroll
        for (int e = 0; e < E_; e++) den += expf(logits[e] - lmax);
        int i1 = 0; float v1 = logits[0];
        #pragma unroll
        for (int e = 1; e < E_; e++) if (logits[e] > v1) { v1 = logits[e]; i1 = e; }
        int i2 = -1; float v2 = -1e30f;
        #pragma unroll
        for (int e = 0; e < E_; e++) if (e != i1 && logits[e] > v2) { v2 = logits[e]; i2 = e; }
        float invd = 1.0f / den;
        expidx[2 * t]     = i1;  gate[2 * t]     = expf(v1 - lmax) * invd;
        expidx[2 * t + 1] = i2;  gate[2 * t + 1] = expf(v2 - lmax) * invd;
    }
}

// ---------------- slot positions + per-expert counts (ballot scan) ----------
__global__ void k_pos(const int* __restrict__ expidx, int* __restrict__ pos,
                      int* __restrict__ cnt)
{
    __shared__ int sidx[NSLOT_];
    for (int i = threadIdx.x; i < NSLOT_; i += 512) sidx[i] = expidx[i];
    __syncthreads();
    int w = threadIdx.x >> 5, lane = threadIdx.x & 31;
    int c = 0;
    for (int base = 0; base < NSLOT_; base += 32) {
        bool f = (sidx[base + lane] == w);
        unsigned m = __ballot_sync(0xFFFFFFFFu, f);
        if (f) pos[base + lane] = c + __popc(m & ((1u << lane) - 1));
        c += __popc(m);
    }
    if (lane == 0) cnt[w] = (c < CAP_) ? c : CAP_;
}

// ---------------- dispatch kept slots into fp16 expert buffer ----------------
__global__ void k_dispatch(const float* __restrict__ ln2, const int* __restrict__ expidx,
                           const int* __restrict__ pos, __half* __restrict__ buf)
{
    int slot = blockIdx.x;
    int p = pos[slot];
    if (p >= CAP_) return;
    int e = expidx[slot];
    int t = slot >> 1;
    float4 v = *(const float4*)&ln2[(size_t)t * H_ + threadIdx.x * 4];
    ((uint2*)(buf + ((size_t)e * CAP_ + p) * H_))[threadIdx.x] = cvt_h(v);
}

// ---------------- combine: residual + gated expert outputs ----------------
__global__ void k_combine(const float* __restrict__ hattn, const float* __restrict__ h2,
                          const int* __restrict__ expidx, const int* __restrict__ pos,
                          const float* __restrict__ gate, float* __restrict__ out)
{
    int t = blockIdx.x;
    int s0 = 2 * t, s1 = 2 * t + 1;
    int p0 = pos[s0], p1 = pos[s1];
    int e0 = expidx[s0], e1 = expidx[s1];
    float g0 = (p0 < CAP_) ? gate[s0] : 0.f;
    float g1 = (p1 < CAP_) ? gate[s1] : 0.f;
    const float* r0 = (p0 < CAP_) ? h2 + ((size_t)e0 * CAP_ + p0) * H_ : nullptr;
    const float* r1 = (p1 < CAP_) ? h2 + ((size_t)e1 * CAP_ + p1) * H_ : nullptr;
    for (int h = threadIdx.x; h < H_; h += 256) {
        float v = hattn[(size_t)t * H_ + h];
        if (r0) v += r0[h] * g0;
        if (r1) v += r1[h] * g1;
        out[(size_t)t * H_ + h] = v;
    }
}

// ---------------- launch ----------------
extern "C" void kernel_launch(void* const* d_in, const int* in_sizes, int n_in,
                              void* d_out, int out_size)
{
    const float* hidden  = (const float*)d_in[0];
    const float* ln1w    = (const float*)d_in[1];
    const float* ln1b    = (const float*)d_in[2];
    const float* ln2w    = (const float*)d_in[3];
    const float* ln2b    = (const float*)d_in[4];
    const float* qkvw    = (const float*)d_in[5];
    const float* projw   = (const float*)d_in[6];
    const float* routerw = (const float*)d_in[7];
    const float* w1      = (const float*)d_in[8];
    const float* w2      = (const float*)d_in[9];
    float* out = (float*)d_out;

    __half *ln1, *attn, *buf, *h1, *qkvw16, *projw16, *w116, *w216;
    float *qkv, *hattn, *ln2, *gatep, *h2;
    int *expidx, *pos, *cnt;
    cudaGetSymbolAddress((void**)&ln1,     g_ln1);
    cudaGetSymbolAddress((void**)&qkv,     g_qkv);
    cudaGetSymbolAddress((void**)&attn,    g_attn);
    cudaGetSymbolAddress((void**)&hattn,   g_hattn);
    cudaGetSymbolAddress((void**)&ln2,     g_ln2);
    cudaGetSymbolAddress((void**)&expidx,  g_expidx);
    cudaGetSymbolAddress((void**)&pos,     g_pos);
    cudaGetSymbolAddress((void**)&cnt,     g_cnt);
    cudaGetSymbolAddress((void**)&gatep,   g_gate);
    cudaGetSymbolAddress((void**)&buf,     g_buf);
    cudaGetSymbolAddress((void**)&h1,      g_h1);
    cudaGetSymbolAddress((void**)&h2,      g_h2);
    cudaGetSymbolAddress((void**)&qkvw16,  g_qkvw16);
    cudaGetSymbolAddress((void**)&projw16, g_projw16);
    cudaGetSymbolAddress((void**)&w116,    g_w116);
    cudaGetSymbolAddress((void**)&w216,    g_w216);

    cudaFuncSetAttribute((void*)k_gemm_h<OutF32>,
                         cudaFuncAttributeMaxDynamicSharedMemorySize, GEMM_SMEM);
    cudaFuncSetAttribute((void*)k_gemm_h<OutResid>,
                         cudaFuncAttributeMaxDynamicSharedMemorySize, GEMM_SMEM);
    cudaFuncSetAttribute((void*)k_gemm_h<OutGeluH>,
                         cudaFuncAttributeMaxDynamicSharedMemorySize, GEMM_SMEM);
    cudaFuncSetAttribute((void*)k_flash,
                         cudaFuncAttributeMaxDynamicSharedMemorySize, FLASH_SMEM);

    // weight fp16 conversion
    k_split_h<<<(QKV_OUT_ * H_ / 4) / 256, 256>>>(qkvw, qkvw16, QKV_OUT_ * H_ / 4);
    k_split_h<<<(H_ * H_ / 4) / 256, 256>>>(projw, projw16, H_ * H_ / 4);
    k_split_h<<<(E_ * FFN_ * H_ / 4) / 256, 256>>>(w1, w116, E_ * FFN_ * H_ / 4);
    k_split_h<<<(E_ * H_ * FFN_ / 4) / 256, 256>>>(w2, w216, E_ * H_ * FFN_ / 4);

    // LN1 (fp16 out)
    k_layernorm_h<<<T_, 256>>>(hidden, ln1w, ln1b, ln1);
    // QKV = ln1 @ W_qkv^T -> fp32 qkv (flash input)
    k_gemm_h<<<dim3(QKV_OUT_ / 128, T_ / 128, 1), 256, GEMM_SMEM>>>(
        ln1, H_, (size_t)0, qkvw16, H_, (size_t)0, H_,
        OutF32{qkv, QKV_OUT_, 0}, nullptr);
    // fused causal flash attention -> fp16 attn
    k_flash<<<dim3(B_ * NH_, S_ / FL_QROWS), 256, FLASH_SMEM>>>(qkv, attn);
    // proj + residual -> fp32 hattn
    k_gemm_h<<<dim3(H_ / 128, T_ / 128, 1), 256, GEMM_SMEM>>>(
        attn, H_, (size_t)0, projw16, H_, (size_t)0, H_,
        OutResid{hattn, hidden, H_}, nullptr);
    // fused LN2 + router
    k_ln_router<<<T_, 256>>>(hattn, ln2w, ln2b, ln2, routerw, expidx, gatep);
    // slot positions + counts
    k_pos<<<1, 512>>>(expidx, pos, cnt);
    // dispatch -> fp16 buf
    k_dispatch<<<NSLOT_, 256>>>(ln2, expidx, pos, buf);
    // expert FC1 (gelu -> fp16 h1) and FC2 (fp32 h2), count-gated
    k_gemm_h<<<dim3(FFN_ / 128, CAP_ / 128, E_), 256, GEMM_SMEM>>>(
        buf, H_, (size_t)CAP_ * H_, w116, H_, (size_t)FFN_ * H_, H_,
        OutGeluH{h1, FFN_, (size_t)CAP_ * FFN_}, cnt);
    k_gemm_h<<<dim3(H_ / 128, CAP_ / 128, E_), 256, GEMM_SMEM>>>(
        h1, FFN_, (size_t)CAP_ * FFN_, w216, FFN_, (size_t)H_ * FFN_, FFN_,
        OutF32{h2, H_, (size_t)CAP_ * H_}, cnt);
    // combine + final residual
    k_combine<<<T_, 256>>>(hattn, h2, expidx, pos, gatep, out);
}

// round 17
// speedup vs baseline: 2.3546x; 1.0329x over previous
#include <cuda_runtime.h>
#include <cuda_fp16.h>
#include <math.h>
#include <stdint.h>

// ---------------- problem constants ----------------
#define S_   2048
#define B_   2
#define H_   1024
#define NH_  16
#define NKV_ 4
#define HD_  64
#define T_   4096            // S_*B_
#define QKV_OUT_ 1536
#define E_   16
#define TOPK_ 2
#define FFN_ 2048
#define CAP_ 640             // ceil(T*K/E*1.25)
#define NSLOT_ (T_*TOPK_)

// ---------------- scratch (device globals; no runtime allocation) ----------------
__device__ __align__(16) __half g_ln1[(size_t)T_*H_];
__device__ __align__(16) __half g_qkv[(size_t)T_*QKV_OUT_];
__device__ __align__(16) __half g_attn[(size_t)T_*H_];
__device__ __align__(16) float  g_hattn[(size_t)T_*H_];
__device__ __align__(16) float  g_ln2[(size_t)T_*H_];
__device__ int   g_expidx[NSLOT_];
__device__ int   g_pos[NSLOT_];
__device__ int   g_cnt[E_];
__device__ float g_gate[NSLOT_];
__device__ __align__(16) __half g_buf[(size_t)E_*CAP_*H_];
__device__ __align__(16) __half g_h1[(size_t)E_*CAP_*FFN_];
__device__ __align__(16) float  g_h2[(size_t)E_*CAP_*H_];
// fp16 weights (converted once per call)
__device__ __align__(16) __half g_qkvw16[(size_t)QKV_OUT_*H_];
__device__ __align__(16) __half g_projw16[(size_t)H_*H_];
__device__ __align__(16) __half g_w116[(size_t)E_*FFN_*H_];
__device__ __align__(16) __half g_w216[(size_t)E_*H_*FFN_];

// =====================================================================
// PTX helpers (baseline sm_80+ ISA — tcgen05 unavailable on this target)
// =====================================================================
__device__ __forceinline__ uint32_t smem_to_u32(const void* smem_ptr) {
    uint32_t addr;
    asm("{ .reg .u64 tmp; cvta.to.shared.u64 tmp, %1; cvt.u32.u64 %0, tmp; }"
        : "=r"(addr) : "l"(smem_ptr));
    return addr;
}

#define CP_ASYNC16(dst_u32, src_ptr) \
    asm volatile("cp.async.cg.shared.global [%0], [%1], 16;" \
        :: "r"(dst_u32), "l"(src_ptr))
#define CP_COMMIT() asm volatile("cp.async.commit_group;" ::: "memory")
#define CP_WAIT(n)  asm volatile("cp.async.wait_group %0;" :: "n"(n) : "memory")

__device__ __forceinline__ void ldsm_x4(uint32_t& r0, uint32_t& r1,
                                        uint32_t& r2, uint32_t& r3, uint32_t addr) {
    asm volatile("ldmatrix.sync.aligned.m8n8.x4.shared.b16 {%0,%1,%2,%3}, [%4];"
                 : "=r"(r0), "=r"(r1), "=r"(r2), "=r"(r3) : "r"(addr));
}
__device__ __forceinline__ void ldsm_x4_t(uint32_t& r0, uint32_t& r1,
                                          uint32_t& r2, uint32_t& r3, uint32_t addr) {
    asm volatile("ldmatrix.sync.aligned.m8n8.x4.trans.shared.b16 {%0,%1,%2,%3}, [%4];"
                 : "=r"(r0), "=r"(r1), "=r"(r2), "=r"(r3) : "r"(addr));
}

__device__ __forceinline__ void mma16816h(float* c,
        uint32_t a0, uint32_t a1, uint32_t a2, uint32_t a3,
        uint32_t b0, uint32_t b1) {
    asm volatile(
        "mma.sync.aligned.m16n8k16.row.col.f32.f16.f16.f32 "
        "{%0,%1,%2,%3}, {%4,%5,%6,%7}, {%8,%9}, {%0,%1,%2,%3};"
        : "+f"(c[0]), "+f"(c[1]), "+f"(c[2]), "+f"(c[3])
        : "r"(a0), "r"(a1), "r"(a2), "r"(a3), "r"(b0), "r"(b1));
}

__device__ __forceinline__ uint32_t pack_h2(float a, float b) {
    __half2 h = __float22half2_rn(make_float2(a, b));
    return *(uint32_t*)&h;
}
__device__ __forceinline__ uint2 cvt_h(float4 v) {
    __half2 h01 = __float22half2_rn(make_float2(v.x, v.y));
    __half2 h23 = __float22half2_rn(make_float2(v.z, v.w));
    return make_uint2(*(uint32_t*)&h01, *(uint32_t*)&h23);
}
__device__ __forceinline__ float gelu_tanh(float v) {
    float x = 0.7978845608028654f * (v + 0.044715f * v * v * v);
    float t = 1.0f - 2.0f / (__expf(2.0f * x) + 1.0f);
    return 0.5f * v * (1.0f + t);
}

// ---------------- GEMM output functors ----------------
struct OutF32 {
    float* C; int ldc; size_t cB;
    __device__ __forceinline__ void setz(int z) { C += (size_t)z * cB; }
    __device__ __forceinline__ void store2(int m, int n, float a, float b) {
        *(float2*)&C[(size_t)m * ldc + n] = make_float2(a, b);
    }
};
struct OutH {
    __half* C; int ldc; size_t cB;
    __device__ __forceinline__ void setz(int z) { C += (size_t)z * cB; }
    __device__ __forceinline__ void store2(int m, int n, float a, float b) {
        *(uint32_t*)&C[(size_t)m * ldc + n] = pack_h2(a, b);
    }
};
struct OutResid {
    float* C; const float* R; int ldc;
    __device__ __forceinline__ void setz(int) {}
    __device__ __forceinline__ void store2(int m, int n, float a, float b) {
        float2 r = *(const float2*)&R[(size_t)m * ldc + n];
        *(float2*)&C[(size_t)m * ldc + n] = make_float2(a + r.x, b + r.y);
    }
};
struct OutGeluH {
    __half* C; int ldc; size_t cB;
    __device__ __forceinline__ void setz(int z) { C += (size_t)z * cB; }
    __device__ __forceinline__ void store2(int m, int n, float a, float b) {
        *(uint32_t*)&C[(size_t)m * ldc + n] = pack_h2(gelu_tanh(a), gelu_tanh(b));
    }
};

// =====================================================================
// fp16 HMMA NT GEMM, fp16 operands in GLOBAL (preconverted by producers),
// 3-stage cp.async pipeline, ONE barrier per 64-K chunk, no conversions.
// (unchanged from R15/R16 win)
// =====================================================================
#define OST 72
#define GST_B (128 * OST * 2)
#define GSTAGE (2 * GST_B)
#define GNSTG 3
#define GEMM_SMEM (GNSTG * GSTAGE)      // 110592

template<typename Out>
__global__ void __launch_bounds__(256, 2)
k_gemm_h(const __half* __restrict__ A, int lda, size_t aB,
         const __half* __restrict__ B, int ldb, size_t bB,
         int K, Out out, const int* __restrict__ cnt)
{
    if (cnt) {
        int lim = cnt[blockIdx.z];
        if (lim > CAP_) lim = CAP_;
        if ((int)(blockIdx.y * 128) >= lim) return;
    }

    extern __shared__ __half sm[];
    const int tid = threadIdx.x, lane = tid & 31, wid = tid >> 5;
    const int m0 = blockIdx.y * 128, n0 = blockIdx.x * 128;
    const int z = blockIdx.z;
    A += (size_t)z * aB;
    B += (size_t)z * bB;
    out.setz(z);
    const int warpM = (wid >> 2) * 64, warpN = (wid & 3) * 32;
    const int lrow = lane & 15, lsel = lane >> 4;

    const int ldrow = tid >> 1;
    const int ldcol = (tid & 1) * 32;
    const __half* gA = A + (size_t)(m0 + ldrow) * lda + ldcol;
    const __half* gB = B + (size_t)(n0 + ldrow) * ldb + ldcol;
    const uint32_t smbase = smem_to_u32(sm);
    const uint32_t dA = smbase + (uint32_t)(ldrow * OST + ldcol) * 2;
    const uint32_t dB = dA + GST_B;

    float acc[4][4][4] = {};
    const int nch = K >> 6;

    #pragma unroll
    for (int p = 0; p < 2; p++) {
        if (p < nch) {
            const int kk = p << 6;
            const uint32_t st = (uint32_t)p * GSTAGE;
            #pragma unroll
            for (int i = 0; i < 4; i++) {
                CP_ASYNC16(dA + st + i * 16, gA + kk + i * 8);
                CP_ASYNC16(dB + st + i * 16, gB + kk + i * 8);
            }
        }
        CP_COMMIT();
    }

    for (int c = 0; c < nch; c++) {
        CP_WAIT(1);
        __syncthreads();

        if (c + 2 < nch) {
            const int k1 = (c + 2) << 6;
            const uint32_t st = (uint32_t)((c + 2) % GNSTG) * GSTAGE;
            #pragma unroll
            for (int i = 0; i < 4; i++) {
                CP_ASYNC16(dA + st + i * 16, gA + k1 + i * 8);
                CP_ASYNC16(dB + st + i * 16, gB + k1 + i * 8);
            }
        }
        CP_COMMIT();

        const uint32_t sA = smbase + (uint32_t)(c % GNSTG) * GSTAGE;
        const uint32_t sB = sA + GST_B;
        #pragma unroll
        for (int s = 0; s < 4; s++) {
            const int ko = s * 16;
            uint32_t af[4][4];
            #pragma unroll
            for (int mt = 0; mt < 4; mt++) {
                uint32_t addr = sA +
                    ((uint32_t)(warpM + mt * 16 + lrow) * OST + ko + lsel * 8) * 2;
                ldsm_x4(af[mt][0], af[mt][1], af[mt][2], af[mt][3], addr);
            }
            uint32_t bf[4][2];
            #pragma unroll
            for (int pt = 0; pt < 2; pt++) {
                uint32_t r0, r1, r2, r3;
                uint32_t addr = sB +
                    ((uint32_t)(warpN + pt * 16 + lrow) * OST + ko + lsel * 8) * 2;
                ldsm_x4(r0, r1, r2, r3, addr);
                bf[pt * 2][0] = r0;     bf[pt * 2][1] = r2;
                bf[pt * 2 + 1][0] = r1; bf[pt * 2 + 1][1] = r3;
            }
            #pragma unroll
            for (int mt = 0; mt < 4; mt++)
                #pragma unroll
                for (int nt = 0; nt < 4; nt++)
                    mma16816h(acc[mt][nt], af[mt][0], af[mt][1], af[mt][2], af[mt][3],
                              bf[nt][0], bf[nt][1]);
        }
    }

    const int r = lane >> 2, cpair = (lane & 3) * 2;
    #pragma unroll
    for (int mt = 0; mt < 4; mt++) {
        int gm0 = m0 + warpM + mt * 16 + r;
        #pragma unroll
        for (int nt = 0; nt < 4; nt++) {
            int gn = n0 + warpN + nt * 8 + cpair;
            out.store2(gm0,     gn, acc[mt][nt][0], acc[mt][nt][1]);
            out.store2(gm0 + 8, gn, acc[mt][nt][2], acc[mt][nt][3]);
        }
    }
}

// ---------------- fp32 -> fp16 conversion (weights, once per call) ----
__global__ void k_split_h(const float* __restrict__ src, __half* __restrict__ dst, int n4)
{
    int i = blockIdx.x * blockDim.x + threadIdx.x;
    if (i >= n4) return;
    ((uint2*)dst)[i] = cvt_h(((const float4*)src)[i]);
}

// =====================================================================
// Fused flash attention — fp16 qkv input (no conversions, half traffic):
// S = Qh Kh (1-product), O += Ph Vh (1-product). fp16 attn output.
// =====================================================================
#define FL_QROWS 128
#define FL_KT    64
#define FL_ST    72
#define FL_RB    (FL_ST * 2)     // 144
#define FLASH_SMEM ((FL_QROWS + 2 * FL_KT) * FL_RB)   // 36864

__global__ void __launch_bounds__(256, 2)
k_flash(const __half* __restrict__ qkv, __half* __restrict__ attn)
{
    extern __shared__ char sm8[];
    const uint32_t sQ = smem_to_u32(sm8);
    const uint32_t sK = sQ + FL_QROWS * FL_RB;
    const uint32_t sV = sK + FL_KT * FL_RB;
    char* pQ = sm8;
    char* pK = sm8 + FL_QROWS * FL_RB;
    char* pV = pK + FL_KT * FL_RB;

    const int tid = threadIdx.x, lane = tid & 31, wid = tid >> 5;
    const int lrow = lane & 15, lsel = lane >> 4;
    const int bh = blockIdx.x;
    const int b = bh >> 4, hq = bh & 15, hk = hq >> 2;
    const int q0 = (int)(gridDim.y - 1 - blockIdx.y) * FL_QROWS;

    const int seqstride = B_ * QKV_OUT_;
    const __half* Qg = qkv + (size_t)b * QKV_OUT_ + hq * HD_;
    const __half* Kg = qkv + (size_t)b * QKV_OUT_ + NH_ * HD_ + hk * HD_;
    const __half* Vg = qkv + (size_t)b * QKV_OUT_ + (NH_ + NKV_) * HD_ + hk * HD_;

    // ---- Q tile: direct fp16 copy (128 rows x 64 halves) ----
    #pragma unroll
    for (int i = 0; i < 4; i++) {
        int u = tid + i * 256;           // 0..1023 uint4 slots
        int row = u >> 3, c8 = (u & 7) * 8;
        *(uint4*)(pQ + row * FL_RB + c8 * 2) =
            *(const uint4*)(Qg + (size_t)(q0 + row) * seqstride + c8);
    }

    float accO[8][4] = {};
    float S[8][4];
    float m0 = -1e30f, m1 = -1e30f, l0 = 0.f, l1 = 0.f;

    const int rbase = q0 + wid * 16;
    const int q_hi = rbase + 15;
    const int jmax = (q0 >> 6) + 2;

    for (int j = 0; j < jmax; j++) {
        const int jbase = j * FL_KT;
        // ---- K/V tiles: direct fp16 copies ----
        #pragma unroll
        for (int i = 0; i < 2; i++) {
            int u = tid + i * 256;       // 0..511
            int row = u >> 3, c8 = (u & 7) * 8;
            size_t go = (size_t)(jbase + row) * seqstride + c8;
            *(uint4*)(pK + row * FL_RB + c8 * 2) = *(const uint4*)(Kg + go);
            *(uint4*)(pV + row * FL_RB + c8 * 2) = *(const uint4*)(Vg + go);
        }
        __syncthreads();

        if (jbase <= q_hi) {
            #pragma unroll
            for (int t = 0; t < 8; t++) {
                S[t][0] = 0.f; S[t][1] = 0.f; S[t][2] = 0.f; S[t][3] = 0.f;
            }
            // ---- S = Qh Kh ----
            #pragma unroll
            for (int s = 0; s < 4; s++) {
                uint32_t qh[4];
                uint32_t qaddr = sQ + (uint32_t)(wid * 16 + lrow) * FL_RB +
                                 (s * 16 + lsel * 8) * 2;
                ldsm_x4(qh[0], qh[1], qh[2], qh[3], qaddr);
                #pragma unroll
                for (int g = 0; g < 4; g++) {
                    uint32_t r0, r1, r2, r3;
                    uint32_t kaddr = sK + (uint32_t)(g * 16 + lrow) * FL_RB +
                                     (s * 16 + lsel * 8) * 2;
                    ldsm_x4(r0, r1, r2, r3, kaddr);
                    mma16816h(S[g * 2],     qh[0], qh[1], qh[2], qh[3], r0, r2);
                    mma16816h(S[g * 2 + 1], qh[0], qh[1], qh[2], qh[3], r1, r3);
                }
            }

            const float scale = 0.125f;
            #pragma unroll
            for (int t = 0; t < 8; t++) {
                S[t][0] *= scale; S[t][1] *= scale;
                S[t][2] *= scale; S[t][3] *= scale;
            }
            if (jbase + 63 > rbase) {
                int r0g = rbase + (lane >> 2);
                int cg = jbase + (lane & 3) * 2;
                #pragma unroll
                for (int t = 0; t < 8; t++) {
                    int c0 = cg + t * 8;
                    if (c0 > r0g)     S[t][0] = -1e30f;
                    if (c0 + 1 > r0g) S[t][1] = -1e30f;
                    if (c0 > r0g + 8)     S[t][2] = -1e30f;
                    if (c0 + 1 > r0g + 8) S[t][3] = -1e30f;
                }
            }

            float tm0 = -1e30f, tm1 = -1e30f;
            #pragma unroll
            for (int t = 0; t < 8; t++) {
                tm0 = fmaxf(tm0, fmaxf(S[t][0], S[t][1]));
                tm1 = fmaxf(tm1, fmaxf(S[t][2], S[t][3]));
            }
            tm0 = fmaxf(tm0, __shfl_xor_sync(0xFFFFFFFFu, tm0, 1));
            tm0 = fmaxf(tm0, __shfl_xor_sync(0xFFFFFFFFu, tm0, 2));
            tm1 = fmaxf(tm1, __shfl_xor_sync(0xFFFFFFFFu, tm1, 1));
            tm1 = fmaxf(tm1, __shfl_xor_sync(0xFFFFFFFFu, tm1, 2));
            float mn0 = fmaxf(m0, tm0), mn1 = fmaxf(m1, tm1);
            float fac0 = __expf(m0 - mn0), fac1 = __expf(m1 - mn1);

            float ts0 = 0.f, ts1 = 0.f;
            #pragma unroll
            for (int t = 0; t < 8; t++) {
                S[t][0] = __expf(S[t][0] - mn0);
                S[t][1] = __expf(S[t][1] - mn0);
                S[t][2] = __expf(S[t][2] - mn1);
                S[t][3] = __expf(S[t][3] - mn1);
                ts0 += S[t][0] + S[t][1];
                ts1 += S[t][2] + S[t][3];
            }
            ts0 += __shfl_xor_sync(0xFFFFFFFFu, ts0, 1);
            ts0 += __shfl_xor_sync(0xFFFFFFFFu, ts0, 2);
            ts1 += __shfl_xor_sync(0xFFFFFFFFu, ts1, 1);
            ts1 += __shfl_xor_sync(0xFFFFFFFFu, ts1, 2);
            l0 = l0 * fac0 + ts0;
            l1 = l1 * fac1 + ts1;
            m0 = mn0; m1 = mn1;

            #pragma unroll
            for (int t = 0; t < 8; t++) {
                accO[t][0] *= fac0; accO[t][1] *= fac0;
                accO[t][2] *= fac1; accO[t][3] *= fac1;
            }

            // ---- O += Ph Vh ----
            #pragma unroll
            for (int s = 0; s < 4; s++) {
                uint32_t ah[4];
                ah[0] = pack_h2(S[2*s][0],   S[2*s][1]);
                ah[1] = pack_h2(S[2*s][2],   S[2*s][3]);
                ah[2] = pack_h2(S[2*s+1][0], S[2*s+1][1]);
                ah[3] = pack_h2(S[2*s+1][2], S[2*s+1][3]);
                #pragma unroll
                for (int dg = 0; dg < 4; dg++) {
                    uint32_t vrow = (uint32_t)(s * 16 + ((lane >> 3) & 1) * 8 + (lane & 7));
                    uint32_t vcol = (uint32_t)(dg * 16 + (lane >> 4) * 8);
                    uint32_t vaddr = sV + vrow * FL_RB + vcol * 2;
                    uint32_t h0, h1, h2, h3;
                    ldsm_x4_t(h0, h1, h2, h3, vaddr);
                    mma16816h(accO[dg * 2],     ah[0], ah[1], ah[2], ah[3], h0, h1);
                    mma16816h(accO[dg * 2 + 1], ah[0], ah[1], ah[2], ah[3], h2, h3);
                }
            }
        }
        __syncthreads();
    }

    float inv0 = 1.f / l0, inv1 = 1.f / l1;
    int r0g = rbase + (lane >> 2);
    __half* Og = attn + (size_t)b * H_ + hq * HD_;
    const int ostride = B_ * H_;
    #pragma unroll
    for (int t = 0; t < 8; t++) {
        int gd = t * 8 + (lane & 3) * 2;
        *(uint32_t*)&Og[(size_t)r0g * ostride + gd] =
            pack_h2(accO[t][0] * inv0, accO[t][1] * inv0);
        *(uint32_t*)&Og[(size_t)(r0g + 8) * ostride + gd] =
            pack_h2(accO[t][2] * inv1, accO[t][3] * inv1);
    }
}

// ---------------- layernorm (fp16 output, for GEMM A) ----------------
__global__ void k_layernorm_h(const float* __restrict__ x, const float* __restrict__ w,
                              const float* __restrict__ b, __half* __restrict__ y)
{
    int t = blockIdx.x;
    int h0 = threadIdx.x * 4;
    float4 v = *(const float4*)&x[(size_t)t * H_ + h0];
    float s = v.x + v.y + v.z + v.w;
    float s2 = v.x*v.x + v.y*v.y + v.z*v.z + v.w*v.w;
    __shared__ float r1[256], r2[256];
    r1[threadIdx.x] = s; r2[threadIdx.x] = s2;
    __syncthreads();
    for (int o = 128; o; o >>= 1) {
        if (threadIdx.x < o) {
            r1[threadIdx.x] += r1[threadIdx.x + o];
            r2[threadIdx.x] += r2[threadIdx.x + o];
        }
        __syncthreads();
    }
    float mean = r1[0] * (1.0f / H_);
    float var  = r2[0] * (1.0f / H_) - mean * mean;
    float inv  = rsqrtf(var + 1e-5f);
    float4 wv = *(const float4*)&w[h0];
    float4 bv = *(const float4*)&b[h0];
    float4 yv = make_float4((v.x - mean) * inv * wv.x + bv.x,
                            (v.y - mean) * inv * wv.y + bv.y,
                            (v.z - mean) * inv * wv.z + bv.z,
                            (v.w - mean) * inv * wv.w + bv.w);
    ((uint2*)(y + (size_t)t * H_))[threadIdx.x] = cvt_h(yv);
}

// ---------------- fused LN2 + router ----------------
__global__ void k_ln_router(const float* __restrict__ x, const float* __restrict__ w,
                            const float* __restrict__ b, float* __restrict__ y,
                            const float* __restrict__ Wr,
                            int* __restrict__ expidx, float* __restrict__ gate)
{
    int t = blockIdx.x;
    int tid = threadIdx.x;
    int h0 = tid * 4;
    __shared__ float r1[256], r2[256];
    __shared__ float rowbuf[H_];
    __shared__ float logits[E_];

    float4 v = *(const float4*)&x[(size_t)t * H_ + h0];
    float s = v.x + v.y + v.z + v.w;
    float s2 = v.x*v.x + v.y*v.y + v.z*v.z + v.w*v.w;
    r1[tid] = s; r2[tid] = s2;
    __syncthreads();
    for (int o = 128; o; o >>= 1) {
        if (tid < o) {
            r1[tid] += r1[tid + o];
            r2[tid] += r2[tid + o];
        }
        __syncthreads();
    }
    float mean = r1[0] * (1.0f / H_);
    float var  = r2[0] * (1.0f / H_) - mean * mean;
    float inv  = rsqrtf(var + 1e-5f);
    float4 wv = *(const float4*)&w[h0];
    float4 bv = *(const float4*)&b[h0];
    float4 yv = make_float4((v.x - mean) * inv * wv.x + bv.x,
                            (v.y - mean) * inv * wv.y + bv.y,
                            (v.z - mean) * inv * wv.z + bv.z,
                            (v.w - mean) * inv * wv.w + bv.w);
    *(float4*)&y[(size_t)t * H_ + h0] = yv;
    *(float4*)&rowbuf[h0] = yv;
    __syncthreads();

    int wid = tid >> 5, lane = tid & 31;
    for (int e = wid; e < E_; e += 8) {
        const float* wr = Wr + (size_t)e * H_;
        float acc = 0.f;
        for (int i = lane; i < H_; i += 32) acc += rowbuf[i] * wr[i];
        #pragma unroll
        for (int o = 16; o; o >>= 1) acc += __shfl_xor_sync(0xFFFFFFFFu, acc, o);
        if (lane == 0) logits[e] = acc;
    }
    __syncthreads();
    if (tid == 0) {
        float lmax = -1e30f;
        #pragma unroll
        for (int e = 0; e < E_; e++) lmax = fmaxf(lmax, logits[e]);
        float den = 0.f;
        #pragma unroll
        for (int e = 0; e < E_; e++) den += expf(logits[e] - lmax);
        int i1 = 0; float v1 = logits[0];
        #pragma unroll
        for (int e = 1; e < E_; e++) if (logits[e] > v1) { v1 = logits[e]; i1 = e; }
        int i2 = -1; float v2 = -1e30f;
        #pragma unroll
        for (int e = 0; e < E_; e++) if (e != i1 && logits[e] > v2) { v2 = logits[e]; i2 = e; }
        float invd = 1.0f / den;
        expidx[2 * t]     = i1;  gate[2 * t]     = expf(v1 - lmax) * invd;
        expidx[2 * t + 1] = i2;  gate[2 * t + 1] = expf(v2 - lmax) * invd;
    }
}

// ---------------- slot positions + per-expert counts (ballot scan) ----------
__global__ void k_pos(const int* __restrict__ expidx, int* __restrict__ pos,
                      int* __restrict__ cnt)
{
    __shared__ int sidx[NSLOT_];
    for (int i = threadIdx.x; i < NSLOT_; i += 512) sidx[i] = expidx[i];
    __syncthreads();
    int w = threadIdx.x >> 5, lane = threadIdx.x & 31;
    int c = 0;
    for (int base = 0; base < NSLOT_; base += 32) {
        bool f = (sidx[base + lane] == w);
        unsigned m = __ballot_sync(0xFFFFFFFFu, f);
        if (f) pos[base + lane] = c + __popc(m & ((1u << lane) - 1));
        c += __popc(m);
    }
    if (lane == 0) cnt[w] = (c < CAP_) ? c : CAP_;
}

// ---------------- dispatch kept slots into fp16 expert buffer ----------------
__global__ void k_dispatch(const float* __restrict__ ln2, const int* __restrict__ expidx,
                           const int* __restrict__ pos, __half* __restrict__ buf)
{
    int slot = blockIdx.x;
    int p = pos[slot];
    if (p >= CAP_) return;
    int e = expidx[slot];
    int t = slot >> 1;
    float4 v = *(const float4*)&ln2[(size_t)t * H_ + threadIdx.x * 4];
    ((uint2*)(buf + ((size_t)e * CAP_ + p) * H_))[threadIdx.x] = cvt_h(v);
}

// ---------------- combine: residual + gated expert outputs ----------------
__global__ void k_combine(const float* __restrict__ hattn, const float* __restrict__ h2,
                          const int* __restrict__ expidx, const int* __restrict__ pos,
                          const float* __restrict__ gate, float* __restrict__ out)
{
    int t = blockIdx.x;
    int s0 = 2 * t, s1 = 2 * t + 1;
    int p0 = pos[s0], p1 = pos[s1];
    int e0 = expidx[s0], e1 = expidx[s1];
    float g0 = (p0 < CAP_) ? gate[s0] : 0.f;
    float g1 = (p1 < CAP_) ? gate[s1] : 0.f;
    const float* r0 = (p0 < CAP_) ? h2 + ((size_t)e0 * CAP_ + p0) * H_ : nullptr;
    const float* r1 = (p1 < CAP_) ? h2 + ((size_t)e1 * CAP_ + p1) * H_ : nullptr;
    for (int h = threadIdx.x; h < H_; h += 256) {
        float v = hattn[(size_t)t * H_ + h];
        if (r0) v += r0[h] * g0;
        if (r1) v += r1[h] * g1;
        out[(size_t)t * H_ + h] = v;
    }
}

// ---------------- launch ----------------
extern "C" void kernel_launch(void* const* d_in, const int* in_sizes, int n_in,
                              void* d_out, int out_size)
{
    const float* hidden  = (const float*)d_in[0];
    const float* ln1w    = (const float*)d_in[1];
    const float* ln1b    = (const float*)d_in[2];
    const float* ln2w    = (const float*)d_in[3];
    const float* ln2b    = (const float*)d_in[4];
    const float* qkvw    = (const float*)d_in[5];
    const float* projw   = (const float*)d_in[6];
    const float* routerw = (const float*)d_in[7];
    const float* w1      = (const float*)d_in[8];
    const float* w2      = (const float*)d_in[9];
    float* out = (float*)d_out;

    __half *ln1, *qkv, *attn, *buf, *h1, *qkvw16, *projw16, *w116, *w216;
    float *hattn, *ln2, *gatep, *h2;
    int *expidx, *pos, *cnt;
    cudaGetSymbolAddress((void**)&ln1,     g_ln1);
    cudaGetSymbolAddress((void**)&qkv,     g_qkv);
    cudaGetSymbolAddress((void**)&attn,    g_attn);
    cudaGetSymbolAddress((void**)&hattn,   g_hattn);
    cudaGetSymbolAddress((void**)&ln2,     g_ln2);
    cudaGetSymbolAddress((void**)&expidx,  g_expidx);
    cudaGetSymbolAddress((void**)&pos,     g_pos);
    cudaGetSymbolAddress((void**)&cnt,     g_cnt);
    cudaGetSymbolAddress((void**)&gatep,   g_gate);
    cudaGetSymbolAddress((void**)&buf,     g_buf);
    cudaGetSymbolAddress((void**)&h1,      g_h1);
    cudaGetSymbolAddress((void**)&h2,      g_h2);
    cudaGetSymbolAddress((void**)&qkvw16,  g_qkvw16);
    cudaGetSymbolAddress((void**)&projw16, g_projw16);
    cudaGetSymbolAddress((void**)&w116,    g_w116);
    cudaGetSymbolAddress((void**)&w216,    g_w216);

    cudaFuncSetAttribute((void*)k_gemm_h<OutF32>,
                         cudaFuncAttributeMaxDynamicSharedMemorySize, GEMM_SMEM);
    cudaFuncSetAttribute((void*)k_gemm_h<OutH>,
                         cudaFuncAttributeMaxDynamicSharedMemorySize, GEMM_SMEM);
    cudaFuncSetAttribute((void*)k_gemm_h<OutResid>,
                         cudaFuncAttributeMaxDynamicSharedMemorySize, GEMM_SMEM);
    cudaFuncSetAttribute((void*)k_gemm_h<OutGeluH>,
                         cudaFuncAttributeMaxDynamicSharedMemorySize, GEMM_SMEM);
    cudaFuncSetAttribute((void*)k_flash,
                         cudaFuncAttributeMaxDynamicSharedMemorySize, FLASH_SMEM);

    // weight fp16 conversion
    k_split_h<<<(QKV_OUT_ * H_ / 4) / 256, 256>>>(qkvw, qkvw16, QKV_OUT_ * H_ / 4);
    k_split_h<<<(H_ * H_ / 4) / 256, 256>>>(projw, projw16, H_ * H_ / 4);
    k_split_h<<<(E_ * FFN_ * H_ / 4) / 256, 256>>>(w1, w116, E_ * FFN_ * H_ / 4);
    k_split_h<<<(E_ * H_ * FFN_ / 4) / 256, 256>>>(w2, w216, E_ * H_ * FFN_ / 4);

    // LN1 (fp16 out)
    k_layernorm_h<<<T_, 256>>>(hidden, ln1w, ln1b, ln1);
    // QKV = ln1 @ W_qkv^T -> fp16 qkv (flash consumes directly)
    k_gemm_h<<<dim3(QKV_OUT_ / 128, T_ / 128, 1), 256, GEMM_SMEM>>>(
        ln1, H_, (size_t)0, qkvw16, H_, (size_t)0, H_,
        OutH{qkv, QKV_OUT_, 0}, nullptr);
    // fused causal flash attention (fp16 in/out, zero conversions)
    k_flash<<<dim3(B_ * NH_, S_ / FL_QROWS), 256, FLASH_SMEM>>>(qkv, attn);
    // proj + residual -> fp32 hattn
    k_gemm_h<<<dim3(H_ / 128, T_ / 128, 1), 256, GEMM_SMEM>>>(
        attn, H_, (size_t)0, projw16, H_, (size_t)0, H_,
        OutResid{hattn, hidden, H_}, nullptr);
    // fused LN2 + router
    k_ln_router<<<T_, 256>>>(hattn, ln2w, ln2b, ln2, routerw, expidx, gatep);
    // slot positions + counts
    k_pos<<<1, 512>>>(expidx, pos, cnt);
    // dispatch -> fp16 buf
    k_dispatch<<<NSLOT_, 256>>>(ln2, expidx, pos, buf);
    // expert FC1 (gelu -> fp16 h1) and FC2 (fp32 h2), count-gated
    k_gemm_h<<<dim3(FFN_ / 128, CAP_ / 128, E_), 256, GEMM_SMEM>>>(
        buf, H_, (size_t)CAP_ * H_, w116, H_, (size_t)FFN_ * H_, H_,
        OutGeluH{h1, FFN_, (size_t)CAP_ * FFN_}, cnt);
    k_gemm_h<<<dim3(H_ / 128, CAP_ / 128, E_), 256, GEMM_SMEM>>>(
        h1, FFN_, (size_t)CAP_ * FFN_, w216, FFN_, (size_t)H_ * FFN_, FFN_,
        OutF32{h2, H_, (size_t)CAP_ * H_}, cnt);
    // combine + final residual
    k_combine<<<T_, 256>>>(hattn, h2, expidx, pos, gatep, out);
}